// round 9
// baseline (speedup 1.0000x reference)
#include <cuda_runtime.h>
#include <cuda_fp16.h>
#include <cstdint>
#include <math.h>

#define HH 256
#define WW 256
#define DD 64
#define NH 8
#define KBIG 16384
#define XS 72

// fp16 scratch: Q needs hi+lo (A operand); K, V hi only (B operands); P hi+lo (A).
__device__ __half g_Qh[NH * 256 * KBIG], g_Ql[NH * 256 * KBIG];
__device__ __half g_Kh[NH * 256 * KBIG];
__device__ __half g_Vh[256 * 256 * 512];
__device__ __half g_Ph[NH * 256 * 256], g_Pl[NH * 256 * 256];
__device__ float g_DOTS[NH * 256 * 256];
__device__ float g_PB[NH * 256 * 256];

// ---------------- warp-MMA helpers ------------------------------------------
__device__ __forceinline__ void ldsm4(uint32_t* r, uint32_t a) {
    asm volatile("ldmatrix.sync.aligned.m8n8.x4.shared.b16 {%0,%1,%2,%3}, [%4];"
                 : "=r"(r[0]), "=r"(r[1]), "=r"(r[2]), "=r"(r[3]) : "r"(a));
}
__device__ __forceinline__ void ldsm4t(uint32_t* r, uint32_t a) {
    asm volatile("ldmatrix.sync.aligned.m8n8.x4.trans.shared.b16 {%0,%1,%2,%3}, [%4];"
                 : "=r"(r[0]), "=r"(r[1]), "=r"(r[2]), "=r"(r[3]) : "r"(a));
}
__device__ __forceinline__ void mmaH(float* c, const uint32_t* a, const uint32_t* b) {
    asm volatile("mma.sync.aligned.m16n8k16.row.col.f32.f16.f16.f32 "
                 "{%0,%1,%2,%3},{%4,%5,%6,%7},{%8,%9},{%0,%1,%2,%3};"
                 : "+f"(c[0]), "+f"(c[1]), "+f"(c[2]), "+f"(c[3])
                 : "r"(a[0]), "r"(a[1]), "r"(a[2]), "r"(a[3]), "r"(b[0]), "r"(b[1]));
}
__device__ __forceinline__ void splitH(float a, float b, uint32_t& h, uint32_t& l) {
    __half2 hv = __floats2half2_rn(a, b);
    float2 hf = __half22float2(hv);
    __half2 lv = __floats2half2_rn(a - hf.x, b - hf.y);
    h = *reinterpret_cast<uint32_t*>(&hv);
    l = *reinterpret_cast<uint32_t*>(&lv);
}
__device__ __forceinline__ uint32_t packH(float a, float b) {
    __half2 hv = __floats2half2_rn(a, b);
    return *reinterpret_cast<uint32_t*>(&hv);
}
__device__ __forceinline__ uint32_t aAddr(const __half* base, int lane, int r0, int k0) {
    int row = r0 + (lane & 15), col = k0 + ((lane >> 4) << 3);
    return (uint32_t)__cvta_generic_to_shared(base + row * XS + col);
}
__device__ __forceinline__ uint32_t bAddrT(const __half* base, int lane, int k0, int n0) {
    int row = k0 + (lane & 7) + (((lane >> 3) & 1) << 3);
    int col = n0 + ((lane >> 4) << 3);
    return (uint32_t)__cvta_generic_to_shared(base + row * XS + col);
}
__device__ __forceinline__ uint32_t bAddrN(const __half* base, int lane, int j0, int d0) {
    int row = j0 + (lane & 7) + ((lane >> 4) << 3);
    int col = d0 + (((lane >> 3) & 1) << 3);
    return (uint32_t)__cvta_generic_to_shared(base + row * XS + col);
}

// ============================================================================
// Width attention, fp16 split-2. Block=(w,head), 16 warps x 16 rows.
// smem: Xh,Xl,Kh (256xXS each; V-hi reuses Xh), Wh (64xXS)  ~117KB
// ============================================================================
__global__ void __launch_bounds__(512, 1)
k_width_mma(const float* __restrict__ x, const float* __restrict__ Wq,
            const float* __restrict__ Wkv, const float* __restrict__ Wout,
            float* __restrict__ out) {
    extern __shared__ __half sb[];
    __half* Xh = sb;                  // later: V hi
    __half* Xl = sb + 256 * XS;
    __half* Kh = sb + 512 * XS;
    __half* Wh = sb + 768 * XS;

    const int t = threadIdx.x, lane = t & 31, warp = t >> 5, m0 = warp * 16;
    const int w = blockIdx.x, head = blockIdx.y;
    {
        int row = t >> 1, q0 = (t & 1) * 8;
        const float4* src = (const float4*)(x + (size_t)row * (WW * DD) + w * DD) + q0;
#pragma unroll
        for (int q4 = 0; q4 < 8; q4++) {
            float4 v = src[q4];
            uint32_t h0, l0, h1, l1;
            splitH(v.x, v.y, h0, l0);
            splitH(v.z, v.w, h1, l1);
            int cc = (q0 + q4) * 4;
            *(uint32_t*)(Xh + row * XS + cc) = h0;
            *(uint32_t*)(Xh + row * XS + cc + 2) = h1;
            *(uint32_t*)(Xl + row * XS + cc) = l0;
            *(uint32_t*)(Xl + row * XS + cc + 2) = l1;
        }
    }
    auto loadW = [&](const float* wsrc, int stride, float scale) {
        for (int e = t; e < 2048; e += 512) {
            int k = e >> 5, n2 = e & 31;
            float2 v = *(const float2*)(wsrc + (size_t)k * stride + n2 * 2);
            *(uint32_t*)(Wh + k * XS + n2 * 2) = packH(v.x * scale, v.y * scale);
        }
    };
    // C[16x64] = X[own 16 rows] @ W  (split-2: ah*bh + al*bh)
    auto proj = [&](float (&c)[8][4]) {
#pragma unroll
        for (int nt = 0; nt < 8; nt++)
#pragma unroll
            for (int i = 0; i < 4; i++) c[nt][i] = 0.f;
#pragma unroll
        for (int ks = 0; ks < 4; ks++) {
            uint32_t ah[4], al[4];
            ldsm4(ah, aAddr(Xh, lane, m0, ks * 16));
            ldsm4(al, aAddr(Xl, lane, m0, ks * 16));
#pragma unroll
            for (int np = 0; np < 4; np++) {
                uint32_t bh[4];
                ldsm4t(bh, bAddrT(Wh, lane, ks * 16, np * 16));
#pragma unroll
                for (int hf = 0; hf < 2; hf++) {
                    float* cc = c[np * 2 + hf];
                    mmaH(cc, ah, bh + hf * 2);
                    mmaH(cc, al, bh + hf * 2);
                }
            }
        }
    };
    auto storeHi = [&](float (&c)[8][4], __half* Dh) {
#pragma unroll
        for (int nt = 0; nt < 8; nt++) {
            int r = m0 + (lane >> 2), cc = nt * 8 + ((lane & 3) << 1);
            *(uint32_t*)(Dh + r * XS + cc) = packH(c[nt][0], c[nt][1]);
            *(uint32_t*)(Dh + (r + 8) * XS + cc) = packH(c[nt][2], c[nt][3]);
        }
    };

    float c[8][4];
    loadW(Wkv + head * 64, 1024, 1.f);  // Wk
    __syncthreads();
    proj(c);
    storeHi(c, Kh);
    __syncthreads();
    loadW(Wq + head * 64, 512, 0.125f);  // Wq (scale folded)
    __syncthreads();
    proj(c);
    uint32_t qh[4][4], ql[4][4];
#pragma unroll
    for (int ks = 0; ks < 4; ks++) {
        splitH(c[2 * ks][0], c[2 * ks][1], qh[ks][0], ql[ks][0]);
        splitH(c[2 * ks][2], c[2 * ks][3], qh[ks][1], ql[ks][1]);
        splitH(c[2 * ks + 1][0], c[2 * ks + 1][1], qh[ks][2], ql[ks][2]);
        splitH(c[2 * ks + 1][2], c[2 * ks + 1][3], qh[ks][3], ql[ks][3]);
    }
    __syncthreads();
    loadW(Wkv + 512 + head * 64, 1024, 1.f);  // Wv
    __syncthreads();
    proj(c);
    storeHi(c, Xh);  // V-hi overwrites X-hi (own rows only)
    __syncthreads();
    loadW(Wout + (size_t)head * 64 * 64, 64, 1.f);  // Wout slice
    __syncthreads();

    float o[8][4];
#pragma unroll
    for (int nt = 0; nt < 8; nt++)
#pragma unroll
        for (int i = 0; i < 4; i++) o[nt][i] = 0.f;
    float lsum[2] = {0.f, 0.f};

    for (int jc = 0; jc < 8; jc++) {
        float s[4][4];
#pragma unroll
        for (int jt = 0; jt < 4; jt++)
#pragma unroll
            for (int i = 0; i < 4; i++) s[jt][i] = 0.f;
#pragma unroll
        for (int ks = 0; ks < 4; ks++) {
            uint32_t kb[2][4];
            ldsm4(kb[0], bAddrN(Kh, lane, jc * 32, ks * 16));
            ldsm4(kb[1], bAddrN(Kh, lane, jc * 32 + 16, ks * 16));
#pragma unroll
            for (int jt = 0; jt < 4; jt++) {
                float* ss = s[jt];
                const uint32_t* bh = &kb[jt >> 1][(jt & 1) * 2];
                mmaH(ss, qh[ks], bh);
                mmaH(ss, ql[ks], bh);
            }
        }
        uint32_t ph[2][4], pl[2][4];
#pragma unroll
        for (int k2 = 0; k2 < 2; k2++) {
            float e0 = __expf(s[2 * k2][0]), e1 = __expf(s[2 * k2][1]);
            float e2 = __expf(s[2 * k2][2]), e3 = __expf(s[2 * k2][3]);
            float f0 = __expf(s[2 * k2 + 1][0]), f1 = __expf(s[2 * k2 + 1][1]);
            float f2 = __expf(s[2 * k2 + 1][2]), f3 = __expf(s[2 * k2 + 1][3]);
            lsum[0] += e0 + e1 + f0 + f1;
            lsum[1] += e2 + e3 + f2 + f3;
            splitH(e0, e1, ph[k2][0], pl[k2][0]);
            splitH(e2, e3, ph[k2][1], pl[k2][1]);
            splitH(f0, f1, ph[k2][2], pl[k2][2]);
            splitH(f2, f3, ph[k2][3], pl[k2][3]);
        }
#pragma unroll
        for (int k2 = 0; k2 < 2; k2++) {
            int j0 = jc * 32 + k2 * 16;
#pragma unroll
            for (int np = 0; np < 4; np++) {
                uint32_t vb[4];
                ldsm4t(vb, bAddrT(Xh, lane, j0, np * 16));
#pragma unroll
                for (int hf = 0; hf < 2; hf++) {
                    float* oo = o[np * 2 + hf];
                    mmaH(oo, ph[k2], vb + hf * 2);
                    mmaH(oo, pl[k2], vb + hf * 2);
                }
            }
        }
    }
#pragma unroll
    for (int i = 0; i < 2; i++) {
        lsum[i] += __shfl_xor_sync(0xffffffffu, lsum[i], 1);
        lsum[i] += __shfl_xor_sync(0xffffffffu, lsum[i], 2);
    }
    float i0 = 1.f / lsum[0], i1 = 1.f / lsum[1];
    uint32_t oh[4][4], ol[4][4];
#pragma unroll
    for (int ks = 0; ks < 4; ks++) {
        splitH(o[2 * ks][0] * i0, o[2 * ks][1] * i0, oh[ks][0], ol[ks][0]);
        splitH(o[2 * ks][2] * i1, o[2 * ks][3] * i1, oh[ks][1], ol[ks][1]);
        splitH(o[2 * ks + 1][0] * i0, o[2 * ks + 1][1] * i0, oh[ks][2], ol[ks][2]);
        splitH(o[2 * ks + 1][2] * i1, o[2 * ks + 1][3] * i1, oh[ks][3], ol[ks][3]);
    }
    float r[8][4];
#pragma unroll
    for (int nt = 0; nt < 8; nt++)
#pragma unroll
        for (int i = 0; i < 4; i++) r[nt][i] = 0.f;
#pragma unroll
    for (int ks = 0; ks < 4; ks++)
#pragma unroll
        for (int np = 0; np < 4; np++) {
            uint32_t bh[4];
            ldsm4t(bh, bAddrT(Wh, lane, ks * 16, np * 16));
#pragma unroll
            for (int hf = 0; hf < 2; hf++) {
                float* rr = r[np * 2 + hf];
                mmaH(rr, oh[ks], bh + hf * 2);
                mmaH(rr, ol[ks], bh + hf * 2);
            }
        }
#pragma unroll
    for (int nt = 0; nt < 8; nt++) {
        int row = m0 + (lane >> 2), col = nt * 8 + ((lane & 3) << 1);
        float* op = out + ((size_t)row * WW + w) * DD;
        atomicAdd(op + col, 0.5f * r[nt][0]);
        atomicAdd(op + col + 1, 0.5f * r[nt][1]);
        float* op2 = out + ((size_t)(row + 8) * WW + w) * DD;
        atomicAdd(op2 + col, 0.5f * r[nt][2]);
        atomicAdd(op2 + col + 1, 0.5f * r[nt][3]);
    }
}

// ============================================================================
// Height projection: per row r; Q -> hi+lo, K,V -> hi only.
// ============================================================================
__global__ void __launch_bounds__(512, 1)
k_hproj_mma(const float* __restrict__ x, const float* __restrict__ Wq,
            const float* __restrict__ Wkv) {
    extern __shared__ __half sb[];
    __half* Xh = sb;
    __half* Xl = sb + 256 * XS;
    __half* Wh = sb + 512 * XS;

    const int t = threadIdx.x, lane = t & 31, warp = t >> 5, m0 = warp * 16;
    const int r = blockIdx.x;
    {
        int row = t >> 1, q0 = (t & 1) * 8;
        const float4* src = (const float4*)(x + (size_t)r * (WW * DD) + row * 64) + q0;
#pragma unroll
        for (int q4 = 0; q4 < 8; q4++) {
            float4 v = src[q4];
            uint32_t h0, l0, h1, l1;
            splitH(v.x, v.y, h0, l0);
            splitH(v.z, v.w, h1, l1);
            int cc = (q0 + q4) * 4;
            *(uint32_t*)(Xh + row * XS + cc) = h0;
            *(uint32_t*)(Xh + row * XS + cc + 2) = h1;
            *(uint32_t*)(Xl + row * XS + cc) = l0;
            *(uint32_t*)(Xl + row * XS + cc + 2) = l1;
        }
    }
    for (int mk = 0; mk < 3; mk++) {
        for (int g = 0; g < 8; g++) {
            const float* wsrc;
            int stride;
            float scale = 1.f;
            if (mk == 0) { wsrc = Wq + g * 64; stride = 512; scale = 0.0078125f; }
            else if (mk == 1) { wsrc = Wkv + g * 64; stride = 1024; }
            else { wsrc = Wkv + 512 + g * 64; stride = 1024; }
            for (int e = t; e < 2048; e += 512) {
                int k = e >> 5, n2 = e & 31;
                float2 v = *(const float2*)(wsrc + (size_t)k * stride + n2 * 2);
                *(uint32_t*)(Wh + k * XS + n2 * 2) = packH(v.x * scale, v.y * scale);
            }
            __syncthreads();
            float c[8][4];
#pragma unroll
            for (int nt = 0; nt < 8; nt++)
#pragma unroll
                for (int i = 0; i < 4; i++) c[nt][i] = 0.f;
#pragma unroll
            for (int ks = 0; ks < 4; ks++) {
                uint32_t ah[4], al[4];
                ldsm4(ah, aAddr(Xh, lane, m0, ks * 16));
                ldsm4(al, aAddr(Xl, lane, m0, ks * 16));
#pragma unroll
                for (int np = 0; np < 4; np++) {
                    uint32_t bh[4];
                    ldsm4t(bh, bAddrT(Wh, lane, ks * 16, np * 16));
#pragma unroll
                    for (int hf = 0; hf < 2; hf++) {
                        float* cc = c[np * 2 + hf];
                        mmaH(cc, ah, bh + hf * 2);
                        mmaH(cc, al, bh + hf * 2);
                    }
                }
            }
#pragma unroll
            for (int nt = 0; nt < 8; nt++) {
                int row = m0 + (lane >> 2), cc = nt * 8 + ((lane & 3) << 1);
                if (mk == 0) {  // Q: hi + lo
                    uint32_t h0, l0, h1, l1;
                    splitH(c[nt][0], c[nt][1], h0, l0);
                    splitH(c[nt][2], c[nt][3], h1, l1);
                    size_t i1 = ((size_t)(g * 256 + row)) * KBIG + r * 64 + cc;
                    size_t i2 = ((size_t)(g * 256 + row + 8)) * KBIG + r * 64 + cc;
                    *(uint32_t*)(g_Qh + i1) = h0;
                    *(uint32_t*)(g_Ql + i1) = l0;
                    *(uint32_t*)(g_Qh + i2) = h1;
                    *(uint32_t*)(g_Ql + i2) = l1;
                } else if (mk == 1) {  // K: hi only
                    size_t i1 = ((size_t)(g * 256 + row)) * KBIG + r * 64 + cc;
                    size_t i2 = ((size_t)(g * 256 + row + 8)) * KBIG + r * 64 + cc;
                    *(uint32_t*)(g_Kh + i1) = packH(c[nt][0], c[nt][1]);
                    *(uint32_t*)(g_Kh + i2) = packH(c[nt][2], c[nt][3]);
                } else {  // V: hi only
                    size_t i1 = ((size_t)(r * 256 + row)) * 512 + g * 64 + cc;
                    size_t i2 = ((size_t)(r * 256 + row + 8)) * 512 + g * 64 + cc;
                    *(uint32_t*)(g_Vh + i1) = packH(c[nt][0], c[nt][1]);
                    *(uint32_t*)(g_Vh + i2) = packH(c[nt][2], c[nt][3]);
                }
            }
            __syncthreads();
        }
    }
}

// ============================================================================
// Height dots: grid (kc=4, it=4, head=8); block 64 i x 256 j, K=4096.
// ============================================================================
__global__ void __launch_bounds__(512, 1) k_hdots_mma() {
    extern __shared__ __half sb[];
    __half* Qh = sb;
    __half* Ql = sb + 64 * XS;
    __half* Kh = sb + 128 * XS;

    const int t = threadIdx.x, lane = t & 31, warp = t >> 5;
    const int kc = blockIdx.x, it = blockIdx.y, head = blockIdx.z;
    const int wm = warp >> 2, wn = warp & 3;
    const int m0 = wm * 16, j0 = wn * 64;

    float c[8][4];
#pragma unroll
    for (int nt = 0; nt < 8; nt++)
#pragma unroll
        for (int i = 0; i < 4; i++) c[nt][i] = 0.f;

    for (int step = 0; step < 64; step++) {
        const int k0 = kc * 4096 + step * 64;
        __syncthreads();
        for (int e = t; e < 2048; e += 512) {
            int row = e >> 5, cp = (e & 31) * 2;
            size_t gi = ((size_t)(head * 256 + it * 64 + row)) * KBIG + k0 + cp;
            *(uint32_t*)(Qh + row * XS + cp) = *(const uint32_t*)(g_Qh + gi);
            *(uint32_t*)(Ql + row * XS + cp) = *(const uint32_t*)(g_Ql + gi);
        }
        for (int e = t; e < 8192; e += 512) {
            int row = e >> 5, cp = (e & 31) * 2;
            size_t gi = ((size_t)(head * 256 + row)) * KBIG + k0 + cp;
            *(uint32_t*)(Kh + row * XS + cp) = *(const uint32_t*)(g_Kh + gi);
        }
        __syncthreads();
#pragma unroll
        for (int ks = 0; ks < 4; ks++) {
            uint32_t ah[4], al[4];
            ldsm4(ah, aAddr(Qh, lane, m0, ks * 16));
            ldsm4(al, aAddr(Ql, lane, m0, ks * 16));
#pragma unroll
            for (int jt = 0; jt < 4; jt++) {
                uint32_t bh[4];
                ldsm4(bh, bAddrN(Kh, lane, j0 + jt * 16, ks * 16));
#pragma unroll
                for (int hf = 0; hf < 2; hf++) {
                    float* cc = c[jt * 2 + hf];
                    mmaH(cc, ah, bh + hf * 2);
                    mmaH(cc, al, bh + hf * 2);
                }
            }
        }
    }
#pragma unroll
    for (int nt = 0; nt < 8; nt++) {
        int row = it * 64 + m0 + (lane >> 2), col = j0 + nt * 8 + ((lane & 3) << 1);
        atomicAdd(&g_DOTS[head * 65536 + row * 256 + col], c[nt][0]);
        atomicAdd(&g_DOTS[head * 65536 + row * 256 + col + 1], c[nt][1]);
        atomicAdd(&g_DOTS[head * 65536 + (row + 8) * 256 + col], c[nt][2]);
        atomicAdd(&g_DOTS[head * 65536 + (row + 8) * 256 + col + 1], c[nt][3]);
    }
}

// ============================================================================
// Softmax (+pair bias) -> normalized P as fp16 hi/lo.
// ============================================================================
__global__ void k_hsm2() {
    const int t = threadIdx.x, warp = t >> 5, lane = t & 31;
    const int row = blockIdx.x * 8 + warp;
    float v[8];
    float mx = -1e30f;
#pragma unroll
    for (int kk = 0; kk < 8; kk++) {
        int j = kk * 32 + lane;
        v[kk] = g_DOTS[row * 256 + j] + g_PB[row * 256 + j];
        mx = fmaxf(mx, v[kk]);
    }
#pragma unroll
    for (int o = 16; o; o >>= 1) mx = fmaxf(mx, __shfl_xor_sync(0xffffffffu, mx, o));
    float s = 0.f;
#pragma unroll
    for (int kk = 0; kk < 8; kk++) { v[kk] = __expf(v[kk] - mx); s += v[kk]; }
#pragma unroll
    for (int o = 16; o; o >>= 1) s += __shfl_xor_sync(0xffffffffu, s, o);
    float inv = 1.f / s;
#pragma unroll
    for (int kk = 0; kk < 8; kk++) {
        float p = v[kk] * inv;
        __half h = __float2half_rn(p);
        g_Ph[row * 256 + kk * 32 + lane] = h;
        g_Pl[row * 256 + kk * 32 + lane] = __float2half_rn(p - __half2float(h));
    }
}

// ============================================================================
// Height AV + out-projection: block (r, head); 16 warps x 16 i rows.
// ============================================================================
__global__ void __launch_bounds__(512, 1)
k_hav_mma(const float* __restrict__ Wout, float* __restrict__ out) {
    extern __shared__ __half sb[];
    __half* Ph = sb;
    __half* Pl = sb + 256 * XS;
    __half* Vh = sb + 512 * XS;
    __half* Wh = sb + 576 * XS;

    const int t = threadIdx.x, lane = t & 31, warp = t >> 5, m0 = warp * 16;
    const int r = blockIdx.x, head = blockIdx.y;

    for (int e = t; e < 2048; e += 512) {
        int k = e >> 5, n2 = e & 31;
        float2 v = *(const float2*)(Wout + (size_t)(head * 64 + k) * 64 + n2 * 2);
        *(uint32_t*)(Wh + k * XS + n2 * 2) = packH(v.x, v.y);
    }

    float o[8][4];
#pragma unroll
    for (int nt = 0; nt < 8; nt++)
#pragma unroll
        for (int i = 0; i < 4; i++) o[nt][i] = 0.f;

    for (int jt = 0; jt < 4; jt++) {
        __syncthreads();
        for (int e = t; e < 8192; e += 512) {
            int row = e >> 5, cp = (e & 31) * 2;
            size_t gi = ((size_t)(head * 256 + row)) * 256 + jt * 64 + cp;
            *(uint32_t*)(Ph + row * XS + cp) = *(const uint32_t*)(g_Ph + gi);
            *(uint32_t*)(Pl + row * XS + cp) = *(const uint32_t*)(g_Pl + gi);
        }
        for (int e = t; e < 2048; e += 512) {
            int row = e >> 5, cp = (e & 31) * 2;
            size_t gi = ((size_t)(r * 256 + jt * 64 + row)) * 512 + head * 64 + cp;
            *(uint32_t*)(Vh + row * XS + cp) = *(const uint32_t*)(g_Vh + gi);
        }
        __syncthreads();
#pragma unroll
        for (int ks = 0; ks < 4; ks++) {
            uint32_t ah[4], al[4];
            ldsm4(ah, aAddr(Ph, lane, m0, ks * 16));
            ldsm4(al, aAddr(Pl, lane, m0, ks * 16));
#pragma unroll
            for (int np = 0; np < 4; np++) {
                uint32_t bh[4];
                ldsm4t(bh, bAddrT(Vh, lane, ks * 16, np * 16));
#pragma unroll
                for (int hf = 0; hf < 2; hf++) {
                    float* oo = o[np * 2 + hf];
                    mmaH(oo, ah, bh + hf * 2);
                    mmaH(oo, al, bh + hf * 2);
                }
            }
        }
    }
    uint32_t oh[4][4], ol[4][4];
#pragma unroll
    for (int ks = 0; ks < 4; ks++) {
        splitH(o[2 * ks][0], o[2 * ks][1], oh[ks][0], ol[ks][0]);
        splitH(o[2 * ks][2], o[2 * ks][3], oh[ks][1], ol[ks][1]);
        splitH(o[2 * ks + 1][0], o[2 * ks + 1][1], oh[ks][2], ol[ks][2]);
        splitH(o[2 * ks + 1][2], o[2 * ks + 1][3], oh[ks][3], ol[ks][3]);
    }
    float rr[8][4];
#pragma unroll
    for (int nt = 0; nt < 8; nt++)
#pragma unroll
        for (int i = 0; i < 4; i++) rr[nt][i] = 0.f;
#pragma unroll
    for (int ks = 0; ks < 4; ks++)
#pragma unroll
        for (int np = 0; np < 4; np++) {
            uint32_t bh[4];
            ldsm4t(bh, bAddrT(Wh, lane, ks * 16, np * 16));
#pragma unroll
            for (int hf = 0; hf < 2; hf++) {
                float* cc = rr[np * 2 + hf];
                mmaH(cc, oh[ks], bh + hf * 2);
                mmaH(cc, ol[ks], bh + hf * 2);
            }
        }
#pragma unroll
    for (int nt = 0; nt < 8; nt++) {
        int row = m0 + (lane >> 2), col = nt * 8 + ((lane & 3) << 1);
        float* op = out + ((size_t)r * WW + row) * DD;
        atomicAdd(op + col, 0.5f * rr[nt][0]);
        atomicAdd(op + col + 1, 0.5f * rr[nt][1]);
        float* op2 = out + ((size_t)r * WW + row + 8) * DD;
        atomicAdd(op2 + col, 0.5f * rr[nt][2]);
        atomicAdd(op2 + col + 1, 0.5f * rr[nt][3]);
    }
}

// ============================ small kernels ==================================
__global__ void k_init(const float* __restrict__ bw, const float* __restrict__ bh,
                       float* __restrict__ out) {
    int idx = blockIdx.x * 256 + threadIdx.x;
    out[idx] = 0.5f * (bw[idx & 63] + bh[idx & 63]);
}
__global__ void k_zero_dots() { g_DOTS[blockIdx.x * 256 + threadIdx.x] = 0.f; }

__global__ void k_pair(const float* __restrict__ pb, const float* __restrict__ g,
                       const float* __restrict__ b, const float* __restrict__ Wp) {
    __shared__ float swp[1024], sg[128], sb2[128];
    const int t = threadIdx.x;
    if (t < 128) { sg[t] = g[t]; sb2[t] = b[t]; }
    for (int e = t; e < 1024; e += 256) swp[e] = Wp[e];
    __syncthreads();
    const int warp = t >> 5, lane = t & 31;
    const int gw = blockIdx.x * 8 + warp;
    const int i = gw >> 8, j = gw & 255;
    const float4* src = (const float4*)(pb + (size_t)gw * 128);
    float4 v = src[lane];
    float s1 = v.x + v.y + v.z + v.w;
    float s2 = v.x * v.x + v.y * v.y + v.z * v.z + v.w * v.w;
#pragma unroll
    for (int o = 16; o; o >>= 1) {
        s1 += __shfl_xor_sync(0xffffffffu, s1, o);
        s2 += __shfl_xor_sync(0xffffffffu, s2, o);
    }
    float mu = s1 * (1.f / 128.f);
    float rstd = rsqrtf(s2 * (1.f / 128.f) - mu * mu + 1e-5f);
    float phd[8];
#pragma unroll
    for (int h = 0; h < 8; h++) phd[h] = 0.f;
    float vv[4] = {v.x, v.y, v.z, v.w};
#pragma unroll
    for (int qi = 0; qi < 4; qi++) {
        int p = lane * 4 + qi;
        float n = (vv[qi] - mu) * rstd * sg[p] + sb2[p];
#pragma unroll
        for (int h = 0; h < 8; h++) phd[h] = fmaf(n, swp[p * 8 + h], phd[h]);
    }
#pragma unroll
    for (int h = 0; h < 8; h++)
#pragma unroll
        for (int o = 16; o; o >>= 1) phd[h] += __shfl_xor_sync(0xffffffffu, phd[h], o);
    if (lane == 0)
#pragma unroll
        for (int h = 0; h < 8; h++) g_PB[h * 65536 + i * 256 + j] = phd[h];
}

// ============================================================================
extern "C" void kernel_launch(void* const* d_in, const int* in_sizes, int n_in,
                              void* d_out, int out_size) {
    (void)in_sizes; (void)n_in; (void)out_size;
    const float* x = (const float*)d_in[0];
    const float* pb = (const float*)d_in[1];
    const float* Wq_w = (const float*)d_in[2];
    const float* Wkv_w = (const float*)d_in[3];
    const float* Wout_w = (const float*)d_in[4];
    const float* bout_w = (const float*)d_in[5];
    const float* Wq_h = (const float*)d_in[6];
    const float* Wkv_h = (const float*)d_in[7];
    const float* Wout_h = (const float*)d_in[8];
    const float* bout_h = (const float*)d_in[9];
    const float* lng = (const float*)d_in[10];
    const float* lnb = (const float*)d_in[11];
    const float* Wp = (const float*)d_in[12];
    float* out = (float*)d_out;

    const int smw = (768 + 64) * XS * 2;   // Xh,Xl,Kh,Wh
    const int smp = (512 + 64) * XS * 2;   // Xh,Xl,Wh
    const int smd = (128 + 256) * XS * 2;  // Qh,Ql,Kh
    const int sma = (512 + 128) * XS * 2;  // Ph,Pl,Vh,Wh
    cudaFuncSetAttribute(k_width_mma, cudaFuncAttributeMaxDynamicSharedMemorySize, smw);
    cudaFuncSetAttribute(k_hproj_mma, cudaFuncAttributeMaxDynamicSharedMemorySize, smp);
    cudaFuncSetAttribute(k_hdots_mma, cudaFuncAttributeMaxDynamicSharedMemorySize, smd);
    cudaFuncSetAttribute(k_hav_mma, cudaFuncAttributeMaxDynamicSharedMemorySize, sma);

    k_init<<<16384, 256>>>(bout_w, bout_h, out);
    k_zero_dots<<<2048, 256>>>();
    k_hproj_mma<<<256, 512, smp>>>(x, Wq_h, Wkv_h);
    k_pair<<<8192, 256>>>(pb, lng, lnb, Wp);
    k_hdots_mma<<<dim3(4, 4, 8), 512, smd>>>();
    k_hsm2<<<256, 256>>>();
    k_hav_mma<<<dim3(256, 8), 512, sma>>>(Wout_h, out);
    k_width_mma<<<dim3(256, 8), 512, smw>>>(x, Wq_w, Wkv_w, Wout_w, out);
}

// round 10
// speedup vs baseline: 1.4572x; 1.4572x over previous
#include <cuda_runtime.h>
#include <cuda_fp16.h>
#include <cstdint>
#include <math.h>

#define HH 256
#define WW 256
#define DD 64
#define NH 8
#define KBIG 16384
#define XS 72

__device__ __half g_Qh[NH * 256 * KBIG], g_Ql[NH * 256 * KBIG];
__device__ __half g_Kh[NH * 256 * KBIG];
__device__ __half g_Vh[256 * 256 * 512];
__device__ __half g_Ph[NH * 256 * 256], g_Pl[NH * 256 * 256];
__device__ float g_DOTS[NH * 256 * 256];
__device__ float g_PB[NH * 256 * 256];

// ---------------- warp-MMA helpers ------------------------------------------
__device__ __forceinline__ void ldsm4(uint32_t* r, uint32_t a) {
    asm volatile("ldmatrix.sync.aligned.m8n8.x4.shared.b16 {%0,%1,%2,%3}, [%4];"
                 : "=r"(r[0]), "=r"(r[1]), "=r"(r[2]), "=r"(r[3]) : "r"(a));
}
__device__ __forceinline__ void ldsm4t(uint32_t* r, uint32_t a) {
    asm volatile("ldmatrix.sync.aligned.m8n8.x4.trans.shared.b16 {%0,%1,%2,%3}, [%4];"
                 : "=r"(r[0]), "=r"(r[1]), "=r"(r[2]), "=r"(r[3]) : "r"(a));
}
__device__ __forceinline__ void mmaH(float* c, const uint32_t* a, const uint32_t* b) {
    asm volatile("mma.sync.aligned.m16n8k16.row.col.f32.f16.f16.f32 "
                 "{%0,%1,%2,%3},{%4,%5,%6,%7},{%8,%9},{%0,%1,%2,%3};"
                 : "+f"(c[0]), "+f"(c[1]), "+f"(c[2]), "+f"(c[3])
                 : "r"(a[0]), "r"(a[1]), "r"(a[2]), "r"(a[3]), "r"(b[0]), "r"(b[1]));
}
__device__ __forceinline__ void splitH(float a, float b, uint32_t& h, uint32_t& l) {
    __half2 hv = __floats2half2_rn(a, b);
    float2 hf = __half22float2(hv);
    __half2 lv = __floats2half2_rn(a - hf.x, b - hf.y);
    h = *reinterpret_cast<uint32_t*>(&hv);
    l = *reinterpret_cast<uint32_t*>(&lv);
}
__device__ __forceinline__ uint32_t packH(float a, float b) {
    __half2 hv = __floats2half2_rn(a, b);
    return *reinterpret_cast<uint32_t*>(&hv);
}
__device__ __forceinline__ uint32_t aAddr(const __half* base, int lane, int r0, int k0) {
    int row = r0 + (lane & 15), col = k0 + ((lane >> 4) << 3);
    return (uint32_t)__cvta_generic_to_shared(base + row * XS + col);
}
__device__ __forceinline__ uint32_t bAddrT(const __half* base, int lane, int k0, int n0) {
    int row = k0 + (lane & 7) + (((lane >> 3) & 1) << 3);
    int col = n0 + ((lane >> 4) << 3);
    return (uint32_t)__cvta_generic_to_shared(base + row * XS + col);
}
__device__ __forceinline__ uint32_t bAddrN(const __half* base, int lane, int j0, int d0) {
    int row = j0 + (lane & 7) + ((lane >> 4) << 3);
    int col = d0 + (((lane >> 3) & 1) << 3);
    return (uint32_t)__cvta_generic_to_shared(base + row * XS + col);
}
#define CP16(sa, gp) asm volatile("cp.async.cg.shared.global [%0], [%1], 16;" :: "r"(sa), "l"(gp))
#define CP_COMMIT()  asm volatile("cp.async.commit_group;" ::: "memory")
#define CP_WAIT0()   asm volatile("cp.async.wait_group 0;" ::: "memory")

// ============================================================================
// Width attention, fp16 split-2 (validated round 9) — unchanged.
// ============================================================================
__global__ void __launch_bounds__(512, 1)
k_width_mma(const float* __restrict__ x, const float* __restrict__ Wq,
            const float* __restrict__ Wkv, const float* __restrict__ Wout,
            float* __restrict__ out) {
    extern __shared__ __half sb[];
    __half* Xh = sb;
    __half* Xl = sb + 256 * XS;
    __half* Kh = sb + 512 * XS;
    __half* Wh = sb + 768 * XS;

    const int t = threadIdx.x, lane = t & 31, warp = t >> 5, m0 = warp * 16;
    const int w = blockIdx.x, head = blockIdx.y;
    {
        int row = t >> 1, q0 = (t & 1) * 8;
        const float4* src = (const float4*)(x + (size_t)row * (WW * DD) + w * DD) + q0;
#pragma unroll
        for (int q4 = 0; q4 < 8; q4++) {
            float4 v = src[q4];
            uint32_t h0, l0, h1, l1;
            splitH(v.x, v.y, h0, l0);
            splitH(v.z, v.w, h1, l1);
            int cc = (q0 + q4) * 4;
            *(uint32_t*)(Xh + row * XS + cc) = h0;
            *(uint32_t*)(Xh + row * XS + cc + 2) = h1;
            *(uint32_t*)(Xl + row * XS + cc) = l0;
            *(uint32_t*)(Xl + row * XS + cc + 2) = l1;
        }
    }
    auto loadW = [&](const float* wsrc, int stride, float scale) {
        for (int e = t; e < 2048; e += 512) {
            int k = e >> 5, n2 = e & 31;
            float2 v = *(const float2*)(wsrc + (size_t)k * stride + n2 * 2);
            *(uint32_t*)(Wh + k * XS + n2 * 2) = packH(v.x * scale, v.y * scale);
        }
    };
    auto proj = [&](float (&c)[8][4]) {
#pragma unroll
        for (int nt = 0; nt < 8; nt++)
#pragma unroll
            for (int i = 0; i < 4; i++) c[nt][i] = 0.f;
#pragma unroll
        for (int ks = 0; ks < 4; ks++) {
            uint32_t ah[4], al[4];
            ldsm4(ah, aAddr(Xh, lane, m0, ks * 16));
            ldsm4(al, aAddr(Xl, lane, m0, ks * 16));
#pragma unroll
            for (int np = 0; np < 4; np++) {
                uint32_t bh[4];
                ldsm4t(bh, bAddrT(Wh, lane, ks * 16, np * 16));
#pragma unroll
                for (int hf = 0; hf < 2; hf++) {
                    float* cc = c[np * 2 + hf];
                    mmaH(cc, ah, bh + hf * 2);
                    mmaH(cc, al, bh + hf * 2);
                }
            }
        }
    };
    auto storeHi = [&](float (&c)[8][4], __half* Dh) {
#pragma unroll
        for (int nt = 0; nt < 8; nt++) {
            int r = m0 + (lane >> 2), cc = nt * 8 + ((lane & 3) << 1);
            *(uint32_t*)(Dh + r * XS + cc) = packH(c[nt][0], c[nt][1]);
            *(uint32_t*)(Dh + (r + 8) * XS + cc) = packH(c[nt][2], c[nt][3]);
        }
    };

    float c[8][4];
    loadW(Wkv + head * 64, 1024, 1.f);
    __syncthreads();
    proj(c);
    storeHi(c, Kh);
    __syncthreads();
    loadW(Wq + head * 64, 512, 0.125f);
    __syncthreads();
    proj(c);
    uint32_t qh[4][4], ql[4][4];
#pragma unroll
    for (int ks = 0; ks < 4; ks++) {
        splitH(c[2 * ks][0], c[2 * ks][1], qh[ks][0], ql[ks][0]);
        splitH(c[2 * ks][2], c[2 * ks][3], qh[ks][1], ql[ks][1]);
        splitH(c[2 * ks + 1][0], c[2 * ks + 1][1], qh[ks][2], ql[ks][2]);
        splitH(c[2 * ks + 1][2], c[2 * ks + 1][3], qh[ks][3], ql[ks][3]);
    }
    __syncthreads();
    loadW(Wkv + 512 + head * 64, 1024, 1.f);
    __syncthreads();
    proj(c);
    storeHi(c, Xh);
    __syncthreads();
    loadW(Wout + (size_t)head * 64 * 64, 64, 1.f);
    __syncthreads();

    float o[8][4];
#pragma unroll
    for (int nt = 0; nt < 8; nt++)
#pragma unroll
        for (int i = 0; i < 4; i++) o[nt][i] = 0.f;
    float lsum[2] = {0.f, 0.f};

    for (int jc = 0; jc < 8; jc++) {
        float s[4][4];
#pragma unroll
        for (int jt = 0; jt < 4; jt++)
#pragma unroll
            for (int i = 0; i < 4; i++) s[jt][i] = 0.f;
#pragma unroll
        for (int ks = 0; ks < 4; ks++) {
            uint32_t kb[2][4];
            ldsm4(kb[0], bAddrN(Kh, lane, jc * 32, ks * 16));
            ldsm4(kb[1], bAddrN(Kh, lane, jc * 32 + 16, ks * 16));
#pragma unroll
            for (int jt = 0; jt < 4; jt++) {
                float* ss = s[jt];
                const uint32_t* bh = &kb[jt >> 1][(jt & 1) * 2];
                mmaH(ss, qh[ks], bh);
                mmaH(ss, ql[ks], bh);
            }
        }
        uint32_t ph[2][4], pl[2][4];
#pragma unroll
        for (int k2 = 0; k2 < 2; k2++) {
            float e0 = __expf(s[2 * k2][0]), e1 = __expf(s[2 * k2][1]);
            float e2 = __expf(s[2 * k2][2]), e3 = __expf(s[2 * k2][3]);
            float f0 = __expf(s[2 * k2 + 1][0]), f1 = __expf(s[2 * k2 + 1][1]);
            float f2 = __expf(s[2 * k2 + 1][2]), f3 = __expf(s[2 * k2 + 1][3]);
            lsum[0] += e0 + e1 + f0 + f1;
            lsum[1] += e2 + e3 + f2 + f3;
            splitH(e0, e1, ph[k2][0], pl[k2][0]);
            splitH(e2, e3, ph[k2][1], pl[k2][1]);
            splitH(f0, f1, ph[k2][2], pl[k2][2]);
            splitH(f2, f3, ph[k2][3], pl[k2][3]);
        }
#pragma unroll
        for (int k2 = 0; k2 < 2; k2++) {
            int j0 = jc * 32 + k2 * 16;
#pragma unroll
            for (int np = 0; np < 4; np++) {
                uint32_t vb[4];
                ldsm4t(vb, bAddrT(Xh, lane, j0, np * 16));
#pragma unroll
                for (int hf = 0; hf < 2; hf++) {
                    float* oo = o[np * 2 + hf];
                    mmaH(oo, ph[k2], vb + hf * 2);
                    mmaH(oo, pl[k2], vb + hf * 2);
                }
            }
        }
    }
#pragma unroll
    for (int i = 0; i < 2; i++) {
        lsum[i] += __shfl_xor_sync(0xffffffffu, lsum[i], 1);
        lsum[i] += __shfl_xor_sync(0xffffffffu, lsum[i], 2);
    }
    float i0 = 1.f / lsum[0], i1 = 1.f / lsum[1];
    uint32_t oh[4][4], ol[4][4];
#pragma unroll
    for (int ks = 0; ks < 4; ks++) {
        splitH(o[2 * ks][0] * i0, o[2 * ks][1] * i0, oh[ks][0], ol[ks][0]);
        splitH(o[2 * ks][2] * i1, o[2 * ks][3] * i1, oh[ks][1], ol[ks][1]);
        splitH(o[2 * ks + 1][0] * i0, o[2 * ks + 1][1] * i0, oh[ks][2], ol[ks][2]);
        splitH(o[2 * ks + 1][2] * i1, o[2 * ks + 1][3] * i1, oh[ks][3], ol[ks][3]);
    }
    float r[8][4];
#pragma unroll
    for (int nt = 0; nt < 8; nt++)
#pragma unroll
        for (int i = 0; i < 4; i++) r[nt][i] = 0.f;
#pragma unroll
    for (int ks = 0; ks < 4; ks++)
#pragma unroll
        for (int np = 0; np < 4; np++) {
            uint32_t bh[4];
            ldsm4t(bh, bAddrT(Wh, lane, ks * 16, np * 16));
#pragma unroll
            for (int hf = 0; hf < 2; hf++) {
                float* rr = r[np * 2 + hf];
                mmaH(rr, oh[ks], bh + hf * 2);
                mmaH(rr, ol[ks], bh + hf * 2);
            }
        }
#pragma unroll
    for (int nt = 0; nt < 8; nt++) {
        int row = m0 + (lane >> 2), col = nt * 8 + ((lane & 3) << 1);
        float* op = out + ((size_t)row * WW + w) * DD;
        atomicAdd(op + col, 0.5f * r[nt][0]);
        atomicAdd(op + col + 1, 0.5f * r[nt][1]);
        float* op2 = out + ((size_t)(row + 8) * WW + w) * DD;
        atomicAdd(op2 + col, 0.5f * r[nt][2]);
        atomicAdd(op2 + col + 1, 0.5f * r[nt][3]);
    }
}

// ============================================================================
// Height projection (validated round 9) — unchanged.
// ============================================================================
__global__ void __launch_bounds__(512, 1)
k_hproj_mma(const float* __restrict__ x, const float* __restrict__ Wq,
            const float* __restrict__ Wkv) {
    extern __shared__ __half sb[];
    __half* Xh = sb;
    __half* Xl = sb + 256 * XS;
    __half* Wh = sb + 512 * XS;

    const int t = threadIdx.x, lane = t & 31, warp = t >> 5, m0 = warp * 16;
    const int r = blockIdx.x;
    {
        int row = t >> 1, q0 = (t & 1) * 8;
        const float4* src = (const float4*)(x + (size_t)r * (WW * DD) + row * 64) + q0;
#pragma unroll
        for (int q4 = 0; q4 < 8; q4++) {
            float4 v = src[q4];
            uint32_t h0, l0, h1, l1;
            splitH(v.x, v.y, h0, l0);
            splitH(v.z, v.w, h1, l1);
            int cc = (q0 + q4) * 4;
            *(uint32_t*)(Xh + row * XS + cc) = h0;
            *(uint32_t*)(Xh + row * XS + cc + 2) = h1;
            *(uint32_t*)(Xl + row * XS + cc) = l0;
            *(uint32_t*)(Xl + row * XS + cc + 2) = l1;
        }
    }
    for (int mk = 0; mk < 3; mk++) {
        for (int g = 0; g < 8; g++) {
            const float* wsrc;
            int stride;
            float scale = 1.f;
            if (mk == 0) { wsrc = Wq + g * 64; stride = 512; scale = 0.0078125f; }
            else if (mk == 1) { wsrc = Wkv + g * 64; stride = 1024; }
            else { wsrc = Wkv + 512 + g * 64; stride = 1024; }
            for (int e = t; e < 2048; e += 512) {
                int k = e >> 5, n2 = e & 31;
                float2 v = *(const float2*)(wsrc + (size_t)k * stride + n2 * 2);
                *(uint32_t*)(Wh + k * XS + n2 * 2) = packH(v.x * scale, v.y * scale);
            }
            __syncthreads();
            float c[8][4];
#pragma unroll
            for (int nt = 0; nt < 8; nt++)
#pragma unroll
                for (int i = 0; i < 4; i++) c[nt][i] = 0.f;
#pragma unroll
            for (int ks = 0; ks < 4; ks++) {
                uint32_t ah[4], al[4];
                ldsm4(ah, aAddr(Xh, lane, m0, ks * 16));
                ldsm4(al, aAddr(Xl, lane, m0, ks * 16));
#pragma unroll
                for (int np = 0; np < 4; np++) {
                    uint32_t bh[4];
                    ldsm4t(bh, bAddrT(Wh, lane, ks * 16, np * 16));
#pragma unroll
                    for (int hf = 0; hf < 2; hf++) {
                        float* cc = c[np * 2 + hf];
                        mmaH(cc, ah, bh + hf * 2);
                        mmaH(cc, al, bh + hf * 2);
                    }
                }
            }
#pragma unroll
            for (int nt = 0; nt < 8; nt++) {
                int row = m0 + (lane >> 2), cc = nt * 8 + ((lane & 3) << 1);
                if (mk == 0) {
                    uint32_t h0, l0, h1, l1;
                    splitH(c[nt][0], c[nt][1], h0, l0);
                    splitH(c[nt][2], c[nt][3], h1, l1);
                    size_t i1 = ((size_t)(g * 256 + row)) * KBIG + r * 64 + cc;
                    size_t i2 = ((size_t)(g * 256 + row + 8)) * KBIG + r * 64 + cc;
                    *(uint32_t*)(g_Qh + i1) = h0;
                    *(uint32_t*)(g_Ql + i1) = l0;
                    *(uint32_t*)(g_Qh + i2) = h1;
                    *(uint32_t*)(g_Ql + i2) = l1;
                } else if (mk == 1) {
                    size_t i1 = ((size_t)(g * 256 + row)) * KBIG + r * 64 + cc;
                    size_t i2 = ((size_t)(g * 256 + row + 8)) * KBIG + r * 64 + cc;
                    *(uint32_t*)(g_Kh + i1) = packH(c[nt][0], c[nt][1]);
                    *(uint32_t*)(g_Kh + i2) = packH(c[nt][2], c[nt][3]);
                } else {
                    size_t i1 = ((size_t)(r * 256 + row)) * 512 + g * 64 + cc;
                    size_t i2 = ((size_t)(r * 256 + row + 8)) * 512 + g * 64 + cc;
                    *(uint32_t*)(g_Vh + i1) = packH(c[nt][0], c[nt][1]);
                    *(uint32_t*)(g_Vh + i2) = packH(c[nt][2], c[nt][3]);
                }
            }
            __syncthreads();
        }
    }
}

// ============================================================================
// Height dots, double-buffered via cp.async. Buffer = 384 rows (Qh64,Ql64,Kh256).
// ============================================================================
__global__ void __launch_bounds__(512, 1) k_hdots_mma() {
    extern __shared__ __half sb[];
    const int t = threadIdx.x, lane = t & 31, warp = t >> 5;
    const int kc = blockIdx.x, it = blockIdx.y, head = blockIdx.z;
    const int wm = warp >> 2, wn = warp & 3;
    const int m0 = wm * 16, j0 = wn * 64;

    auto issue = [&](__half* base, int step) {
        const int k0 = kc * 4096 + step * 64;
#pragma unroll
        for (int rr2 = 0; rr2 < 6; rr2++) {
            int e = rr2 * 512 + t;
            const __half* gp;
            uint32_t sa;
            if (e < 1024) {
                int row = (e & 511) >> 3, c8 = e & 7;
                size_t gi = ((size_t)(head * 256 + it * 64 + row)) * KBIG + k0 + c8 * 8;
                if (e < 512) { gp = g_Qh + gi; sa = (uint32_t)__cvta_generic_to_shared(base + row * XS + c8 * 8); }
                else { gp = g_Ql + gi; sa = (uint32_t)__cvta_generic_to_shared(base + (64 + row) * XS + c8 * 8); }
            } else {
                int idx = e - 1024, row = idx >> 3, c8 = idx & 7;
                gp = g_Kh + ((size_t)(head * 256 + row)) * KBIG + k0 + c8 * 8;
                sa = (uint32_t)__cvta_generic_to_shared(base + (128 + row) * XS + c8 * 8);
            }
            CP16(sa, gp);
        }
        CP_COMMIT();
    };

    float c[8][4];
#pragma unroll
    for (int nt = 0; nt < 8; nt++)
#pragma unroll
        for (int i = 0; i < 4; i++) c[nt][i] = 0.f;

    issue(sb, 0);
    for (int step = 0; step < 64; step++) {
        CP_WAIT0();
        __syncthreads();
        __half* cur = sb + (step & 1) * 384 * XS;
        if (step + 1 < 64) issue(sb + ((step + 1) & 1) * 384 * XS, step + 1);
        __half* Qh = cur;
        __half* Ql = cur + 64 * XS;
        __half* Kh = cur + 128 * XS;
#pragma unroll
        for (int ks = 0; ks < 4; ks++) {
            uint32_t ah[4], al[4];
            ldsm4(ah, aAddr(Qh, lane, m0, ks * 16));
            ldsm4(al, aAddr(Ql, lane, m0, ks * 16));
#pragma unroll
            for (int jt = 0; jt < 4; jt++) {
                uint32_t bh[4];
                ldsm4(bh, bAddrN(Kh, lane, j0 + jt * 16, ks * 16));
#pragma unroll
                for (int hf = 0; hf < 2; hf++) {
                    float* cc = c[jt * 2 + hf];
                    mmaH(cc, ah, bh + hf * 2);
                    mmaH(cc, al, bh + hf * 2);
                }
            }
        }
    }
#pragma unroll
    for (int nt = 0; nt < 8; nt++) {
        int row = it * 64 + m0 + (lane >> 2), col = j0 + nt * 8 + ((lane & 3) << 1);
        atomicAdd(&g_DOTS[head * 65536 + row * 256 + col], c[nt][0]);
        atomicAdd(&g_DOTS[head * 65536 + row * 256 + col + 1], c[nt][1]);
        atomicAdd(&g_DOTS[head * 65536 + (row + 8) * 256 + col], c[nt][2]);
        atomicAdd(&g_DOTS[head * 65536 + (row + 8) * 256 + col + 1], c[nt][3]);
    }
}

// ============================================================================
// Softmax (+pair bias) -> normalized P as fp16 hi/lo.
// ============================================================================
__global__ void k_hsm2() {
    const int t = threadIdx.x, warp = t >> 5, lane = t & 31;
    const int row = blockIdx.x * 8 + warp;
    float v[8];
    float mx = -1e30f;
#pragma unroll
    for (int kk = 0; kk < 8; kk++) {
        int j = kk * 32 + lane;
        v[kk] = g_DOTS[row * 256 + j] + g_PB[row * 256 + j];
        mx = fmaxf(mx, v[kk]);
    }
#pragma unroll
    for (int o = 16; o; o >>= 1) mx = fmaxf(mx, __shfl_xor_sync(0xffffffffu, mx, o));
    float s = 0.f;
#pragma unroll
    for (int kk = 0; kk < 8; kk++) { v[kk] = __expf(v[kk] - mx); s += v[kk]; }
#pragma unroll
    for (int o = 16; o; o >>= 1) s += __shfl_xor_sync(0xffffffffu, s, o);
    float inv = 1.f / s;
#pragma unroll
    for (int kk = 0; kk < 8; kk++) {
        float p = v[kk] * inv;
        __half h = __float2half_rn(p);
        g_Ph[row * 256 + kk * 32 + lane] = h;
        g_Pl[row * 256 + kk * 32 + lane] = __float2half_rn(p - __half2float(h));
    }
}

// ============================================================================
// Height AV + out-projection, double-buffered. Buffer = 576 rows (Ph,Pl,Vh);
// W at fixed offset 1152 rows.
// ============================================================================
__global__ void __launch_bounds__(512, 1)
k_hav_mma(const float* __restrict__ Wout, float* __restrict__ out) {
    extern __shared__ __half sb[];
    __half* Wh = sb + 1152 * XS;

    const int t = threadIdx.x, lane = t & 31, warp = t >> 5, m0 = warp * 16;
    const int r = blockIdx.x, head = blockIdx.y;

    for (int e = t; e < 2048; e += 512) {
        int k = e >> 5, n2 = e & 31;
        float2 v = *(const float2*)(Wout + (size_t)(head * 64 + k) * 64 + n2 * 2);
        *(uint32_t*)(Wh + k * XS + n2 * 2) = packH(v.x, v.y);
    }

    auto issue = [&](__half* base, int jt) {
#pragma unroll
        for (int rr2 = 0; rr2 < 9; rr2++) {
            int e = rr2 * 512 + t;
            const __half* gp;
            uint32_t sa;
            if (e < 4096) {
                int idx = e & 2047, row = idx >> 3, c8 = idx & 7;
                size_t gi = ((size_t)(head * 256 + row)) * 256 + jt * 64 + c8 * 8;
                if (e < 2048) { gp = g_Ph + gi; sa = (uint32_t)__cvta_generic_to_shared(base + row * XS + c8 * 8); }
                else { gp = g_Pl + gi; sa = (uint32_t)__cvta_generic_to_shared(base + (256 + row) * XS + c8 * 8); }
            } else {
                int idx = e - 4096, row = idx >> 3, c8 = idx & 7;
                gp = g_Vh + ((size_t)(r * 256 + jt * 64 + row)) * 512 + head * 64 + c8 * 8;
                sa = (uint32_t)__cvta_generic_to_shared(base + (512 + row) * XS + c8 * 8);
            }
            CP16(sa, gp);
        }
        CP_COMMIT();
    };

    float o[8][4];
#pragma unroll
    for (int nt = 0; nt < 8; nt++)
#pragma unroll
        for (int i = 0; i < 4; i++) o[nt][i] = 0.f;

    issue(sb, 0);
    for (int jt = 0; jt < 4; jt++) {
        CP_WAIT0();
        __syncthreads();
        __half* cur = sb + (jt & 1) * 576 * XS;
        if (jt + 1 < 4) issue(sb + ((jt + 1) & 1) * 576 * XS, jt + 1);
        __half* Ph = cur;
        __half* Pl = cur + 256 * XS;
        __half* Vh = cur + 512 * XS;
#pragma unroll
        for (int ks = 0; ks < 4; ks++) {
            uint32_t ah[4], al[4];
            ldsm4(ah, aAddr(Ph, lane, m0, ks * 16));
            ldsm4(al, aAddr(Pl, lane, m0, ks * 16));
#pragma unroll
            for (int np = 0; np < 4; np++) {
                uint32_t bh[4];
                ldsm4t(bh, bAddrT(Vh, lane, ks * 16, np * 16));
#pragma unroll
                for (int hf = 0; hf < 2; hf++) {
                    float* oo = o[np * 2 + hf];
                    mmaH(oo, ah, bh + hf * 2);
                    mmaH(oo, al, bh + hf * 2);
                }
            }
        }
    }
    uint32_t oh[4][4], ol[4][4];
#pragma unroll
    for (int ks = 0; ks < 4; ks++) {
        splitH(o[2 * ks][0], o[2 * ks][1], oh[ks][0], ol[ks][0]);
        splitH(o[2 * ks][2], o[2 * ks][3], oh[ks][1], ol[ks][1]);
        splitH(o[2 * ks + 1][0], o[2 * ks + 1][1], oh[ks][2], ol[ks][2]);
        splitH(o[2 * ks + 1][2], o[2 * ks + 1][3], oh[ks][3], ol[ks][3]);
    }
    float rr[8][4];
#pragma unroll
    for (int nt = 0; nt < 8; nt++)
#pragma unroll
        for (int i = 0; i < 4; i++) rr[nt][i] = 0.f;
#pragma unroll
    for (int ks = 0; ks < 4; ks++)
#pragma unroll
        for (int np = 0; np < 4; np++) {
            uint32_t bh[4];
            ldsm4t(bh, bAddrT(Wh, lane, ks * 16, np * 16));
#pragma unroll
            for (int hf = 0; hf < 2; hf++) {
                float* cc = rr[np * 2 + hf];
                mmaH(cc, oh[ks], bh + hf * 2);
                mmaH(cc, ol[ks], bh + hf * 2);
            }
        }
#pragma unroll
    for (int nt = 0; nt < 8; nt++) {
        int row = m0 + (lane >> 2), col = nt * 8 + ((lane & 3) << 1);
        float* op = out + ((size_t)r * WW + row) * DD;
        atomicAdd(op + col, 0.5f * rr[nt][0]);
        atomicAdd(op + col + 1, 0.5f * rr[nt][1]);
        float* op2 = out + ((size_t)r * WW + row + 8) * DD;
        atomicAdd(op2 + col, 0.5f * rr[nt][2]);
        atomicAdd(op2 + col + 1, 0.5f * rr[nt][3]);
    }
}

// ============================ small kernels ==================================
__global__ void k_init(const float* __restrict__ bw, const float* __restrict__ bh,
                       float* __restrict__ out) {
    int idx = blockIdx.x * 256 + threadIdx.x;
    out[idx] = 0.5f * (bw[idx & 63] + bh[idx & 63]);
}
__global__ void k_zero_dots() { g_DOTS[blockIdx.x * 256 + threadIdx.x] = 0.f; }

// Pair bias: smem-free — per-lane W slice is contiguous 128B -> registers.
__global__ void k_pair(const float* __restrict__ pb, const float* __restrict__ g,
                       const float* __restrict__ b, const float* __restrict__ Wp) {
    const int t = threadIdx.x;
    const int warp = t >> 5, lane = t & 31;
    const int gw = blockIdx.x * 8 + warp;
    const int i = gw >> 8, j = gw & 255;

    float4 gv = ((const float4*)g)[lane];
    float4 bv = ((const float4*)b)[lane];
    float gvv[4] = {gv.x, gv.y, gv.z, gv.w};
    float bvv[4] = {bv.x, bv.y, bv.z, bv.w};
    float wreg[4][8];
#pragma unroll
    for (int qi = 0; qi < 4; qi++) {
        float4 wa = *(const float4*)(Wp + (size_t)(lane * 4 + qi) * 8);
        float4 wb = *(const float4*)(Wp + (size_t)(lane * 4 + qi) * 8 + 4);
        wreg[qi][0] = wa.x; wreg[qi][1] = wa.y; wreg[qi][2] = wa.z; wreg[qi][3] = wa.w;
        wreg[qi][4] = wb.x; wreg[qi][5] = wb.y; wreg[qi][6] = wb.z; wreg[qi][7] = wb.w;
    }

    const float4* src = (const float4*)(pb + (size_t)gw * 128);
    float4 v = src[lane];
    float s1 = v.x + v.y + v.z + v.w;
    float s2 = v.x * v.x + v.y * v.y + v.z * v.z + v.w * v.w;
#pragma unroll
    for (int o = 16; o; o >>= 1) {
        s1 += __shfl_xor_sync(0xffffffffu, s1, o);
        s2 += __shfl_xor_sync(0xffffffffu, s2, o);
    }
    float mu = s1 * (1.f / 128.f);
    float rstd = rsqrtf(s2 * (1.f / 128.f) - mu * mu + 1e-5f);
    float phd[8];
#pragma unroll
    for (int h = 0; h < 8; h++) phd[h] = 0.f;
    float vv[4] = {v.x, v.y, v.z, v.w};
#pragma unroll
    for (int qi = 0; qi < 4; qi++) {
        float n = (vv[qi] - mu) * rstd * gvv[qi] + bvv[qi];
#pragma unroll
        for (int h = 0; h < 8; h++) phd[h] = fmaf(n, wreg[qi][h], phd[h]);
    }
#pragma unroll
    for (int h = 0; h < 8; h++)
#pragma unroll
        for (int o = 16; o; o >>= 1) phd[h] += __shfl_xor_sync(0xffffffffu, phd[h], o);
    if (lane == 0)
#pragma unroll
        for (int h = 0; h < 8; h++) g_PB[h * 65536 + i * 256 + j] = phd[h];
}

// ============================================================================
extern "C" void kernel_launch(void* const* d_in, const int* in_sizes, int n_in,
                              void* d_out, int out_size) {
    (void)in_sizes; (void)n_in; (void)out_size;
    const float* x = (const float*)d_in[0];
    const float* pb = (const float*)d_in[1];
    const float* Wq_w = (const float*)d_in[2];
    const float* Wkv_w = (const float*)d_in[3];
    const float* Wout_w = (const float*)d_in[4];
    const float* bout_w = (const float*)d_in[5];
    const float* Wq_h = (const float*)d_in[6];
    const float* Wkv_h = (const float*)d_in[7];
    const float* Wout_h = (const float*)d_in[8];
    const float* bout_h = (const float*)d_in[9];
    const float* lng = (const float*)d_in[10];
    const float* lnb = (const float*)d_in[11];
    const float* Wp = (const float*)d_in[12];
    float* out = (float*)d_out;

    const int smw = (768 + 64) * XS * 2;
    const int smp = (512 + 64) * XS * 2;
    const int smd = 2 * 384 * XS * 2;          // double-buffered Q/K
    const int sma = (2 * 576 + 64) * XS * 2;   // double-buffered P/V + W
    cudaFuncSetAttribute(k_width_mma, cudaFuncAttributeMaxDynamicSharedMemorySize, smw);
    cudaFuncSetAttribute(k_hproj_mma, cudaFuncAttributeMaxDynamicSharedMemorySize, smp);
    cudaFuncSetAttribute(k_hdots_mma, cudaFuncAttributeMaxDynamicSharedMemorySize, smd);
    cudaFuncSetAttribute(k_hav_mma, cudaFuncAttributeMaxDynamicSharedMemorySize, sma);

    k_init<<<16384, 256>>>(bout_w, bout_h, out);
    k_zero_dots<<<2048, 256>>>();
    k_hproj_mma<<<256, 512, smp>>>(x, Wq_h, Wkv_h);
    k_pair<<<8192, 256>>>(pb, lng, lnb, Wp);
    k_hdots_mma<<<dim3(4, 4, 8), 512, smd>>>();
    k_hsm2<<<256, 256>>>();
    k_hav_mma<<<dim3(256, 8), 512, sma>>>(Wout_h, out);
    k_width_mma<<<dim3(256, 8), 512, smw>>>(x, Wq_w, Wkv_w, Wout_w, out);
}

// round 11
// speedup vs baseline: 1.6268x; 1.1164x over previous
#include <cuda_runtime.h>
#include <cuda_fp16.h>
#include <cstdint>
#include <math.h>

#define HH 256
#define WW 256
#define DD 64
#define NH 8
#define KBIG 16384
#define XS 72

__device__ __half g_Qh[NH * 256 * KBIG], g_Ql[NH * 256 * KBIG];
__device__ __half g_Kh[NH * 256 * KBIG];
__device__ __half g_Vh[256 * 256 * 512];
__device__ __half g_Ph[NH * 256 * 256], g_Pl[NH * 256 * 256];
__device__ float g_DOTS[NH * 256 * 256];
__device__ float g_PB[NH * 256 * 256];
__device__ __half g_Wwid[4 * 8 * 64 * 64];  // width: [mat(K,Q,V,O)][head][k][n] fp16
__device__ __half g_Whgt[3 * 8 * 64 * 64];  // height: [mk(Q,K,V)][g][k][n] fp16

// ---------------- warp-MMA helpers ------------------------------------------
__device__ __forceinline__ void ldsm4(uint32_t* r, uint32_t a) {
    asm volatile("ldmatrix.sync.aligned.m8n8.x4.shared.b16 {%0,%1,%2,%3}, [%4];"
                 : "=r"(r[0]), "=r"(r[1]), "=r"(r[2]), "=r"(r[3]) : "r"(a));
}
__device__ __forceinline__ void ldsm4t(uint32_t* r, uint32_t a) {
    asm volatile("ldmatrix.sync.aligned.m8n8.x4.trans.shared.b16 {%0,%1,%2,%3}, [%4];"
                 : "=r"(r[0]), "=r"(r[1]), "=r"(r[2]), "=r"(r[3]) : "r"(a));
}
__device__ __forceinline__ void mmaH(float* c, const uint32_t* a, const uint32_t* b) {
    asm volatile("mma.sync.aligned.m16n8k16.row.col.f32.f16.f16.f32 "
                 "{%0,%1,%2,%3},{%4,%5,%6,%7},{%8,%9},{%0,%1,%2,%3};"
                 : "+f"(c[0]), "+f"(c[1]), "+f"(c[2]), "+f"(c[3])
                 : "r"(a[0]), "r"(a[1]), "r"(a[2]), "r"(a[3]), "r"(b[0]), "r"(b[1]));
}
__device__ __forceinline__ void splitH(float a, float b, uint32_t& h, uint32_t& l) {
    __half2 hv = __floats2half2_rn(a, b);
    float2 hf = __half22float2(hv);
    __half2 lv = __floats2half2_rn(a - hf.x, b - hf.y);
    h = *reinterpret_cast<uint32_t*>(&hv);
    l = *reinterpret_cast<uint32_t*>(&lv);
}
__device__ __forceinline__ uint32_t packH(float a, float b) {
    __half2 hv = __floats2half2_rn(a, b);
    return *reinterpret_cast<uint32_t*>(&hv);
}
__device__ __forceinline__ uint32_t aAddr(const __half* base, int lane, int r0, int k0) {
    int row = r0 + (lane & 15), col = k0 + ((lane >> 4) << 3);
    return (uint32_t)__cvta_generic_to_shared(base + row * XS + col);
}
__device__ __forceinline__ uint32_t bAddrT(const __half* base, int lane, int k0, int n0) {
    int row = k0 + (lane & 7) + (((lane >> 3) & 1) << 3);
    int col = n0 + ((lane >> 4) << 3);
    return (uint32_t)__cvta_generic_to_shared(base + row * XS + col);
}
__device__ __forceinline__ uint32_t bAddrN(const __half* base, int lane, int j0, int d0) {
    int row = j0 + (lane & 7) + ((lane >> 4) << 3);
    int col = d0 + (((lane >> 3) & 1) << 3);
    return (uint32_t)__cvta_generic_to_shared(base + row * XS + col);
}
#define CP16(sa, gp) asm volatile("cp.async.cg.shared.global [%0], [%1], 16;" :: "r"(sa), "l"(gp))
#define CP_COMMIT()  asm volatile("cp.async.commit_group;" ::: "memory")
#define CP_WAIT0()   asm volatile("cp.async.wait_group 0;" ::: "memory")

// ============================================================================
// One-time weight conversion to fp16 (scales folded).
// ============================================================================
__global__ void k_wconv(const float* __restrict__ Wq_w, const float* __restrict__ Wkv_w,
                        const float* __restrict__ Wout_w, const float* __restrict__ Wq_h,
                        const float* __restrict__ Wkv_h) {
    int idx = blockIdx.x * 512 + threadIdx.x;
    if (idx < 131072) {
        int mat = idx >> 15, rem = idx & 32767, head = rem >> 12, e = rem & 4095;
        int k = e >> 6, n = e & 63;
        float v;
        if (mat == 0) v = Wkv_w[k * 1024 + head * 64 + n];
        else if (mat == 1) v = Wq_w[k * 512 + head * 64 + n] * 0.125f;
        else if (mat == 2) v = Wkv_w[k * 1024 + 512 + head * 64 + n];
        else v = Wout_w[(head * 64 + k) * 64 + n];
        g_Wwid[idx] = __float2half_rn(v);
    } else if (idx < 229376) {
        int j = idx - 131072;
        int mk = j >> 15, rem = j & 32767, gg = rem >> 12, e = rem & 4095;
        int k = e >> 6, n = e & 63;
        float v;
        if (mk == 0) v = Wq_h[k * 512 + gg * 64 + n] * 0.0078125f;
        else if (mk == 1) v = Wkv_h[k * 1024 + gg * 64 + n];
        else v = Wkv_h[k * 1024 + 512 + gg * 64 + n];
        g_Whgt[j] = __float2half_rn(v);
    }
}

// ============================================================================
// Width attention, fp16 split-2, double-buffered W (fp16 pre-converted).
// smem rows: Xh 256, Xl 256, Kh 256, W0 64, W1 64  (=896 rows)
// ============================================================================
__global__ void __launch_bounds__(512, 1)
k_width_mma(const float* __restrict__ x, float* __restrict__ out) {
    extern __shared__ __half sb[];
    __half* Xh = sb;
    __half* Xl = sb + 256 * XS;
    __half* Kh = sb + 512 * XS;
    __half* W0 = sb + 768 * XS;
    __half* W1 = sb + 832 * XS;

    const int t = threadIdx.x, lane = t & 31, warp = t >> 5, m0 = warp * 16;
    const int w = blockIdx.x, head = blockIdx.y;

    auto loadW = [&](__half* dst, int mat) {
        const __half* src = g_Wwid + (size_t)(mat * 8 + head) * 4096;
        for (int e = t; e < 2048; e += 512) {
            int k = e >> 5, n2 = e & 31;
            *(uint32_t*)(dst + k * XS + n2 * 2) = *(const uint32_t*)(src + k * 64 + n2 * 2);
        }
    };
    loadW(W0, 0);  // Wk — issue before the X conversion to overlap
    {
        int row = t >> 1, q0 = (t & 1) * 8;
        const float4* src = (const float4*)(x + (size_t)row * (WW * DD) + w * DD) + q0;
#pragma unroll
        for (int q4 = 0; q4 < 8; q4++) {
            float4 v = src[q4];
            uint32_t h0, l0, h1, l1;
            splitH(v.x, v.y, h0, l0);
            splitH(v.z, v.w, h1, l1);
            int cc = (q0 + q4) * 4;
            *(uint32_t*)(Xh + row * XS + cc) = h0;
            *(uint32_t*)(Xh + row * XS + cc + 2) = h1;
            *(uint32_t*)(Xl + row * XS + cc) = l0;
            *(uint32_t*)(Xl + row * XS + cc + 2) = l1;
        }
    }
    auto proj = [&](float (&c)[8][4], const __half* Wb) {
#pragma unroll
        for (int nt = 0; nt < 8; nt++)
#pragma unroll
            for (int i = 0; i < 4; i++) c[nt][i] = 0.f;
#pragma unroll
        for (int ks = 0; ks < 4; ks++) {
            uint32_t ah[4], al[4];
            ldsm4(ah, aAddr(Xh, lane, m0, ks * 16));
            ldsm4(al, aAddr(Xl, lane, m0, ks * 16));
#pragma unroll
            for (int np = 0; np < 4; np++) {
                uint32_t bh[4];
                ldsm4t(bh, bAddrT(Wb, lane, ks * 16, np * 16));
#pragma unroll
                for (int hf = 0; hf < 2; hf++) {
                    float* cc = c[np * 2 + hf];
                    mmaH(cc, ah, bh + hf * 2);
                    mmaH(cc, al, bh + hf * 2);
                }
            }
        }
    };
    auto storeHi = [&](float (&c)[8][4], __half* Dh) {
#pragma unroll
        for (int nt = 0; nt < 8; nt++) {
            int r = m0 + (lane >> 2), cc = nt * 8 + ((lane & 3) << 1);
            *(uint32_t*)(Dh + r * XS + cc) = packH(c[nt][0], c[nt][1]);
            *(uint32_t*)(Dh + (r + 8) * XS + cc) = packH(c[nt][2], c[nt][3]);
        }
    };

    float c[8][4];
    __syncthreads();          // X + Wk ready
    loadW(W1, 1);             // prefetch Wq during K projection
    proj(c, W0);
    storeHi(c, Kh);
    __syncthreads();          // K + Wq ready
    loadW(W0, 2);             // prefetch Wv during Q projection
    proj(c, W1);
    uint32_t qh[4][4], ql[4][4];
#pragma unroll
    for (int ks = 0; ks < 4; ks++) {
        splitH(c[2 * ks][0], c[2 * ks][1], qh[ks][0], ql[ks][0]);
        splitH(c[2 * ks][2], c[2 * ks][3], qh[ks][1], ql[ks][1]);
        splitH(c[2 * ks + 1][0], c[2 * ks + 1][1], qh[ks][2], ql[ks][2]);
        splitH(c[2 * ks + 1][2], c[2 * ks + 1][3], qh[ks][3], ql[ks][3]);
    }
    __syncthreads();          // Wv ready
    loadW(W1, 3);             // prefetch Wout during V projection
    proj(c, W0);
    storeHi(c, Xh);           // V overwrites X (own rows; warp-local)
    __syncthreads();          // V + Wout ready

    float o[8][4];
#pragma unroll
    for (int nt = 0; nt < 8; nt++)
#pragma unroll
        for (int i = 0; i < 4; i++) o[nt][i] = 0.f;
    float lsum[2] = {0.f, 0.f};

    for (int jc = 0; jc < 8; jc++) {
        float s[4][4];
#pragma unroll
        for (int jt = 0; jt < 4; jt++)
#pragma unroll
            for (int i = 0; i < 4; i++) s[jt][i] = 0.f;
#pragma unroll
        for (int ks = 0; ks < 4; ks++) {
            uint32_t kb[2][4];
            ldsm4(kb[0], bAddrN(Kh, lane, jc * 32, ks * 16));
            ldsm4(kb[1], bAddrN(Kh, lane, jc * 32 + 16, ks * 16));
#pragma unroll
            for (int jt = 0; jt < 4; jt++) {
                float* ss = s[jt];
                const uint32_t* bh = &kb[jt >> 1][(jt & 1) * 2];
                mmaH(ss, qh[ks], bh);
                mmaH(ss, ql[ks], bh);
            }
        }
        uint32_t ph[2][4], pl[2][4];
#pragma unroll
        for (int k2 = 0; k2 < 2; k2++) {
            float e0 = __expf(s[2 * k2][0]), e1 = __expf(s[2 * k2][1]);
            float e2 = __expf(s[2 * k2][2]), e3 = __expf(s[2 * k2][3]);
            float f0 = __expf(s[2 * k2 + 1][0]), f1 = __expf(s[2 * k2 + 1][1]);
            float f2 = __expf(s[2 * k2 + 1][2]), f3 = __expf(s[2 * k2 + 1][3]);
            lsum[0] += e0 + e1 + f0 + f1;
            lsum[1] += e2 + e3 + f2 + f3;
            splitH(e0, e1, ph[k2][0], pl[k2][0]);
            splitH(e2, e3, ph[k2][1], pl[k2][1]);
            splitH(f0, f1, ph[k2][2], pl[k2][2]);
            splitH(f2, f3, ph[k2][3], pl[k2][3]);
        }
#pragma unroll
        for (int k2 = 0; k2 < 2; k2++) {
            int j0 = jc * 32 + k2 * 16;
#pragma unroll
            for (int np = 0; np < 4; np++) {
                uint32_t vb[4];
                ldsm4t(vb, bAddrT(Xh, lane, j0, np * 16));
#pragma unroll
                for (int hf = 0; hf < 2; hf++) {
                    float* oo = o[np * 2 + hf];
                    mmaH(oo, ph[k2], vb + hf * 2);
                    mmaH(oo, pl[k2], vb + hf * 2);
                }
            }
        }
    }
#pragma unroll
    for (int i = 0; i < 2; i++) {
        lsum[i] += __shfl_xor_sync(0xffffffffu, lsum[i], 1);
        lsum[i] += __shfl_xor_sync(0xffffffffu, lsum[i], 2);
    }
    float i0 = 1.f / lsum[0], i1 = 1.f / lsum[1];
    uint32_t oh[4][4], ol[4][4];
#pragma unroll
    for (int ks = 0; ks < 4; ks++) {
        splitH(o[2 * ks][0] * i0, o[2 * ks][1] * i0, oh[ks][0], ol[ks][0]);
        splitH(o[2 * ks][2] * i1, o[2 * ks][3] * i1, oh[ks][1], ol[ks][1]);
        splitH(o[2 * ks + 1][0] * i0, o[2 * ks + 1][1] * i0, oh[ks][2], ol[ks][2]);
        splitH(o[2 * ks + 1][2] * i1, o[2 * ks + 1][3] * i1, oh[ks][3], ol[ks][3]);
    }
    float r[8][4];
#pragma unroll
    for (int nt = 0; nt < 8; nt++)
#pragma unroll
        for (int i = 0; i < 4; i++) r[nt][i] = 0.f;
#pragma unroll
    for (int ks = 0; ks < 4; ks++)
#pragma unroll
        for (int np = 0; np < 4; np++) {
            uint32_t bh[4];
            ldsm4t(bh, bAddrT(W1, lane, ks * 16, np * 16));
#pragma unroll
            for (int hf = 0; hf < 2; hf++) {
                float* rr = r[np * 2 + hf];
                mmaH(rr, oh[ks], bh + hf * 2);
                mmaH(rr, ol[ks], bh + hf * 2);
            }
        }
#pragma unroll
    for (int nt = 0; nt < 8; nt++) {
        int row = m0 + (lane >> 2), col = nt * 8 + ((lane & 3) << 1);
        float* op = out + ((size_t)row * WW + w) * DD;
        atomicAdd(op + col, 0.5f * r[nt][0]);
        atomicAdd(op + col + 1, 0.5f * r[nt][1]);
        float* op2 = out + ((size_t)(row + 8) * WW + w) * DD;
        atomicAdd(op2 + col, 0.5f * r[nt][2]);
        atomicAdd(op2 + col + 1, 0.5f * r[nt][3]);
    }
}

// ============================================================================
// Height projection: per row r; cp.async double-buffered fp16 W tiles.
// smem rows: Xh 256, Xl 256, W0 64, W1 64
// ============================================================================
__global__ void __launch_bounds__(512, 1)
k_hproj_mma(const float* __restrict__ x) {
    extern __shared__ __half sb[];
    __half* Xh = sb;
    __half* Xl = sb + 256 * XS;
    __half* Wb[2] = {sb + 512 * XS, sb + 576 * XS};

    const int t = threadIdx.x, lane = t & 31, warp = t >> 5, m0 = warp * 16;
    const int r = blockIdx.x;

    auto issueW = [&](__half* dst, int tile) {
        // 4096 halfs = 512 x 16B chunks; 512 threads -> 1 chunk each
        int row = t >> 3, c8 = t & 7;
        uint32_t sa = (uint32_t)__cvta_generic_to_shared(dst + row * XS + c8 * 8);
        CP16(sa, g_Whgt + (size_t)tile * 4096 + row * 64 + c8 * 8);
        CP_COMMIT();
    };
    issueW(Wb[0], 0);
    {
        int row = t >> 1, q0 = (t & 1) * 8;
        const float4* src = (const float4*)(x + (size_t)r * (WW * DD) + row * 64) + q0;
#pragma unroll
        for (int q4 = 0; q4 < 8; q4++) {
            float4 v = src[q4];
            uint32_t h0, l0, h1, l1;
            splitH(v.x, v.y, h0, l0);
            splitH(v.z, v.w, h1, l1);
            int cc = (q0 + q4) * 4;
            *(uint32_t*)(Xh + row * XS + cc) = h0;
            *(uint32_t*)(Xh + row * XS + cc + 2) = h1;
            *(uint32_t*)(Xl + row * XS + cc) = l0;
            *(uint32_t*)(Xl + row * XS + cc + 2) = l1;
        }
    }
    for (int it = 0; it < 24; it++) {
        CP_WAIT0();
        __syncthreads();
        __half* cur = Wb[it & 1];
        if (it + 1 < 24) issueW(Wb[(it + 1) & 1], it + 1);
        const int mk = it >> 3, g = it & 7;

        float c[8][4];
#pragma unroll
        for (int nt = 0; nt < 8; nt++)
#pragma unroll
            for (int i = 0; i < 4; i++) c[nt][i] = 0.f;
#pragma unroll
        for (int ks = 0; ks < 4; ks++) {
            uint32_t ah[4], al[4];
            ldsm4(ah, aAddr(Xh, lane, m0, ks * 16));
            ldsm4(al, aAddr(Xl, lane, m0, ks * 16));
#pragma unroll
            for (int np = 0; np < 4; np++) {
                uint32_t bh[4];
                ldsm4t(bh, bAddrT(cur, lane, ks * 16, np * 16));
#pragma unroll
                for (int hf = 0; hf < 2; hf++) {
                    float* cc = c[np * 2 + hf];
                    mmaH(cc, ah, bh + hf * 2);
                    mmaH(cc, al, bh + hf * 2);
                }
            }
        }
#pragma unroll
        for (int nt = 0; nt < 8; nt++) {
            int row = m0 + (lane >> 2), cc = nt * 8 + ((lane & 3) << 1);
            if (mk == 0) {
                uint32_t h0, l0, h1, l1;
                splitH(c[nt][0], c[nt][1], h0, l0);
                splitH(c[nt][2], c[nt][3], h1, l1);
                size_t i1 = ((size_t)(g * 256 + row)) * KBIG + r * 64 + cc;
                size_t i2 = ((size_t)(g * 256 + row + 8)) * KBIG + r * 64 + cc;
                *(uint32_t*)(g_Qh + i1) = h0;
                *(uint32_t*)(g_Ql + i1) = l0;
                *(uint32_t*)(g_Qh + i2) = h1;
                *(uint32_t*)(g_Ql + i2) = l1;
            } else if (mk == 1) {
                size_t i1 = ((size_t)(g * 256 + row)) * KBIG + r * 64 + cc;
                size_t i2 = ((size_t)(g * 256 + row + 8)) * KBIG + r * 64 + cc;
                *(uint32_t*)(g_Kh + i1) = packH(c[nt][0], c[nt][1]);
                *(uint32_t*)(g_Kh + i2) = packH(c[nt][2], c[nt][3]);
            } else {
                size_t i1 = ((size_t)(r * 256 + row)) * 512 + g * 64 + cc;
                size_t i2 = ((size_t)(r * 256 + row + 8)) * 512 + g * 64 + cc;
                *(uint32_t*)(g_Vh + i1) = packH(c[nt][0], c[nt][1]);
                *(uint32_t*)(g_Vh + i2) = packH(c[nt][2], c[nt][3]);
            }
        }
    }
}

// ============================================================================
// Height dots, double-buffered via cp.async (validated round 10) — unchanged.
// ============================================================================
__global__ void __launch_bounds__(512, 1) k_hdots_mma() {
    extern __shared__ __half sb[];
    const int t = threadIdx.x, lane = t & 31, warp = t >> 5;
    const int kc = blockIdx.x, it = blockIdx.y, head = blockIdx.z;
    const int wm = warp >> 2, wn = warp & 3;
    const int m0 = wm * 16, j0 = wn * 64;

    auto issue = [&](__half* base, int step) {
        const int k0 = kc * 4096 + step * 64;
#pragma unroll
        for (int rr2 = 0; rr2 < 6; rr2++) {
            int e = rr2 * 512 + t;
            const __half* gp;
            uint32_t sa;
            if (e < 1024) {
                int row = (e & 511) >> 3, c8 = e & 7;
                size_t gi = ((size_t)(head * 256 + it * 64 + row)) * KBIG + k0 + c8 * 8;
                if (e < 512) { gp = g_Qh + gi; sa = (uint32_t)__cvta_generic_to_shared(base + row * XS + c8 * 8); }
                else { gp = g_Ql + gi; sa = (uint32_t)__cvta_generic_to_shared(base + (64 + row) * XS + c8 * 8); }
            } else {
                int idx = e - 1024, row = idx >> 3, c8 = idx & 7;
                gp = g_Kh + ((size_t)(head * 256 + row)) * KBIG + k0 + c8 * 8;
                sa = (uint32_t)__cvta_generic_to_shared(base + (128 + row) * XS + c8 * 8);
            }
            CP16(sa, gp);
        }
        CP_COMMIT();
    };

    float c[8][4];
#pragma unroll
    for (int nt = 0; nt < 8; nt++)
#pragma unroll
        for (int i = 0; i < 4; i++) c[nt][i] = 0.f;

    issue(sb, 0);
    for (int step = 0; step < 64; step++) {
        CP_WAIT0();
        __syncthreads();
        __half* cur = sb + (step & 1) * 384 * XS;
        if (step + 1 < 64) issue(sb + ((step + 1) & 1) * 384 * XS, step + 1);
        __half* Qh = cur;
        __half* Ql = cur + 64 * XS;
        __half* Kh = cur + 128 * XS;
#pragma unroll
        for (int ks = 0; ks < 4; ks++) {
            uint32_t ah[4], al[4];
            ldsm4(ah, aAddr(Qh, lane, m0, ks * 16));
            ldsm4(al, aAddr(Ql, lane, m0, ks * 16));
#pragma unroll
            for (int jt = 0; jt < 4; jt++) {
                uint32_t bh[4];
                ldsm4(bh, bAddrN(Kh, lane, j0 + jt * 16, ks * 16));
#pragma unroll
                for (int hf = 0; hf < 2; hf++) {
                    float* cc = c[jt * 2 + hf];
                    mmaH(cc, ah, bh + hf * 2);
                    mmaH(cc, al, bh + hf * 2);
                }
            }
        }
    }
#pragma unroll
    for (int nt = 0; nt < 8; nt++) {
        int row = it * 64 + m0 + (lane >> 2), col = j0 + nt * 8 + ((lane & 3) << 1);
        atomicAdd(&g_DOTS[head * 65536 + row * 256 + col], c[nt][0]);
        atomicAdd(&g_DOTS[head * 65536 + row * 256 + col + 1], c[nt][1]);
        atomicAdd(&g_DOTS[head * 65536 + (row + 8) * 256 + col], c[nt][2]);
        atomicAdd(&g_DOTS[head * 65536 + (row + 8) * 256 + col + 1], c[nt][3]);
    }
}

// ============================================================================
// Softmax (+pair bias) -> normalized P as fp16 hi/lo.
// ============================================================================
__global__ void k_hsm2() {
    const int t = threadIdx.x, warp = t >> 5, lane = t & 31;
    const int row = blockIdx.x * 8 + warp;
    float v[8];
    float mx = -1e30f;
#pragma unroll
    for (int kk = 0; kk < 8; kk++) {
        int j = kk * 32 + lane;
        v[kk] = g_DOTS[row * 256 + j] + g_PB[row * 256 + j];
        mx = fmaxf(mx, v[kk]);
    }
#pragma unroll
    for (int o = 16; o; o >>= 1) mx = fmaxf(mx, __shfl_xor_sync(0xffffffffu, mx, o));
    float s = 0.f;
#pragma unroll
    for (int kk = 0; kk < 8; kk++) { v[kk] = __expf(v[kk] - mx); s += v[kk]; }
#pragma unroll
    for (int o = 16; o; o >>= 1) s += __shfl_xor_sync(0xffffffffu, s, o);
    float inv = 1.f / s;
#pragma unroll
    for (int kk = 0; kk < 8; kk++) {
        float p = v[kk] * inv;
        __half h = __float2half_rn(p);
        g_Ph[row * 256 + kk * 32 + lane] = h;
        g_Pl[row * 256 + kk * 32 + lane] = __float2half_rn(p - __half2float(h));
    }
}

// ============================================================================
// Height AV + out-projection, double-buffered (validated round 10) — unchanged.
// ============================================================================
__global__ void __launch_bounds__(512, 1)
k_hav_mma(const float* __restrict__ Wout, float* __restrict__ out) {
    extern __shared__ __half sb[];
    __half* Wh = sb + 1152 * XS;

    const int t = threadIdx.x, lane = t & 31, warp = t >> 5, m0 = warp * 16;
    const int r = blockIdx.x, head = blockIdx.y;

    for (int e = t; e < 2048; e += 512) {
        int k = e >> 5, n2 = e & 31;
        float2 v = *(const float2*)(Wout + (size_t)(head * 64 + k) * 64 + n2 * 2);
        *(uint32_t*)(Wh + k * XS + n2 * 2) = packH(v.x, v.y);
    }

    auto issue = [&](__half* base, int jt) {
#pragma unroll
        for (int rr2 = 0; rr2 < 9; rr2++) {
            int e = rr2 * 512 + t;
            const __half* gp;
            uint32_t sa;
            if (e < 4096) {
                int idx = e & 2047, row = idx >> 3, c8 = idx & 7;
                size_t gi = ((size_t)(head * 256 + row)) * 256 + jt * 64 + c8 * 8;
                if (e < 2048) { gp = g_Ph + gi; sa = (uint32_t)__cvta_generic_to_shared(base + row * XS + c8 * 8); }
                else { gp = g_Pl + gi; sa = (uint32_t)__cvta_generic_to_shared(base + (256 + row) * XS + c8 * 8); }
            } else {
                int idx = e - 4096, row = idx >> 3, c8 = idx & 7;
                gp = g_Vh + ((size_t)(r * 256 + jt * 64 + row)) * 512 + head * 64 + c8 * 8;
                sa = (uint32_t)__cvta_generic_to_shared(base + (512 + row) * XS + c8 * 8);
            }
            CP16(sa, gp);
        }
        CP_COMMIT();
    };

    float o[8][4];
#pragma unroll
    for (int nt = 0; nt < 8; nt++)
#pragma unroll
        for (int i = 0; i < 4; i++) o[nt][i] = 0.f;

    issue(sb, 0);
    for (int jt = 0; jt < 4; jt++) {
        CP_WAIT0();
        __syncthreads();
        __half* cur = sb + (jt & 1) * 576 * XS;
        if (jt + 1 < 4) issue(sb + ((jt + 1) & 1) * 576 * XS, jt + 1);
        __half* Ph = cur;
        __half* Pl = cur + 256 * XS;
        __half* Vh = cur + 512 * XS;
#pragma unroll
        for (int ks = 0; ks < 4; ks++) {
            uint32_t ah[4], al[4];
            ldsm4(ah, aAddr(Ph, lane, m0, ks * 16));
            ldsm4(al, aAddr(Pl, lane, m0, ks * 16));
#pragma unroll
            for (int np = 0; np < 4; np++) {
                uint32_t bh[4];
                ldsm4t(bh, bAddrT(Vh, lane, ks * 16, np * 16));
#pragma unroll
                for (int hf = 0; hf < 2; hf++) {
                    float* oo = o[np * 2 + hf];
                    mmaH(oo, ah, bh + hf * 2);
                    mmaH(oo, al, bh + hf * 2);
                }
            }
        }
    }
    uint32_t oh[4][4], ol[4][4];
#pragma unroll
    for (int ks = 0; ks < 4; ks++) {
        splitH(o[2 * ks][0], o[2 * ks][1], oh[ks][0], ol[ks][0]);
        splitH(o[2 * ks][2], o[2 * ks][3], oh[ks][1], ol[ks][1]);
        splitH(o[2 * ks + 1][0], o[2 * ks + 1][1], oh[ks][2], ol[ks][2]);
        splitH(o[2 * ks + 1][2], o[2 * ks + 1][3], oh[ks][3], ol[ks][3]);
    }
    float rr[8][4];
#pragma unroll
    for (int nt = 0; nt < 8; nt++)
#pragma unroll
        for (int i = 0; i < 4; i++) rr[nt][i] = 0.f;
#pragma unroll
    for (int ks = 0; ks < 4; ks++)
#pragma unroll
        for (int np = 0; np < 4; np++) {
            uint32_t bh[4];
            ldsm4t(bh, bAddrT(Wh, lane, ks * 16, np * 16));
#pragma unroll
            for (int hf = 0; hf < 2; hf++) {
                float* cc = rr[np * 2 + hf];
                mmaH(cc, oh[ks], bh + hf * 2);
                mmaH(cc, ol[ks], bh + hf * 2);
            }
        }
#pragma unroll
    for (int nt = 0; nt < 8; nt++) {
        int row = m0 + (lane >> 2), col = nt * 8 + ((lane & 3) << 1);
        float* op = out + ((size_t)r * WW + row) * DD;
        atomicAdd(op + col, 0.5f * rr[nt][0]);
        atomicAdd(op + col + 1, 0.5f * rr[nt][1]);
        float* op2 = out + ((size_t)r * WW + row + 8) * DD;
        atomicAdd(op2 + col, 0.5f * rr[nt][2]);
        atomicAdd(op2 + col + 1, 0.5f * rr[nt][3]);
    }
}

// ============================ small kernels ==================================
__global__ void k_init(const float* __restrict__ bw, const float* __restrict__ bh,
                       float* __restrict__ out) {
    int idx = blockIdx.x * 256 + threadIdx.x;
    out[idx] = 0.5f * (bw[idx & 63] + bh[idx & 63]);
}
__global__ void k_zero_dots() { g_DOTS[blockIdx.x * 256 + threadIdx.x] = 0.f; }

// Pair bias: 8 lanes per (i,j) pair, 4 pairs per warp — 6.7x less shfl work.
__global__ void k_pair(const float* __restrict__ pb, const float* __restrict__ g,
                       const float* __restrict__ b, const float* __restrict__ Wp) {
    const int t = threadIdx.x;
    const int warp = t >> 5, lane = t & 31, sub = lane >> 3, l8 = lane & 7;
    const int gw = (blockIdx.x * 8 + warp) * 4 + sub;

    // each lane: 16 consecutive channels of this pair's 128-vector
    const float4* src = (const float4*)(pb + (size_t)gw * 128) + l8 * 4;
    float4 v[4];
#pragma unroll
    for (int qi = 0; qi < 4; qi++) v[qi] = src[qi];
    float s1 = 0.f, s2 = 0.f;
#pragma unroll
    for (int qi = 0; qi < 4; qi++) {
        s1 += v[qi].x + v[qi].y + v[qi].z + v[qi].w;
        s2 += v[qi].x * v[qi].x + v[qi].y * v[qi].y + v[qi].z * v[qi].z + v[qi].w * v[qi].w;
    }
#pragma unroll
    for (int o = 4; o; o >>= 1) {
        s1 += __shfl_xor_sync(0xffffffffu, s1, o);
        s2 += __shfl_xor_sync(0xffffffffu, s2, o);
    }
    float mu = s1 * (1.f / 128.f);
    float rstd = rsqrtf(s2 * (1.f / 128.f) - mu * mu + 1e-5f);

    float phd[8];
#pragma unroll
    for (int h = 0; h < 8; h++) phd[h] = 0.f;
#pragma unroll
    for (int qi = 0; qi < 4; qi++) {
        float4 gv = ((const float4*)g)[l8 * 4 + qi];
        float4 bv = ((const float4*)b)[l8 * 4 + qi];
        float vv[4] = {v[qi].x, v[qi].y, v[qi].z, v[qi].w};
        float gg[4] = {gv.x, gv.y, gv.z, gv.w};
        float bb[4] = {bv.x, bv.y, bv.z, bv.w};
#pragma unroll
        for (int u = 0; u < 4; u++) {
            int p = l8 * 16 + qi * 4 + u;
            float n = (vv[u] - mu) * rstd * gg[u] + bb[u];
            float4 wa = *(const float4*)(Wp + (size_t)p * 8);
            float4 wb = *(const float4*)(Wp + (size_t)p * 8 + 4);
            phd[0] = fmaf(n, wa.x, phd[0]);
            phd[1] = fmaf(n, wa.y, phd[1]);
            phd[2] = fmaf(n, wa.z, phd[2]);
            phd[3] = fmaf(n, wa.w, phd[3]);
            phd[4] = fmaf(n, wb.x, phd[4]);
            phd[5] = fmaf(n, wb.y, phd[5]);
            phd[6] = fmaf(n, wb.z, phd[6]);
            phd[7] = fmaf(n, wb.w, phd[7]);
        }
    }
#pragma unroll
    for (int h = 0; h < 8; h++)
#pragma unroll
        for (int o = 4; o; o >>= 1) phd[h] += __shfl_xor_sync(0xffffffffu, phd[h], o);
    if (l8 == 0)
#pragma unroll
        for (int h = 0; h < 8; h++) g_PB[h * 65536 + gw] = phd[h];
}

// ============================================================================
extern "C" void kernel_launch(void* const* d_in, const int* in_sizes, int n_in,
                              void* d_out, int out_size) {
    (void)in_sizes; (void)n_in; (void)out_size;
    const float* x = (const float*)d_in[0];
    const float* pb = (const float*)d_in[1];
    const float* Wq_w = (const float*)d_in[2];
    const float* Wkv_w = (const float*)d_in[3];
    const float* Wout_w = (const float*)d_in[4];
    const float* bout_w = (const float*)d_in[5];
    const float* Wq_h = (const float*)d_in[6];
    const float* Wkv_h = (const float*)d_in[7];
    const float* Wout_h = (const float*)d_in[8];
    const float* bout_h = (const float*)d_in[9];
    const float* lng = (const float*)d_in[10];
    const float* lnb = (const float*)d_in[11];
    const float* Wp = (const float*)d_in[12];
    float* out = (float*)d_out;

    const int smw = 896 * XS * 2;            // X,Xl,Kh,W0,W1
    const int smp = 640 * XS * 2;            // X,Xl,W0,W1
    const int smd = 2 * 384 * XS * 2;
    const int sma = (2 * 576 + 64) * XS * 2;
    cudaFuncSetAttribute(k_width_mma, cudaFuncAttributeMaxDynamicSharedMemorySize, smw);
    cudaFuncSetAttribute(k_hproj_mma, cudaFuncAttributeMaxDynamicSharedMemorySize, smp);
    cudaFuncSetAttribute(k_hdots_mma, cudaFuncAttributeMaxDynamicSharedMemorySize, smd);
    cudaFuncSetAttribute(k_hav_mma, cudaFuncAttributeMaxDynamicSharedMemorySize, sma);

    k_init<<<16384, 256>>>(bout_w, bout_h, out);
    k_zero_dots<<<2048, 256>>>();
    k_wconv<<<448, 512>>>(Wq_w, Wkv_w, Wout_w, Wq_h, Wkv_h);
    k_hproj_mma<<<256, 512, smp>>>(x);
    k_pair<<<2048, 256>>>(pb, lng, lnb, Wp);
    k_hdots_mma<<<dim3(4, 4, 8), 512, smd>>>();
    k_hsm2<<<256, 256>>>();
    k_hav_mma<<<dim3(256, 8), 512, sma>>>(Wout_h, out);
    k_width_mma<<<dim3(256, 8), 512, smw>>>(x, out);
}

// round 12
// speedup vs baseline: 1.6955x; 1.0422x over previous
#include <cuda_runtime.h>
#include <cuda_fp16.h>
#include <cstdint>
#include <math.h>

#define HH 256
#define WW 256
#define DD 64
#define NH 8
#define KBIG 16384
#define XS 72

__device__ __half g_Qh[NH * 256 * KBIG], g_Ql[NH * 256 * KBIG];
__device__ __half g_Kh[NH * 256 * KBIG];
__device__ __half g_Vh[256 * 256 * 512];
__device__ __half g_Ph[NH * 256 * 256], g_Pl[NH * 256 * 256];
__device__ float g_DOTS[NH * 256 * 256];
__device__ float g_PB[NH * 256 * 256];
__device__ __half g_Wwid[4 * 8 * 64 * 64];
__device__ __half g_Whgt[3 * 8 * 64 * 64];

// ---------------- warp-MMA helpers ------------------------------------------
__device__ __forceinline__ void ldsm4(uint32_t* r, uint32_t a) {
    asm volatile("ldmatrix.sync.aligned.m8n8.x4.shared.b16 {%0,%1,%2,%3}, [%4];"
                 : "=r"(r[0]), "=r"(r[1]), "=r"(r[2]), "=r"(r[3]) : "r"(a));
}
__device__ __forceinline__ void ldsm4t(uint32_t* r, uint32_t a) {
    asm volatile("ldmatrix.sync.aligned.m8n8.x4.trans.shared.b16 {%0,%1,%2,%3}, [%4];"
                 : "=r"(r[0]), "=r"(r[1]), "=r"(r[2]), "=r"(r[3]) : "r"(a));
}
__device__ __forceinline__ void mmaH(float* c, const uint32_t* a, const uint32_t* b) {
    asm volatile("mma.sync.aligned.m16n8k16.row.col.f32.f16.f16.f32 "
                 "{%0,%1,%2,%3},{%4,%5,%6,%7},{%8,%9},{%0,%1,%2,%3};"
                 : "+f"(c[0]), "+f"(c[1]), "+f"(c[2]), "+f"(c[3])
                 : "r"(a[0]), "r"(a[1]), "r"(a[2]), "r"(a[3]), "r"(b[0]), "r"(b[1]));
}
__device__ __forceinline__ void splitH(float a, float b, uint32_t& h, uint32_t& l) {
    __half2 hv = __floats2half2_rn(a, b);
    float2 hf = __half22float2(hv);
    __half2 lv = __floats2half2_rn(a - hf.x, b - hf.y);
    h = *reinterpret_cast<uint32_t*>(&hv);
    l = *reinterpret_cast<uint32_t*>(&lv);
}
__device__ __forceinline__ uint32_t packH(float a, float b) {
    __half2 hv = __floats2half2_rn(a, b);
    return *reinterpret_cast<uint32_t*>(&hv);
}
__device__ __forceinline__ uint32_t aAddr(const __half* base, int lane, int r0, int k0) {
    int row = r0 + (lane & 15), col = k0 + ((lane >> 4) << 3);
    return (uint32_t)__cvta_generic_to_shared(base + row * XS + col);
}
__device__ __forceinline__ uint32_t bAddrT(const __half* base, int lane, int k0, int n0) {
    int row = k0 + (lane & 7) + (((lane >> 3) & 1) << 3);
    int col = n0 + ((lane >> 4) << 3);
    return (uint32_t)__cvta_generic_to_shared(base + row * XS + col);
}
__device__ __forceinline__ uint32_t bAddrN(const __half* base, int lane, int j0, int d0) {
    int row = j0 + (lane & 7) + ((lane >> 4) << 3);
    int col = d0 + (((lane >> 3) & 1) << 3);
    return (uint32_t)__cvta_generic_to_shared(base + row * XS + col);
}
#define CP16(sa, gp) asm volatile("cp.async.cg.shared.global [%0], [%1], 16;" :: "r"(sa), "l"(gp))
#define CP_COMMIT()  asm volatile("cp.async.commit_group;" ::: "memory")
#define CP_WAIT0()   asm volatile("cp.async.wait_group 0;" ::: "memory")

// ============================================================================
__global__ void k_wconv(const float* __restrict__ Wq_w, const float* __restrict__ Wkv_w,
                        const float* __restrict__ Wout_w, const float* __restrict__ Wq_h,
                        const float* __restrict__ Wkv_h) {
    int idx = blockIdx.x * 512 + threadIdx.x;
    if (idx < 131072) {
        int mat = idx >> 15, rem = idx & 32767, head = rem >> 12, e = rem & 4095;
        int k = e >> 6, n = e & 63;
        float v;
        if (mat == 0) v = Wkv_w[k * 1024 + head * 64 + n];
        else if (mat == 1) v = Wq_w[k * 512 + head * 64 + n] * 0.125f;
        else if (mat == 2) v = Wkv_w[k * 1024 + 512 + head * 64 + n];
        else v = Wout_w[(head * 64 + k) * 64 + n];
        g_Wwid[idx] = __float2half_rn(v);
    } else if (idx < 229376) {
        int j = idx - 131072;
        int mk = j >> 15, rem = j & 32767, gg = rem >> 12, e = rem & 4095;
        int k = e >> 6, n = e & 63;
        float v;
        if (mk == 0) v = Wq_h[k * 512 + gg * 64 + n] * 0.0078125f;
        else if (mk == 1) v = Wkv_h[k * 1024 + gg * 64 + n];
        else v = Wkv_h[k * 1024 + 512 + gg * 64 + n];
        g_Whgt[j] = __float2half_rn(v);
    }
}

// ============================================================================
// Width attention (validated round 11) — unchanged.
// ============================================================================
__global__ void __launch_bounds__(512, 1)
k_width_mma(const float* __restrict__ x, float* __restrict__ out) {
    extern __shared__ __half sb[];
    __half* Xh = sb;
    __half* Xl = sb + 256 * XS;
    __half* Kh = sb + 512 * XS;
    __half* W0 = sb + 768 * XS;
    __half* W1 = sb + 832 * XS;

    const int t = threadIdx.x, lane = t & 31, warp = t >> 5, m0 = warp * 16;
    const int w = blockIdx.x, head = blockIdx.y;

    auto loadW = [&](__half* dst, int mat) {
        const __half* src = g_Wwid + (size_t)(mat * 8 + head) * 4096;
        for (int e = t; e < 2048; e += 512) {
            int k = e >> 5, n2 = e & 31;
            *(uint32_t*)(dst + k * XS + n2 * 2) = *(const uint32_t*)(src + k * 64 + n2 * 2);
        }
    };
    loadW(W0, 0);
    {
        int row = t >> 1, q0 = (t & 1) * 8;
        const float4* src = (const float4*)(x + (size_t)row * (WW * DD) + w * DD) + q0;
#pragma unroll
        for (int q4 = 0; q4 < 8; q4++) {
            float4 v = src[q4];
            uint32_t h0, l0, h1, l1;
            splitH(v.x, v.y, h0, l0);
            splitH(v.z, v.w, h1, l1);
            int cc = (q0 + q4) * 4;
            *(uint32_t*)(Xh + row * XS + cc) = h0;
            *(uint32_t*)(Xh + row * XS + cc + 2) = h1;
            *(uint32_t*)(Xl + row * XS + cc) = l0;
            *(uint32_t*)(Xl + row * XS + cc + 2) = l1;
        }
    }
    auto proj = [&](float (&c)[8][4], const __half* Wb) {
#pragma unroll
        for (int nt = 0; nt < 8; nt++)
#pragma unroll
            for (int i = 0; i < 4; i++) c[nt][i] = 0.f;
#pragma unroll
        for (int ks = 0; ks < 4; ks++) {
            uint32_t ah[4], al[4];
            ldsm4(ah, aAddr(Xh, lane, m0, ks * 16));
            ldsm4(al, aAddr(Xl, lane, m0, ks * 16));
#pragma unroll
            for (int np = 0; np < 4; np++) {
                uint32_t bh[4];
                ldsm4t(bh, bAddrT(Wb, lane, ks * 16, np * 16));
#pragma unroll
                for (int hf = 0; hf < 2; hf++) {
                    float* cc = c[np * 2 + hf];
                    mmaH(cc, ah, bh + hf * 2);
                    mmaH(cc, al, bh + hf * 2);
                }
            }
        }
    };
    auto storeHi = [&](float (&c)[8][4], __half* Dh) {
#pragma unroll
        for (int nt = 0; nt < 8; nt++) {
            int r = m0 + (lane >> 2), cc = nt * 8 + ((lane & 3) << 1);
            *(uint32_t*)(Dh + r * XS + cc) = packH(c[nt][0], c[nt][1]);
            *(uint32_t*)(Dh + (r + 8) * XS + cc) = packH(c[nt][2], c[nt][3]);
        }
    };

    float c[8][4];
    __syncthreads();
    loadW(W1, 1);
    proj(c, W0);
    storeHi(c, Kh);
    __syncthreads();
    loadW(W0, 2);
    proj(c, W1);
    uint32_t qh[4][4], ql[4][4];
#pragma unroll
    for (int ks = 0; ks < 4; ks++) {
        splitH(c[2 * ks][0], c[2 * ks][1], qh[ks][0], ql[ks][0]);
        splitH(c[2 * ks][2], c[2 * ks][3], qh[ks][1], ql[ks][1]);
        splitH(c[2 * ks + 1][0], c[2 * ks + 1][1], qh[ks][2], ql[ks][2]);
        splitH(c[2 * ks + 1][2], c[2 * ks + 1][3], qh[ks][3], ql[ks][3]);
    }
    __syncthreads();
    loadW(W1, 3);
    proj(c, W0);
    storeHi(c, Xh);
    __syncthreads();

    float o[8][4];
#pragma unroll
    for (int nt = 0; nt < 8; nt++)
#pragma unroll
        for (int i = 0; i < 4; i++) o[nt][i] = 0.f;
    float lsum[2] = {0.f, 0.f};

    for (int jc = 0; jc < 8; jc++) {
        float s[4][4];
#pragma unroll
        for (int jt = 0; jt < 4; jt++)
#pragma unroll
            for (int i = 0; i < 4; i++) s[jt][i] = 0.f;
#pragma unroll
        for (int ks = 0; ks < 4; ks++) {
            uint32_t kb[2][4];
            ldsm4(kb[0], bAddrN(Kh, lane, jc * 32, ks * 16));
            ldsm4(kb[1], bAddrN(Kh, lane, jc * 32 + 16, ks * 16));
#pragma unroll
            for (int jt = 0; jt < 4; jt++) {
                float* ss = s[jt];
                const uint32_t* bh = &kb[jt >> 1][(jt & 1) * 2];
                mmaH(ss, qh[ks], bh);
                mmaH(ss, ql[ks], bh);
            }
        }
        uint32_t ph[2][4], pl[2][4];
#pragma unroll
        for (int k2 = 0; k2 < 2; k2++) {
            float e0 = __expf(s[2 * k2][0]), e1 = __expf(s[2 * k2][1]);
            float e2 = __expf(s[2 * k2][2]), e3 = __expf(s[2 * k2][3]);
            float f0 = __expf(s[2 * k2 + 1][0]), f1 = __expf(s[2 * k2 + 1][1]);
            float f2 = __expf(s[2 * k2 + 1][2]), f3 = __expf(s[2 * k2 + 1][3]);
            lsum[0] += e0 + e1 + f0 + f1;
            lsum[1] += e2 + e3 + f2 + f3;
            splitH(e0, e1, ph[k2][0], pl[k2][0]);
            splitH(e2, e3, ph[k2][1], pl[k2][1]);
            splitH(f0, f1, ph[k2][2], pl[k2][2]);
            splitH(f2, f3, ph[k2][3], pl[k2][3]);
        }
#pragma unroll
        for (int k2 = 0; k2 < 2; k2++) {
            int j0 = jc * 32 + k2 * 16;
#pragma unroll
            for (int np = 0; np < 4; np++) {
                uint32_t vb[4];
                ldsm4t(vb, bAddrT(Xh, lane, j0, np * 16));
#pragma unroll
                for (int hf = 0; hf < 2; hf++) {
                    float* oo = o[np * 2 + hf];
                    mmaH(oo, ph[k2], vb + hf * 2);
                    mmaH(oo, pl[k2], vb + hf * 2);
                }
            }
        }
    }
#pragma unroll
    for (int i = 0; i < 2; i++) {
        lsum[i] += __shfl_xor_sync(0xffffffffu, lsum[i], 1);
        lsum[i] += __shfl_xor_sync(0xffffffffu, lsum[i], 2);
    }
    float i0 = 1.f / lsum[0], i1 = 1.f / lsum[1];
    uint32_t oh[4][4], ol[4][4];
#pragma unroll
    for (int ks = 0; ks < 4; ks++) {
        splitH(o[2 * ks][0] * i0, o[2 * ks][1] * i0, oh[ks][0], ol[ks][0]);
        splitH(o[2 * ks][2] * i1, o[2 * ks][3] * i1, oh[ks][1], ol[ks][1]);
        splitH(o[2 * ks + 1][0] * i0, o[2 * ks + 1][1] * i0, oh[ks][2], ol[ks][2]);
        splitH(o[2 * ks + 1][2] * i1, o[2 * ks + 1][3] * i1, oh[ks][3], ol[ks][3]);
    }
    float r[8][4];
#pragma unroll
    for (int nt = 0; nt < 8; nt++)
#pragma unroll
        for (int i = 0; i < 4; i++) r[nt][i] = 0.f;
#pragma unroll
    for (int ks = 0; ks < 4; ks++)
#pragma unroll
        for (int np = 0; np < 4; np++) {
            uint32_t bh[4];
            ldsm4t(bh, bAddrT(W1, lane, ks * 16, np * 16));
#pragma unroll
            for (int hf = 0; hf < 2; hf++) {
                float* rr = r[np * 2 + hf];
                mmaH(rr, oh[ks], bh + hf * 2);
                mmaH(rr, ol[ks], bh + hf * 2);
            }
        }
#pragma unroll
    for (int nt = 0; nt < 8; nt++) {
        int row = m0 + (lane >> 2), col = nt * 8 + ((lane & 3) << 1);
        float* op = out + ((size_t)row * WW + w) * DD;
        atomicAdd(op + col, 0.5f * r[nt][0]);
        atomicAdd(op + col + 1, 0.5f * r[nt][1]);
        float* op2 = out + ((size_t)(row + 8) * WW + w) * DD;
        atomicAdd(op2 + col, 0.5f * r[nt][2]);
        atomicAdd(op2 + col + 1, 0.5f * r[nt][3]);
    }
}

// ============================================================================
// Height projection v2: grid (r=256, mk=3); coalesced stores via smem staging.
// smem rows: Xh 256, Xl 256, W0 64, W1 64, Sg0 256, Sg1 256 = 1152 rows
// ============================================================================
__global__ void __launch_bounds__(512, 1)
k_hproj_mma(const float* __restrict__ x) {
    extern __shared__ __half sb[];
    __half* Xh = sb;
    __half* Xl = sb + 256 * XS;
    __half* Wb[2] = {sb + 512 * XS, sb + 576 * XS};
    __half* Sg0 = sb + 640 * XS;
    __half* Sg1 = sb + 896 * XS;

    const int t = threadIdx.x, lane = t & 31, warp = t >> 5, m0 = warp * 16;
    const int r = blockIdx.x, mk = blockIdx.y;

    auto issueW = [&](__half* dst, int g) {
        int row = t >> 3, c8 = t & 7;
        uint32_t sa = (uint32_t)__cvta_generic_to_shared(dst + row * XS + c8 * 8);
        CP16(sa, g_Whgt + (size_t)(mk * 8 + g) * 4096 + row * 64 + c8 * 8);
        CP_COMMIT();
    };
    issueW(Wb[0], 0);
    {
        int row = t >> 1, q0 = (t & 1) * 8;
        const float4* src = (const float4*)(x + (size_t)r * (WW * DD) + row * 64) + q0;
#pragma unroll
        for (int q4 = 0; q4 < 8; q4++) {
            float4 v = src[q4];
            uint32_t h0, l0, h1, l1;
            splitH(v.x, v.y, h0, l0);
            splitH(v.z, v.w, h1, l1);
            int cc = (q0 + q4) * 4;
            *(uint32_t*)(Xh + row * XS + cc) = h0;
            *(uint32_t*)(Xh + row * XS + cc + 2) = h1;
            *(uint32_t*)(Xl + row * XS + cc) = l0;
            *(uint32_t*)(Xl + row * XS + cc + 2) = l1;
        }
    }
    for (int g = 0; g < 8; g++) {
        CP_WAIT0();
        __syncthreads();
        __half* cur = Wb[g & 1];
        if (g + 1 < 8) issueW(Wb[(g + 1) & 1], g + 1);

        float c[8][4];
#pragma unroll
        for (int nt = 0; nt < 8; nt++)
#pragma unroll
            for (int i = 0; i < 4; i++) c[nt][i] = 0.f;
#pragma unroll
        for (int ks = 0; ks < 4; ks++) {
            uint32_t ah[4], al[4];
            ldsm4(ah, aAddr(Xh, lane, m0, ks * 16));
            ldsm4(al, aAddr(Xl, lane, m0, ks * 16));
#pragma unroll
            for (int np = 0; np < 4; np++) {
                uint32_t bh[4];
                ldsm4t(bh, bAddrT(cur, lane, ks * 16, np * 16));
#pragma unroll
                for (int hf = 0; hf < 2; hf++) {
                    float* cc = c[np * 2 + hf];
                    mmaH(cc, ah, bh + hf * 2);
                    mmaH(cc, al, bh + hf * 2);
                }
            }
        }
        // fragments -> staging (conflict-free)
#pragma unroll
        for (int nt = 0; nt < 8; nt++) {
            int row = m0 + (lane >> 2), cc = nt * 8 + ((lane & 3) << 1);
            if (mk == 0) {
                uint32_t h0, l0, h1, l1;
                splitH(c[nt][0], c[nt][1], h0, l0);
                splitH(c[nt][2], c[nt][3], h1, l1);
                *(uint32_t*)(Sg0 + row * XS + cc) = h0;
                *(uint32_t*)(Sg1 + row * XS + cc) = l0;
                *(uint32_t*)(Sg0 + (row + 8) * XS + cc) = h1;
                *(uint32_t*)(Sg1 + (row + 8) * XS + cc) = l1;
            } else {
                *(uint32_t*)(Sg0 + row * XS + cc) = packH(c[nt][0], c[nt][1]);
                *(uint32_t*)(Sg0 + (row + 8) * XS + cc) = packH(c[nt][2], c[nt][3]);
            }
        }
        __syncthreads();
        // coalesced copy out: 128B lines
#pragma unroll
        for (int pass = 0; pass < 4; pass++) {
            int idx = pass * 512 + t, row = idx >> 3, c8 = idx & 7;
            uint4 v = *(uint4*)(Sg0 + row * XS + c8 * 8);
            if (mk == 0) {
                size_t gi = ((size_t)(g * 256 + row)) * KBIG + r * 64 + c8 * 8;
                *(uint4*)(g_Qh + gi) = v;
                uint4 v2 = *(uint4*)(Sg1 + row * XS + c8 * 8);
                *(uint4*)(g_Ql + gi) = v2;
            } else if (mk == 1) {
                *(uint4*)(g_Kh + ((size_t)(g * 256 + row)) * KBIG + r * 64 + c8 * 8) = v;
            } else {
                *(uint4*)(g_Vh + ((size_t)(r * 256 + row)) * 512 + g * 64 + c8 * 8) = v;
            }
        }
        __syncthreads();
    }
}

// ============================================================================
// Height dots v2: grid (kc=8, it=2, head=8); 128 Q rows/block, K read 2x.
// Buffer = 512 rows (Qh128, Ql128, Kh256); double-buffered.
// ============================================================================
__global__ void __launch_bounds__(512, 1) k_hdots_mma() {
    extern __shared__ __half sb[];
    const int t = threadIdx.x, lane = t & 31, warp = t >> 5;
    const int kc = blockIdx.x, it = blockIdx.y, head = blockIdx.z;
    const int wm = warp >> 1, wn = warp & 1;
    const int m0 = wm * 16, j0 = wn * 128;

    auto issue = [&](__half* base, int step) {
        const int k0 = kc * 2048 + step * 64;
#pragma unroll
        for (int rr2 = 0; rr2 < 8; rr2++) {
            int e = rr2 * 512 + t;
            const __half* gp;
            uint32_t sa;
            if (e < 2048) {
                int row = (e & 1023) >> 3, c8 = e & 7;
                size_t gi = ((size_t)(head * 256 + it * 128 + row)) * KBIG + k0 + c8 * 8;
                if (e < 1024) { gp = g_Qh + gi; sa = (uint32_t)__cvta_generic_to_shared(base + row * XS + c8 * 8); }
                else { gp = g_Ql + gi; sa = (uint32_t)__cvta_generic_to_shared(base + (128 + row) * XS + c8 * 8); }
            } else {
                int idx = e - 2048, row = idx >> 3, c8 = idx & 7;
                gp = g_Kh + ((size_t)(head * 256 + row)) * KBIG + k0 + c8 * 8;
                sa = (uint32_t)__cvta_generic_to_shared(base + (256 + row) * XS + c8 * 8);
            }
            CP16(sa, gp);
        }
        CP_COMMIT();
    };

    float c[16][4];
#pragma unroll
    for (int nt = 0; nt < 16; nt++)
#pragma unroll
        for (int i = 0; i < 4; i++) c[nt][i] = 0.f;

    issue(sb, 0);
    for (int step = 0; step < 32; step++) {
        CP_WAIT0();
        __syncthreads();
        __half* cur = sb + (step & 1) * 512 * XS;
        if (step + 1 < 32) issue(sb + ((step + 1) & 1) * 512 * XS, step + 1);
        __half* Qh = cur;
        __half* Ql = cur + 128 * XS;
        __half* Kh = cur + 256 * XS;
#pragma unroll
        for (int ks = 0; ks < 4; ks++) {
            uint32_t ah[4], al[4];
            ldsm4(ah, aAddr(Qh, lane, m0, ks * 16));
            ldsm4(al, aAddr(Ql, lane, m0, ks * 16));
#pragma unroll
            for (int jt = 0; jt < 8; jt++) {
                uint32_t bh[4];
                ldsm4(bh, bAddrN(Kh, lane, j0 + jt * 16, ks * 16));
#pragma unroll
                for (int hf = 0; hf < 2; hf++) {
                    float* cc = c[jt * 2 + hf];
                    mmaH(cc, ah, bh + hf * 2);
                    mmaH(cc, al, bh + hf * 2);
                }
            }
        }
    }
#pragma unroll
    for (int nt = 0; nt < 16; nt++) {
        int row = it * 128 + m0 + (lane >> 2), col = j0 + nt * 8 + ((lane & 3) << 1);
        atomicAdd(&g_DOTS[head * 65536 + row * 256 + col], c[nt][0]);
        atomicAdd(&g_DOTS[head * 65536 + row * 256 + col + 1], c[nt][1]);
        atomicAdd(&g_DOTS[head * 65536 + (row + 8) * 256 + col], c[nt][2]);
        atomicAdd(&g_DOTS[head * 65536 + (row + 8) * 256 + col + 1], c[nt][3]);
    }
}

// ============================================================================
__global__ void k_hsm2() {
    const int t = threadIdx.x, warp = t >> 5, lane = t & 31;
    const int row = blockIdx.x * 8 + warp;
    float v[8];
    float mx = -1e30f;
#pragma unroll
    for (int kk = 0; kk < 8; kk++) {
        int j = kk * 32 + lane;
        v[kk] = g_DOTS[row * 256 + j] + g_PB[row * 256 + j];
        mx = fmaxf(mx, v[kk]);
    }
#pragma unroll
    for (int o = 16; o; o >>= 1) mx = fmaxf(mx, __shfl_xor_sync(0xffffffffu, mx, o));
    float s = 0.f;
#pragma unroll
    for (int kk = 0; kk < 8; kk++) { v[kk] = __expf(v[kk] - mx); s += v[kk]; }
#pragma unroll
    for (int o = 16; o; o >>= 1) s += __shfl_xor_sync(0xffffffffu, s, o);
    float inv = 1.f / s;
#pragma unroll
    for (int kk = 0; kk < 8; kk++) {
        float p = v[kk] * inv;
        __half h = __float2half_rn(p);
        g_Ph[row * 256 + kk * 32 + lane] = h;
        g_Pl[row * 256 + kk * 32 + lane] = __float2half_rn(p - __half2float(h));
    }
}

// ============================================================================
// Height AV + out-projection (validated round 10/11) — unchanged.
// ============================================================================
__global__ void __launch_bounds__(512, 1)
k_hav_mma(const float* __restrict__ Wout, float* __restrict__ out) {
    extern __shared__ __half sb[];
    __half* Wh = sb + 1152 * XS;

    const int t = threadIdx.x, lane = t & 31, warp = t >> 5, m0 = warp * 16;
    const int r = blockIdx.x, head = blockIdx.y;

    for (int e = t; e < 2048; e += 512) {
        int k = e >> 5, n2 = e & 31;
        float2 v = *(const float2*)(Wout + (size_t)(head * 64 + k) * 64 + n2 * 2);
        *(uint32_t*)(Wh + k * XS + n2 * 2) = packH(v.x, v.y);
    }

    auto issue = [&](__half* base, int jt) {
#pragma unroll
        for (int rr2 = 0; rr2 < 9; rr2++) {
            int e = rr2 * 512 + t;
            const __half* gp;
            uint32_t sa;
            if (e < 4096) {
                int idx = e & 2047, row = idx >> 3, c8 = idx & 7;
                size_t gi = ((size_t)(head * 256 + row)) * 256 + jt * 64 + c8 * 8;
                if (e < 2048) { gp = g_Ph + gi; sa = (uint32_t)__cvta_generic_to_shared(base + row * XS + c8 * 8); }
                else { gp = g_Pl + gi; sa = (uint32_t)__cvta_generic_to_shared(base + (256 + row) * XS + c8 * 8); }
            } else {
                int idx = e - 4096, row = idx >> 3, c8 = idx & 7;
                gp = g_Vh + ((size_t)(r * 256 + jt * 64 + row)) * 512 + head * 64 + c8 * 8;
                sa = (uint32_t)__cvta_generic_to_shared(base + (512 + row) * XS + c8 * 8);
            }
            CP16(sa, gp);
        }
        CP_COMMIT();
    };

    float o[8][4];
#pragma unroll
    for (int nt = 0; nt < 8; nt++)
#pragma unroll
        for (int i = 0; i < 4; i++) o[nt][i] = 0.f;

    issue(sb, 0);
    for (int jt = 0; jt < 4; jt++) {
        CP_WAIT0();
        __syncthreads();
        __half* cur = sb + (jt & 1) * 576 * XS;
        if (jt + 1 < 4) issue(sb + ((jt + 1) & 1) * 576 * XS, jt + 1);
        __half* Ph = cur;
        __half* Pl = cur + 256 * XS;
        __half* Vh = cur + 512 * XS;
#pragma unroll
        for (int ks = 0; ks < 4; ks++) {
            uint32_t ah[4], al[4];
            ldsm4(ah, aAddr(Ph, lane, m0, ks * 16));
            ldsm4(al, aAddr(Pl, lane, m0, ks * 16));
#pragma unroll
            for (int np = 0; np < 4; np++) {
                uint32_t bh[4];
                ldsm4t(bh, bAddrT(Vh, lane, ks * 16, np * 16));
#pragma unroll
                for (int hf = 0; hf < 2; hf++) {
                    float* oo = o[np * 2 + hf];
                    mmaH(oo, ah, bh + hf * 2);
                    mmaH(oo, al, bh + hf * 2);
                }
            }
        }
    }
    uint32_t oh[4][4], ol[4][4];
#pragma unroll
    for (int ks = 0; ks < 4; ks++) {
        splitH(o[2 * ks][0], o[2 * ks][1], oh[ks][0], ol[ks][0]);
        splitH(o[2 * ks][2], o[2 * ks][3], oh[ks][1], ol[ks][1]);
        splitH(o[2 * ks + 1][0], o[2 * ks + 1][1], oh[ks][2], ol[ks][2]);
        splitH(o[2 * ks + 1][2], o[2 * ks + 1][3], oh[ks][3], ol[ks][3]);
    }
    float rr[8][4];
#pragma unroll
    for (int nt = 0; nt < 8; nt++)
#pragma unroll
        for (int i = 0; i < 4; i++) rr[nt][i] = 0.f;
#pragma unroll
    for (int ks = 0; ks < 4; ks++)
#pragma unroll
        for (int np = 0; np < 4; np++) {
            uint32_t bh[4];
            ldsm4t(bh, bAddrT(Wh, lane, ks * 16, np * 16));
#pragma unroll
            for (int hf = 0; hf < 2; hf++) {
                float* cc = rr[np * 2 + hf];
                mmaH(cc, oh[ks], bh + hf * 2);
                mmaH(cc, ol[ks], bh + hf * 2);
            }
        }
#pragma unroll
    for (int nt = 0; nt < 8; nt++) {
        int row = m0 + (lane >> 2), col = nt * 8 + ((lane & 3) << 1);
        float* op = out + ((size_t)r * WW + row) * DD;
        atomicAdd(op + col, 0.5f * rr[nt][0]);
        atomicAdd(op + col + 1, 0.5f * rr[nt][1]);
        float* op2 = out + ((size_t)r * WW + row + 8) * DD;
        atomicAdd(op2 + col, 0.5f * rr[nt][2]);
        atomicAdd(op2 + col + 1, 0.5f * rr[nt][3]);
    }
}

// ============================ small kernels ==================================
__global__ void k_init(const float* __restrict__ bw, const float* __restrict__ bh,
                       float* __restrict__ out) {
    int idx = blockIdx.x * 256 + threadIdx.x;
    out[idx] = 0.5f * (bw[idx & 63] + bh[idx & 63]);
}
__global__ void k_zero_dots() { g_DOTS[blockIdx.x * 256 + threadIdx.x] = 0.f; }

__global__ void k_pair(const float* __restrict__ pb, const float* __restrict__ g,
                       const float* __restrict__ b, const float* __restrict__ Wp) {
    const int t = threadIdx.x;
    const int warp = t >> 5, lane = t & 31, sub = lane >> 3, l8 = lane & 7;
    const int gw = (blockIdx.x * 8 + warp) * 4 + sub;

    const float4* src = (const float4*)(pb + (size_t)gw * 128) + l8 * 4;
    float4 v[4];
#pragma unroll
    for (int qi = 0; qi < 4; qi++) v[qi] = src[qi];
    float s1 = 0.f, s2 = 0.f;
#pragma unroll
    for (int qi = 0; qi < 4; qi++) {
        s1 += v[qi].x + v[qi].y + v[qi].z + v[qi].w;
        s2 += v[qi].x * v[qi].x + v[qi].y * v[qi].y + v[qi].z * v[qi].z + v[qi].w * v[qi].w;
    }
#pragma unroll
    for (int o = 4; o; o >>= 1) {
        s1 += __shfl_xor_sync(0xffffffffu, s1, o);
        s2 += __shfl_xor_sync(0xffffffffu, s2, o);
    }
    float mu = s1 * (1.f / 128.f);
    float rstd = rsqrtf(s2 * (1.f / 128.f) - mu * mu + 1e-5f);

    float phd[8];
#pragma unroll
    for (int h = 0; h < 8; h++) phd[h] = 0.f;
#pragma unroll
    for (int qi = 0; qi < 4; qi++) {
        float4 gv = ((const float4*)g)[l8 * 4 + qi];
        float4 bv = ((const float4*)b)[l8 * 4 + qi];
        float vv[4] = {v[qi].x, v[qi].y, v[qi].z, v[qi].w};
        float gg[4] = {gv.x, gv.y, gv.z, gv.w};
        float bb[4] = {bv.x, bv.y, bv.z, bv.w};
#pragma unroll
        for (int u = 0; u < 4; u++) {
            int p = l8 * 16 + qi * 4 + u;
            float n = (vv[u] - mu) * rstd * gg[u] + bb[u];
            float4 wa = *(const float4*)(Wp + (size_t)p * 8);
            float4 wb = *(const float4*)(Wp + (size_t)p * 8 + 4);
            phd[0] = fmaf(n, wa.x, phd[0]);
            phd[1] = fmaf(n, wa.y, phd[1]);
            phd[2] = fmaf(n, wa.z, phd[2]);
            phd[3] = fmaf(n, wa.w, phd[3]);
            phd[4] = fmaf(n, wb.x, phd[4]);
            phd[5] = fmaf(n, wb.y, phd[5]);
            phd[6] = fmaf(n, wb.z, phd[6]);
            phd[7] = fmaf(n, wb.w, phd[7]);
        }
    }
#pragma unroll
    for (int h = 0; h < 8; h++)
#pragma unroll
        for (int o = 4; o; o >>= 1) phd[h] += __shfl_xor_sync(0xffffffffu, phd[h], o);
    if (l8 == 0)
#pragma unroll
        for (int h = 0; h < 8; h++) g_PB[h * 65536 + gw] = phd[h];
}

// ============================================================================
extern "C" void kernel_launch(void* const* d_in, const int* in_sizes, int n_in,
                              void* d_out, int out_size) {
    (void)in_sizes; (void)n_in; (void)out_size;
    const float* x = (const float*)d_in[0];
    const float* pb = (const float*)d_in[1];
    const float* Wq_w = (const float*)d_in[2];
    const float* Wkv_w = (const float*)d_in[3];
    const float* Wout_w = (const float*)d_in[4];
    const float* bout_w = (const float*)d_in[5];
    const float* Wq_h = (const float*)d_in[6];
    const float* Wkv_h = (const float*)d_in[7];
    const float* Wout_h = (const float*)d_in[8];
    const float* bout_h = (const float*)d_in[9];
    const float* lng = (const float*)d_in[10];
    const float* lnb = (const float*)d_in[11];
    const float* Wp = (const float*)d_in[12];
    float* out = (float*)d_out;

    const int smw = 896 * XS * 2;
    const int smp = 1152 * XS * 2;           // X,Xl,W0,W1,Sg0,Sg1
    const int smd = 2 * 512 * XS * 2;        // double-buffered Q128/Ql128/K256
    const int sma = (2 * 576 + 64) * XS * 2;
    cudaFuncSetAttribute(k_width_mma, cudaFuncAttributeMaxDynamicSharedMemorySize, smw);
    cudaFuncSetAttribute(k_hproj_mma, cudaFuncAttributeMaxDynamicSharedMemorySize, smp);
    cudaFuncSetAttribute(k_hdots_mma, cudaFuncAttributeMaxDynamicSharedMemorySize, smd);
    cudaFuncSetAttribute(k_hav_mma, cudaFuncAttributeMaxDynamicSharedMemorySize, sma);

    k_init<<<16384, 256>>>(bout_w, bout_h, out);
    k_zero_dots<<<2048, 256>>>();
    k_wconv<<<448, 512>>>(Wq_w, Wkv_w, Wout_w, Wq_h, Wkv_h);
    k_hproj_mma<<<dim3(256, 3), 512, smp>>>(x);
    k_pair<<<2048, 256>>>(pb, lng, lnb, Wp);
    k_hdots_mma<<<dim3(8, 2, 8), 512, smd>>>();
    k_hsm2<<<256, 256>>>();
    k_hav_mma<<<dim3(256, 8), 512, sma>>>(Wout_h, out);
    k_width_mma<<<dim3(256, 8), 512, smw>>>(x, out);
}

// round 13
// speedup vs baseline: 1.9155x; 1.1298x over previous
#include <cuda_runtime.h>
#include <cuda_fp16.h>
#include <cstdint>
#include <math.h>

#define HH 256
#define WW 256
#define DD 64
#define NH 8
#define KBIG 16384
#define XS 72
#define PS 264

__device__ __half g_Qh[NH * 256 * KBIG];
__device__ __half g_Kh[NH * 256 * KBIG];
__device__ __half g_Vh[256 * 256 * 512];
__device__ __half g_Ph[NH * 256 * 256];
__device__ float g_DOTS[NH * 256 * 256];
__device__ float g_PB[NH * 256 * 256];
__device__ __half g_Wwid[4 * 8 * 64 * 64];
__device__ __half g_Whgt[3 * 8 * 64 * 64];

// ---------------- warp-MMA helpers ------------------------------------------
__device__ __forceinline__ void ldsm4(uint32_t* r, uint32_t a) {
    asm volatile("ldmatrix.sync.aligned.m8n8.x4.shared.b16 {%0,%1,%2,%3}, [%4];"
                 : "=r"(r[0]), "=r"(r[1]), "=r"(r[2]), "=r"(r[3]) : "r"(a));
}
__device__ __forceinline__ void ldsm4t(uint32_t* r, uint32_t a) {
    asm volatile("ldmatrix.sync.aligned.m8n8.x4.trans.shared.b16 {%0,%1,%2,%3}, [%4];"
                 : "=r"(r[0]), "=r"(r[1]), "=r"(r[2]), "=r"(r[3]) : "r"(a));
}
__device__ __forceinline__ void mmaH(float* c, const uint32_t* a, const uint32_t* b) {
    asm volatile("mma.sync.aligned.m16n8k16.row.col.f32.f16.f16.f32 "
                 "{%0,%1,%2,%3},{%4,%5,%6,%7},{%8,%9},{%0,%1,%2,%3};"
                 : "+f"(c[0]), "+f"(c[1]), "+f"(c[2]), "+f"(c[3])
                 : "r"(a[0]), "r"(a[1]), "r"(a[2]), "r"(a[3]), "r"(b[0]), "r"(b[1]));
}
__device__ __forceinline__ void splitH(float a, float b, uint32_t& h, uint32_t& l) {
    __half2 hv = __floats2half2_rn(a, b);
    float2 hf = __half22float2(hv);
    __half2 lv = __floats2half2_rn(a - hf.x, b - hf.y);
    h = *reinterpret_cast<uint32_t*>(&hv);
    l = *reinterpret_cast<uint32_t*>(&lv);
}
__device__ __forceinline__ uint32_t packH(float a, float b) {
    __half2 hv = __floats2half2_rn(a, b);
    return *reinterpret_cast<uint32_t*>(&hv);
}
__device__ __forceinline__ uint32_t aAddr(const __half* base, int lane, int r0, int k0) {
    int row = r0 + (lane & 15), col = k0 + ((lane >> 4) << 3);
    return (uint32_t)__cvta_generic_to_shared(base + row * XS + col);
}
__device__ __forceinline__ uint32_t aAddrS(const __half* base, int lane, int r0, int k0, int st) {
    int row = r0 + (lane & 15), col = k0 + ((lane >> 4) << 3);
    return (uint32_t)__cvta_generic_to_shared(base + row * st + col);
}
__device__ __forceinline__ uint32_t bAddrT(const __half* base, int lane, int k0, int n0) {
    int row = k0 + (lane & 7) + (((lane >> 3) & 1) << 3);
    int col = n0 + ((lane >> 4) << 3);
    return (uint32_t)__cvta_generic_to_shared(base + row * XS + col);
}
__device__ __forceinline__ uint32_t bAddrN(const __half* base, int lane, int j0, int d0) {
    int row = j0 + (lane & 7) + ((lane >> 4) << 3);
    int col = d0 + (((lane >> 3) & 1) << 3);
    return (uint32_t)__cvta_generic_to_shared(base + row * XS + col);
}
#define CP16(sa, gp) asm volatile("cp.async.cg.shared.global [%0], [%1], 16;" :: "r"(sa), "l"(gp))
#define CP_COMMIT()  asm volatile("cp.async.commit_group;" ::: "memory")
#define CP_WAIT0()   asm volatile("cp.async.wait_group 0;" ::: "memory")

// ============================================================================
__global__ void k_wconv(const float* __restrict__ Wq_w, const float* __restrict__ Wkv_w,
                        const float* __restrict__ Wout_w, const float* __restrict__ Wq_h,
                        const float* __restrict__ Wkv_h) {
    int idx = blockIdx.x * 512 + threadIdx.x;
    if (idx < 131072) {
        int mat = idx >> 15, rem = idx & 32767, head = rem >> 12, e = rem & 4095;
        int k = e >> 6, n = e & 63;
        float v;
        if (mat == 0) v = Wkv_w[k * 1024 + head * 64 + n];
        else if (mat == 1) v = Wq_w[k * 512 + head * 64 + n] * 0.125f;
        else if (mat == 2) v = Wkv_w[k * 1024 + 512 + head * 64 + n];
        else v = Wout_w[(head * 64 + k) * 64 + n];
        g_Wwid[idx] = __float2half_rn(v);
    } else if (idx < 229376) {
        int j = idx - 131072;
        int mk = j >> 15, rem = j & 32767, gg = rem >> 12, e = rem & 4095;
        int k = e >> 6, n = e & 63;
        float v;
        if (mk == 0) v = Wq_h[k * 512 + gg * 64 + n] * 0.0078125f;
        else if (mk == 1) v = Wkv_h[k * 1024 + gg * 64 + n];
        else v = Wkv_h[k * 1024 + 512 + gg * 64 + n];
        g_Whgt[j] = __float2half_rn(v);
    }
}

// ============================================================================
// Width attention (validated rounds 9-12) — unchanged.
// ============================================================================
__global__ void __launch_bounds__(512, 1)
k_width_mma(const float* __restrict__ x, float* __restrict__ out) {
    extern __shared__ __half sb[];
    __half* Xh = sb;
    __half* Xl = sb + 256 * XS;
    __half* Kh = sb + 512 * XS;
    __half* W0 = sb + 768 * XS;
    __half* W1 = sb + 832 * XS;

    const int t = threadIdx.x, lane = t & 31, warp = t >> 5, m0 = warp * 16;
    const int w = blockIdx.x, head = blockIdx.y;

    auto loadW = [&](__half* dst, int mat) {
        const __half* src = g_Wwid + (size_t)(mat * 8 + head) * 4096;
        for (int e = t; e < 2048; e += 512) {
            int k = e >> 5, n2 = e & 31;
            *(uint32_t*)(dst + k * XS + n2 * 2) = *(const uint32_t*)(src + k * 64 + n2 * 2);
        }
    };
    loadW(W0, 0);
    {
        int row = t >> 1, q0 = (t & 1) * 8;
        const float4* src = (const float4*)(x + (size_t)row * (WW * DD) + w * DD) + q0;
#pragma unroll
        for (int q4 = 0; q4 < 8; q4++) {
            float4 v = src[q4];
            uint32_t h0, l0, h1, l1;
            splitH(v.x, v.y, h0, l0);
            splitH(v.z, v.w, h1, l1);
            int cc = (q0 + q4) * 4;
            *(uint32_t*)(Xh + row * XS + cc) = h0;
            *(uint32_t*)(Xh + row * XS + cc + 2) = h1;
            *(uint32_t*)(Xl + row * XS + cc) = l0;
            *(uint32_t*)(Xl + row * XS + cc + 2) = l1;
        }
    }
    auto proj = [&](float (&c)[8][4], const __half* Wb) {
#pragma unroll
        for (int nt = 0; nt < 8; nt++)
#pragma unroll
            for (int i = 0; i < 4; i++) c[nt][i] = 0.f;
#pragma unroll
        for (int ks = 0; ks < 4; ks++) {
            uint32_t ah[4], al[4];
            ldsm4(ah, aAddr(Xh, lane, m0, ks * 16));
            ldsm4(al, aAddr(Xl, lane, m0, ks * 16));
#pragma unroll
            for (int np = 0; np < 4; np++) {
                uint32_t bh[4];
                ldsm4t(bh, bAddrT(Wb, lane, ks * 16, np * 16));
#pragma unroll
                for (int hf = 0; hf < 2; hf++) {
                    float* cc = c[np * 2 + hf];
                    mmaH(cc, ah, bh + hf * 2);
                    mmaH(cc, al, bh + hf * 2);
                }
            }
        }
    };
    auto storeHi = [&](float (&c)[8][4], __half* Dh) {
#pragma unroll
        for (int nt = 0; nt < 8; nt++) {
            int r = m0 + (lane >> 2), cc = nt * 8 + ((lane & 3) << 1);
            *(uint32_t*)(Dh + r * XS + cc) = packH(c[nt][0], c[nt][1]);
            *(uint32_t*)(Dh + (r + 8) * XS + cc) = packH(c[nt][2], c[nt][3]);
        }
    };

    float c[8][4];
    __syncthreads();
    loadW(W1, 1);
    proj(c, W0);
    storeHi(c, Kh);
    __syncthreads();
    loadW(W0, 2);
    proj(c, W1);
    uint32_t qh[4][4], ql[4][4];
#pragma unroll
    for (int ks = 0; ks < 4; ks++) {
        splitH(c[2 * ks][0], c[2 * ks][1], qh[ks][0], ql[ks][0]);
        splitH(c[2 * ks][2], c[2 * ks][3], qh[ks][1], ql[ks][1]);
        splitH(c[2 * ks + 1][0], c[2 * ks + 1][1], qh[ks][2], ql[ks][2]);
        splitH(c[2 * ks + 1][2], c[2 * ks + 1][3], qh[ks][3], ql[ks][3]);
    }
    __syncthreads();
    loadW(W1, 3);
    proj(c, W0);
    storeHi(c, Xh);
    __syncthreads();

    float o[8][4];
#pragma unroll
    for (int nt = 0; nt < 8; nt++)
#pragma unroll
        for (int i = 0; i < 4; i++) o[nt][i] = 0.f;
    float lsum[2] = {0.f, 0.f};

    for (int jc = 0; jc < 8; jc++) {
        float s[4][4];
#pragma unroll
        for (int jt = 0; jt < 4; jt++)
#pragma unroll
            for (int i = 0; i < 4; i++) s[jt][i] = 0.f;
#pragma unroll
        for (int ks = 0; ks < 4; ks++) {
            uint32_t kb[2][4];
            ldsm4(kb[0], bAddrN(Kh, lane, jc * 32, ks * 16));
            ldsm4(kb[1], bAddrN(Kh, lane, jc * 32 + 16, ks * 16));
#pragma unroll
            for (int jt = 0; jt < 4; jt++) {
                float* ss = s[jt];
                const uint32_t* bh = &kb[jt >> 1][(jt & 1) * 2];
                mmaH(ss, qh[ks], bh);
                mmaH(ss, ql[ks], bh);
            }
        }
        uint32_t ph[2][4], pl[2][4];
#pragma unroll
        for (int k2 = 0; k2 < 2; k2++) {
            float e0 = __expf(s[2 * k2][0]), e1 = __expf(s[2 * k2][1]);
            float e2 = __expf(s[2 * k2][2]), e3 = __expf(s[2 * k2][3]);
            float f0 = __expf(s[2 * k2 + 1][0]), f1 = __expf(s[2 * k2 + 1][1]);
            float f2 = __expf(s[2 * k2 + 1][2]), f3 = __expf(s[2 * k2 + 1][3]);
            lsum[0] += e0 + e1 + f0 + f1;
            lsum[1] += e2 + e3 + f2 + f3;
            splitH(e0, e1, ph[k2][0], pl[k2][0]);
            splitH(e2, e3, ph[k2][1], pl[k2][1]);
            splitH(f0, f1, ph[k2][2], pl[k2][2]);
            splitH(f2, f3, ph[k2][3], pl[k2][3]);
        }
#pragma unroll
        for (int k2 = 0; k2 < 2; k2++) {
            int j0 = jc * 32 + k2 * 16;
#pragma unroll
            for (int np = 0; np < 4; np++) {
                uint32_t vb[4];
                ldsm4t(vb, bAddrT(Xh, lane, j0, np * 16));
#pragma unroll
                for (int hf = 0; hf < 2; hf++) {
                    float* oo = o[np * 2 + hf];
                    mmaH(oo, ph[k2], vb + hf * 2);
                    mmaH(oo, pl[k2], vb + hf * 2);
                }
            }
        }
    }
#pragma unroll
    for (int i = 0; i < 2; i++) {
        lsum[i] += __shfl_xor_sync(0xffffffffu, lsum[i], 1);
        lsum[i] += __shfl_xor_sync(0xffffffffu, lsum[i], 2);
    }
    float i0 = 1.f / lsum[0], i1 = 1.f / lsum[1];
    uint32_t oh[4][4], ol[4][4];
#pragma unroll
    for (int ks = 0; ks < 4; ks++) {
        splitH(o[2 * ks][0] * i0, o[2 * ks][1] * i0, oh[ks][0], ol[ks][0]);
        splitH(o[2 * ks][2] * i1, o[2 * ks][3] * i1, oh[ks][1], ol[ks][1]);
        splitH(o[2 * ks + 1][0] * i0, o[2 * ks + 1][1] * i0, oh[ks][2], ol[ks][2]);
        splitH(o[2 * ks + 1][2] * i1, o[2 * ks + 1][3] * i1, oh[ks][3], ol[ks][3]);
    }
    float r[8][4];
#pragma unroll
    for (int nt = 0; nt < 8; nt++)
#pragma unroll
        for (int i = 0; i < 4; i++) r[nt][i] = 0.f;
#pragma unroll
    for (int ks = 0; ks < 4; ks++)
#pragma unroll
        for (int np = 0; np < 4; np++) {
            uint32_t bh[4];
            ldsm4t(bh, bAddrT(W1, lane, ks * 16, np * 16));
#pragma unroll
            for (int hf = 0; hf < 2; hf++) {
                float* rr = r[np * 2 + hf];
                mmaH(rr, oh[ks], bh + hf * 2);
                mmaH(rr, ol[ks], bh + hf * 2);
            }
        }
#pragma unroll
    for (int nt = 0; nt < 8; nt++) {
        int row = m0 + (lane >> 2), col = nt * 8 + ((lane & 3) << 1);
        float* op = out + ((size_t)row * WW + w) * DD;
        atomicAdd(op + col, 0.5f * r[nt][0]);
        atomicAdd(op + col + 1, 0.5f * r[nt][1]);
        float* op2 = out + ((size_t)(row + 8) * WW + w) * DD;
        atomicAdd(op2 + col, 0.5f * r[nt][2]);
        atomicAdd(op2 + col + 1, 0.5f * r[nt][3]);
    }
}

// ============================================================================
// Height projection v3: grid (r=256, mk=3); Q stored hi-only now.
// smem rows: Xh 256, Xl 256, W0 64, W1 64, Sg0 256 = 896 rows
// ============================================================================
__global__ void __launch_bounds__(512, 1)
k_hproj_mma(const float* __restrict__ x) {
    extern __shared__ __half sb[];
    __half* Xh = sb;
    __half* Xl = sb + 256 * XS;
    __half* Wb[2] = {sb + 512 * XS, sb + 576 * XS};
    __half* Sg0 = sb + 640 * XS;

    const int t = threadIdx.x, lane = t & 31, warp = t >> 5, m0 = warp * 16;
    const int r = blockIdx.x, mk = blockIdx.y;

    auto issueW = [&](__half* dst, int g) {
        int row = t >> 3, c8 = t & 7;
        uint32_t sa = (uint32_t)__cvta_generic_to_shared(dst + row * XS + c8 * 8);
        CP16(sa, g_Whgt + (size_t)(mk * 8 + g) * 4096 + row * 64 + c8 * 8);
        CP_COMMIT();
    };
    issueW(Wb[0], 0);
    {
        int row = t >> 1, q0 = (t & 1) * 8;
        const float4* src = (const float4*)(x + (size_t)r * (WW * DD) + row * 64) + q0;
#pragma unroll
        for (int q4 = 0; q4 < 8; q4++) {
            float4 v = src[q4];
            uint32_t h0, l0, h1, l1;
            splitH(v.x, v.y, h0, l0);
            splitH(v.z, v.w, h1, l1);
            int cc = (q0 + q4) * 4;
            *(uint32_t*)(Xh + row * XS + cc) = h0;
            *(uint32_t*)(Xh + row * XS + cc + 2) = h1;
            *(uint32_t*)(Xl + row * XS + cc) = l0;
            *(uint32_t*)(Xl + row * XS + cc + 2) = l1;
        }
    }
    for (int g = 0; g < 8; g++) {
        CP_WAIT0();
        __syncthreads();
        __half* cur = Wb[g & 1];
        if (g + 1 < 8) issueW(Wb[(g + 1) & 1], g + 1);

        float c[8][4];
#pragma unroll
        for (int nt = 0; nt < 8; nt++)
#pragma unroll
            for (int i = 0; i < 4; i++) c[nt][i] = 0.f;
#pragma unroll
        for (int ks = 0; ks < 4; ks++) {
            uint32_t ah[4], al[4];
            ldsm4(ah, aAddr(Xh, lane, m0, ks * 16));
            ldsm4(al, aAddr(Xl, lane, m0, ks * 16));
#pragma unroll
            for (int np = 0; np < 4; np++) {
                uint32_t bh[4];
                ldsm4t(bh, bAddrT(cur, lane, ks * 16, np * 16));
#pragma unroll
                for (int hf = 0; hf < 2; hf++) {
                    float* cc = c[np * 2 + hf];
                    mmaH(cc, ah, bh + hf * 2);
                    mmaH(cc, al, bh + hf * 2);
                }
            }
        }
        // fragments -> staging (hi only, all mk)
#pragma unroll
        for (int nt = 0; nt < 8; nt++) {
            int row = m0 + (lane >> 2), cc = nt * 8 + ((lane & 3) << 1);
            *(uint32_t*)(Sg0 + row * XS + cc) = packH(c[nt][0], c[nt][1]);
            *(uint32_t*)(Sg0 + (row + 8) * XS + cc) = packH(c[nt][2], c[nt][3]);
        }
        __syncthreads();
        // coalesced copy out
#pragma unroll
        for (int pass = 0; pass < 4; pass++) {
            int idx = pass * 512 + t, row = idx >> 3, c8 = idx & 7;
            uint4 v = *(uint4*)(Sg0 + row * XS + c8 * 8);
            if (mk == 0) {
                *(uint4*)(g_Qh + ((size_t)(g * 256 + row)) * KBIG + r * 64 + c8 * 8) = v;
            } else if (mk == 1) {
                *(uint4*)(g_Kh + ((size_t)(g * 256 + row)) * KBIG + r * 64 + c8 * 8) = v;
            } else {
                *(uint4*)(g_Vh + ((size_t)(r * 256 + row)) * 512 + g * 64 + c8 * 8) = v;
            }
        }
        __syncthreads();
    }
}

// ============================================================================
// Height dots v3: Q hi only. Buffer = 384 rows (Qh128, Kh256); double-buffered.
// ============================================================================
__global__ void __launch_bounds__(512, 1) k_hdots_mma() {
    extern __shared__ __half sb[];
    const int t = threadIdx.x, lane = t & 31, warp = t >> 5;
    const int kc = blockIdx.x, it = blockIdx.y, head = blockIdx.z;
    const int wm = warp >> 1, wn = warp & 1;
    const int m0 = wm * 16, j0 = wn * 128;

    auto issue = [&](__half* base, int step) {
        const int k0 = kc * 2048 + step * 64;
#pragma unroll
        for (int rr2 = 0; rr2 < 6; rr2++) {
            int e = rr2 * 512 + t;
            const __half* gp;
            uint32_t sa;
            if (e < 1024) {
                int row = e >> 3, c8 = e & 7;
                gp = g_Qh + ((size_t)(head * 256 + it * 128 + row)) * KBIG + k0 + c8 * 8;
                sa = (uint32_t)__cvta_generic_to_shared(base + row * XS + c8 * 8);
            } else {
                int idx = e - 1024, row = idx >> 3, c8 = idx & 7;
                gp = g_Kh + ((size_t)(head * 256 + row)) * KBIG + k0 + c8 * 8;
                sa = (uint32_t)__cvta_generic_to_shared(base + (128 + row) * XS + c8 * 8);
            }
            CP16(sa, gp);
        }
        CP_COMMIT();
    };

    float c[16][4];
#pragma unroll
    for (int nt = 0; nt < 16; nt++)
#pragma unroll
        for (int i = 0; i < 4; i++) c[nt][i] = 0.f;

    issue(sb, 0);
    for (int step = 0; step < 32; step++) {
        CP_WAIT0();
        __syncthreads();
        __half* cur = sb + (step & 1) * 384 * XS;
        if (step + 1 < 32) issue(sb + ((step + 1) & 1) * 384 * XS, step + 1);
        __half* Qh = cur;
        __half* Kh = cur + 128 * XS;
#pragma unroll
        for (int ks = 0; ks < 4; ks++) {
            uint32_t ah[4];
            ldsm4(ah, aAddr(Qh, lane, m0, ks * 16));
#pragma unroll
            for (int jt = 0; jt < 8; jt++) {
                uint32_t bh[4];
                ldsm4(bh, bAddrN(Kh, lane, j0 + jt * 16, ks * 16));
#pragma unroll
                for (int hf = 0; hf < 2; hf++)
                    mmaH(c[jt * 2 + hf], ah, bh + hf * 2);
            }
        }
    }
#pragma unroll
    for (int nt = 0; nt < 16; nt++) {
        int row = it * 128 + m0 + (lane >> 2), col = j0 + nt * 8 + ((lane & 3) << 1);
        atomicAdd(&g_DOTS[head * 65536 + row * 256 + col], c[nt][0]);
        atomicAdd(&g_DOTS[head * 65536 + row * 256 + col + 1], c[nt][1]);
        atomicAdd(&g_DOTS[head * 65536 + (row + 8) * 256 + col], c[nt][2]);
        atomicAdd(&g_DOTS[head * 65536 + (row + 8) * 256 + col + 1], c[nt][3]);
    }
}

// ============================================================================
// Softmax (+pair bias) -> normalized P, fp16 hi only.
// ============================================================================
__global__ void k_hsm2() {
    const int t = threadIdx.x, warp = t >> 5, lane = t & 31;
    const int row = blockIdx.x * 8 + warp;
    float v[8];
    float mx = -1e30f;
#pragma unroll
    for (int kk = 0; kk < 8; kk++) {
        int j = kk * 32 + lane;
        v[kk] = g_DOTS[row * 256 + j] + g_PB[row * 256 + j];
        mx = fmaxf(mx, v[kk]);
    }
#pragma unroll
    for (int o = 16; o; o >>= 1) mx = fmaxf(mx, __shfl_xor_sync(0xffffffffu, mx, o));
    float s = 0.f;
#pragma unroll
    for (int kk = 0; kk < 8; kk++) { v[kk] = __expf(v[kk] - mx); s += v[kk]; }
#pragma unroll
    for (int o = 16; o; o >>= 1) s += __shfl_xor_sync(0xffffffffu, s, o);
    float inv = 1.f / s;
#pragma unroll
    for (int kk = 0; kk < 8; kk++)
        g_Ph[row * 256 + kk * 32 + lane] = __float2half_rn(v[kk] * inv);
}

// ============================================================================
// Height AV v2: block = (rgroup of 4 r, head). P[head] hi loaded ONCE into
// smem (256 x PS), V double-buffered per r. O split-2 for out-projection.
// smem: P 256*PS + V 2*256*XS + W 64*XS  = 218,112 B
// ============================================================================
__global__ void __launch_bounds__(512, 1)
k_hav_mma(const float* __restrict__ Wout, float* __restrict__ out) {
    extern __shared__ __half sb[];
    __half* Pm = sb;                              // 256 x PS
    __half* Vb[2] = {sb + 256 * PS, sb + 256 * PS + 256 * XS};
    __half* Wh = sb + 256 * PS + 512 * XS;

    const int t = threadIdx.x, lane = t & 31, warp = t >> 5, m0 = warp * 16;
    const int rg = blockIdx.x, head = blockIdx.y;

    for (int e = t; e < 2048; e += 512) {
        int k = e >> 5, n2 = e & 31;
        float2 v = *(const float2*)(Wout + (size_t)(head * 64 + k) * 64 + n2 * 2);
        *(uint32_t*)(Wh + k * XS + n2 * 2) = packH(v.x, v.y);
    }
    // P[head] (256x256 hi) -> smem, coalesced cp.async
#pragma unroll
    for (int p = 0; p < 16; p++) {
        int e = p * 512 + t, row = e >> 5, c8 = e & 31;
        uint32_t sa = (uint32_t)__cvta_generic_to_shared(Pm + row * PS + c8 * 8);
        CP16(sa, g_Ph + (size_t)head * 65536 + row * 256 + c8 * 8);
    }
    CP_COMMIT();

    auto issueV = [&](__half* dst, int r) {
#pragma unroll
        for (int p = 0; p < 4; p++) {
            int e = p * 512 + t, row = e >> 3, c8 = e & 7;
            uint32_t sa = (uint32_t)__cvta_generic_to_shared(dst + row * XS + c8 * 8);
            CP16(sa, g_Vh + ((size_t)(r * 256 + row)) * 512 + head * 64 + c8 * 8);
        }
        CP_COMMIT();
    };
    issueV(Vb[0], rg * 4);

    for (int rr = 0; rr < 4; rr++) {
        int r = rg * 4 + rr;
        CP_WAIT0();
        __syncthreads();
        __half* Vc = Vb[rr & 1];
        if (rr + 1 < 4) issueV(Vb[(rr + 1) & 1], r + 1);

        float o[8][4];
#pragma unroll
        for (int nt = 0; nt < 8; nt++)
#pragma unroll
            for (int i = 0; i < 4; i++) o[nt][i] = 0.f;
        // O = P(i, j) @ V(j, hd): contraction over 256 j
#pragma unroll
        for (int ks = 0; ks < 16; ks++) {
            uint32_t ah[4];
            ldsm4(ah, aAddrS(Pm, lane, m0, ks * 16, PS));
#pragma unroll
            for (int np = 0; np < 4; np++) {
                uint32_t bh[4];
                ldsm4t(bh, bAddrT(Vc, lane, ks * 16, np * 16));
#pragma unroll
                for (int hf = 0; hf < 2; hf++)
                    mmaH(o[np * 2 + hf], ah, bh + hf * 2);
            }
        }
        // out-projection (O split-2) + atomics
        uint32_t oh[4][4], ol[4][4];
#pragma unroll
        for (int ks = 0; ks < 4; ks++) {
            splitH(o[2 * ks][0], o[2 * ks][1], oh[ks][0], ol[ks][0]);
            splitH(o[2 * ks][2], o[2 * ks][3], oh[ks][1], ol[ks][1]);
            splitH(o[2 * ks + 1][0], o[2 * ks + 1][1], oh[ks][2], ol[ks][2]);
            splitH(o[2 * ks + 1][2], o[2 * ks + 1][3], oh[ks][3], ol[ks][3]);
        }
        float rv[8][4];
#pragma unroll
        for (int nt = 0; nt < 8; nt++)
#pragma unroll
            for (int i = 0; i < 4; i++) rv[nt][i] = 0.f;
#pragma unroll
        for (int ks = 0; ks < 4; ks++)
#pragma unroll
            for (int np = 0; np < 4; np++) {
                uint32_t bh[4];
                ldsm4t(bh, bAddrT(Wh, lane, ks * 16, np * 16));
#pragma unroll
                for (int hf = 0; hf < 2; hf++) {
                    float* cc = rv[np * 2 + hf];
                    mmaH(cc, oh[ks], bh + hf * 2);
                    mmaH(cc, ol[ks], bh + hf * 2);
                }
            }
#pragma unroll
        for (int nt = 0; nt < 8; nt++) {
            int row = m0 + (lane >> 2), col = nt * 8 + ((lane & 3) << 1);
            float* op = out + ((size_t)r * WW + row) * DD;
            atomicAdd(op + col, 0.5f * rv[nt][0]);
            atomicAdd(op + col + 1, 0.5f * rv[nt][1]);
            float* op2 = out + ((size_t)r * WW + row + 8) * DD;
            atomicAdd(op2 + col, 0.5f * rv[nt][2]);
            atomicAdd(op2 + col + 1, 0.5f * rv[nt][3]);
        }
        __syncthreads();  // all warps done with Vc before it is overwritten
    }
}

// ============================ small kernels ==================================
__global__ void k_init(const float* __restrict__ bw, const float* __restrict__ bh,
                       float* __restrict__ out) {
    int idx = blockIdx.x * 256 + threadIdx.x;
    out[idx] = 0.5f * (bw[idx & 63] + bh[idx & 63]);
}
__global__ void k_zero_dots() { g_DOTS[blockIdx.x * 256 + threadIdx.x] = 0.f; }

__global__ void k_pair(const float* __restrict__ pb, const float* __restrict__ g,
                       const float* __restrict__ b, const float* __restrict__ Wp) {
    const int t = threadIdx.x;
    const int warp = t >> 5, lane = t & 31, sub = lane >> 3, l8 = lane & 7;
    const int gw = (blockIdx.x * 8 + warp) * 4 + sub;

    const float4* src = (const float4*)(pb + (size_t)gw * 128) + l8 * 4;
    float4 v[4];
#pragma unroll
    for (int qi = 0; qi < 4; qi++) v[qi] = src[qi];
    float s1 = 0.f, s2 = 0.f;
#pragma unroll
    for (int qi = 0; qi < 4; qi++) {
        s1 += v[qi].x + v[qi].y + v[qi].z + v[qi].w;
        s2 += v[qi].x * v[qi].x + v[qi].y * v[qi].y + v[qi].z * v[qi].z + v[qi].w * v[qi].w;
    }
#pragma unroll
    for (int o = 4; o; o >>= 1) {
        s1 += __shfl_xor_sync(0xffffffffu, s1, o);
        s2 += __shfl_xor_sync(0xffffffffu, s2, o);
    }
    float mu = s1 * (1.f / 128.f);
    float rstd = rsqrtf(s2 * (1.f / 128.f) - mu * mu + 1e-5f);

    float phd[8];
#pragma unroll
    for (int h = 0; h < 8; h++) phd[h] = 0.f;
#pragma unroll
    for (int qi = 0; qi < 4; qi++) {
        float4 gv = ((const float4*)g)[l8 * 4 + qi];
        float4 bv = ((const float4*)b)[l8 * 4 + qi];
        float vv[4] = {v[qi].x, v[qi].y, v[qi].z, v[qi].w};
        float gg[4] = {gv.x, gv.y, gv.z, gv.w};
        float bb[4] = {bv.x, bv.y, bv.z, bv.w};
#pragma unroll
        for (int u = 0; u < 4; u++) {
            int p = l8 * 16 + qi * 4 + u;
            float n = (vv[u] - mu) * rstd * gg[u] + bb[u];
            float4 wa = *(const float4*)(Wp + (size_t)p * 8);
            float4 wb = *(const float4*)(Wp + (size_t)p * 8 + 4);
            phd[0] = fmaf(n, wa.x, phd[0]);
            phd[1] = fmaf(n, wa.y, phd[1]);
            phd[2] = fmaf(n, wa.z, phd[2]);
            phd[3] = fmaf(n, wa.w, phd[3]);
            phd[4] = fmaf(n, wb.x, phd[4]);
            phd[5] = fmaf(n, wb.y, phd[5]);
            phd[6] = fmaf(n, wb.z, phd[6]);
            phd[7] = fmaf(n, wb.w, phd[7]);
        }
    }
#pragma unroll
    for (int h = 0; h < 8; h++)
#pragma unroll
        for (int o = 4; o; o >>= 1) phd[h] += __shfl_xor_sync(0xffffffffu, phd[h], o);
    if (l8 == 0)
#pragma unroll
        for (int h = 0; h < 8; h++) g_PB[h * 65536 + gw] = phd[h];
}

// ============================================================================
extern "C" void kernel_launch(void* const* d_in, const int* in_sizes, int n_in,
                              void* d_out, int out_size) {
    (void)in_sizes; (void)n_in; (void)out_size;
    const float* x = (const float*)d_in[0];
    const float* pb = (const float*)d_in[1];
    const float* Wq_w = (const float*)d_in[2];
    const float* Wkv_w = (const float*)d_in[3];
    const float* Wout_w = (const float*)d_in[4];
    const float* bout_w = (const float*)d_in[5];
    const float* Wq_h = (const float*)d_in[6];
    const float* Wkv_h = (const float*)d_in[7];
    const float* Wout_h = (const float*)d_in[8];
    const float* bout_h = (const float*)d_in[9];
    const float* lng = (const float*)d_in[10];
    const float* lnb = (const float*)d_in[11];
    const float* Wp = (const float*)d_in[12];
    float* out = (float*)d_out;

    const int smw = 896 * XS * 2;
    const int smp = 896 * XS * 2;                       // Xh,Xl,W0,W1,Sg0
    const int smd = 2 * 384 * XS * 2;                   // Qh128+Kh256, double
    const int sma = (256 * PS + 512 * XS + 64 * XS) * 2;  // P + 2xV + W
    cudaFuncSetAttribute(k_width_mma, cudaFuncAttributeMaxDynamicSharedMemorySize, smw);
    cudaFuncSetAttribute(k_hproj_mma, cudaFuncAttributeMaxDynamicSharedMemorySize, smp);
    cudaFuncSetAttribute(k_hdots_mma, cudaFuncAttributeMaxDynamicSharedMemorySize, smd);
    cudaFuncSetAttribute(k_hav_mma, cudaFuncAttributeMaxDynamicSharedMemorySize, sma);

    k_init<<<16384, 256>>>(bout_w, bout_h, out);
    k_zero_dots<<<2048, 256>>>();
    k_wconv<<<448, 512>>>(Wq_w, Wkv_w, Wout_w, Wq_h, Wkv_h);
    k_hproj_mma<<<dim3(256, 3), 512, smp>>>(x);
    k_pair<<<2048, 256>>>(pb, lng, lnb, Wp);
    k_hdots_mma<<<dim3(8, 2, 8), 512, smd>>>();
    k_hsm2<<<256, 256>>>();
    k_hav_mma<<<dim3(64, 8), 512, sma>>>(Wout_h, out);
    k_width_mma<<<dim3(256, 8), 512, smw>>>(x, out);
}

// round 14
// speedup vs baseline: 2.1066x; 1.0998x over previous
#include <cuda_runtime.h>
#include <cuda_fp16.h>
#include <cstdint>
#include <math.h>

#define HH 256
#define WW 256
#define DD 64
#define NH 8
#define KBIG 16384
#define XS 72
#define PS 264

// chunk-major scratch: Q/K = [head][r][i][64], V = [r][head][j][64]
__device__ __half g_Qh[NH * 256 * KBIG];
__device__ __half g_Kh[NH * 256 * KBIG];
__device__ __half g_Vh[256 * 256 * 512];
__device__ __half g_Ph[NH * 256 * 256];
__device__ float g_DOTS[NH * 256 * 256];
__device__ float g_PB[NH * 256 * 256];
__device__ __half g_Wwid[4 * 8 * 64 * 64];
__device__ __half g_Whgt[3 * 8 * 64 * 64];

// ---------------- warp-MMA helpers ------------------------------------------
__device__ __forceinline__ void ldsm4(uint32_t* r, uint32_t a) {
    asm volatile("ldmatrix.sync.aligned.m8n8.x4.shared.b16 {%0,%1,%2,%3}, [%4];"
                 : "=r"(r[0]), "=r"(r[1]), "=r"(r[2]), "=r"(r[3]) : "r"(a));
}
__device__ __forceinline__ void ldsm4t(uint32_t* r, uint32_t a) {
    asm volatile("ldmatrix.sync.aligned.m8n8.x4.trans.shared.b16 {%0,%1,%2,%3}, [%4];"
                 : "=r"(r[0]), "=r"(r[1]), "=r"(r[2]), "=r"(r[3]) : "r"(a));
}
__device__ __forceinline__ void mmaH(float* c, const uint32_t* a, const uint32_t* b) {
    asm volatile("mma.sync.aligned.m16n8k16.row.col.f32.f16.f16.f32 "
                 "{%0,%1,%2,%3},{%4,%5,%6,%7},{%8,%9},{%0,%1,%2,%3};"
                 : "+f"(c[0]), "+f"(c[1]), "+f"(c[2]), "+f"(c[3])
                 : "r"(a[0]), "r"(a[1]), "r"(a[2]), "r"(a[3]), "r"(b[0]), "r"(b[1]));
}
__device__ __forceinline__ void splitH(float a, float b, uint32_t& h, uint32_t& l) {
    __half2 hv = __floats2half2_rn(a, b);
    float2 hf = __half22float2(hv);
    __half2 lv = __floats2half2_rn(a - hf.x, b - hf.y);
    h = *reinterpret_cast<uint32_t*>(&hv);
    l = *reinterpret_cast<uint32_t*>(&lv);
}
__device__ __forceinline__ uint32_t packH(float a, float b) {
    __half2 hv = __floats2half2_rn(a, b);
    return *reinterpret_cast<uint32_t*>(&hv);
}
__device__ __forceinline__ uint32_t aAddr(const __half* base, int lane, int r0, int k0) {
    int row = r0 + (lane & 15), col = k0 + ((lane >> 4) << 3);
    return (uint32_t)__cvta_generic_to_shared(base + row * XS + col);
}
__device__ __forceinline__ uint32_t aAddrS(const __half* base, int lane, int r0, int k0, int st) {
    int row = r0 + (lane & 15), col = k0 + ((lane >> 4) << 3);
    return (uint32_t)__cvta_generic_to_shared(base + row * st + col);
}
__device__ __forceinline__ uint32_t bAddrT(const __half* base, int lane, int k0, int n0) {
    int row = k0 + (lane & 7) + (((lane >> 3) & 1) << 3);
    int col = n0 + ((lane >> 4) << 3);
    return (uint32_t)__cvta_generic_to_shared(base + row * XS + col);
}
__device__ __forceinline__ uint32_t bAddrN(const __half* base, int lane, int j0, int d0) {
    int row = j0 + (lane & 7) + ((lane >> 4) << 3);
    int col = d0 + (((lane >> 3) & 1) << 3);
    return (uint32_t)__cvta_generic_to_shared(base + row * XS + col);
}
#define CP16(sa, gp) asm volatile("cp.async.cg.shared.global [%0], [%1], 16;" :: "r"(sa), "l"(gp))
#define CP_COMMIT()  asm volatile("cp.async.commit_group;" ::: "memory")
#define CP_WAIT0()   asm volatile("cp.async.wait_group 0;" ::: "memory")

// ============================================================================
__global__ void k_wconv(const float* __restrict__ Wq_w, const float* __restrict__ Wkv_w,
                        const float* __restrict__ Wout_w, const float* __restrict__ Wq_h,
                        const float* __restrict__ Wkv_h) {
    int idx = blockIdx.x * 512 + threadIdx.x;
    if (idx < 131072) {
        int mat = idx >> 15, rem = idx & 32767, head = rem >> 12, e = rem & 4095;
        int k = e >> 6, n = e & 63;
        float v;
        if (mat == 0) v = Wkv_w[k * 1024 + head * 64 + n];
        else if (mat == 1) v = Wq_w[k * 512 + head * 64 + n] * 0.125f;
        else if (mat == 2) v = Wkv_w[k * 1024 + 512 + head * 64 + n];
        else v = Wout_w[(head * 64 + k) * 64 + n];
        g_Wwid[idx] = __float2half_rn(v);
    } else if (idx < 229376) {
        int j = idx - 131072;
        int mk = j >> 15, rem = j & 32767, gg = rem >> 12, e = rem & 4095;
        int k = e >> 6, n = e & 63;
        float v;
        if (mk == 0) v = Wq_h[k * 512 + gg * 64 + n] * 0.0078125f;
        else if (mk == 1) v = Wkv_h[k * 1024 + gg * 64 + n];
        else v = Wkv_h[k * 1024 + 512 + gg * 64 + n];
        g_Whgt[j] = __float2half_rn(v);
    }
}

// ============================================================================
// Width attention: X proj split-2; dots/PV hi-only Q/P; outproj split-2.
// ============================================================================
__global__ void __launch_bounds__(512, 1)
k_width_mma(const float* __restrict__ x, float* __restrict__ out) {
    extern __shared__ __half sb[];
    __half* Xh = sb;
    __half* Xl = sb + 256 * XS;
    __half* Kh = sb + 512 * XS;
    __half* W0 = sb + 768 * XS;
    __half* W1 = sb + 832 * XS;

    const int t = threadIdx.x, lane = t & 31, warp = t >> 5, m0 = warp * 16;
    const int w = blockIdx.x, head = blockIdx.y;

    auto loadW = [&](__half* dst, int mat) {
        const __half* src = g_Wwid + (size_t)(mat * 8 + head) * 4096;
        for (int e = t; e < 2048; e += 512) {
            int k = e >> 5, n2 = e & 31;
            *(uint32_t*)(dst + k * XS + n2 * 2) = *(const uint32_t*)(src + k * 64 + n2 * 2);
        }
    };
    loadW(W0, 0);
    {
        int row = t >> 1, q0 = (t & 1) * 8;
        const float4* src = (const float4*)(x + (size_t)row * (WW * DD) + w * DD) + q0;
#pragma unroll
        for (int q4 = 0; q4 < 8; q4++) {
            float4 v = src[q4];
            uint32_t h0, l0, h1, l1;
            splitH(v.x, v.y, h0, l0);
            splitH(v.z, v.w, h1, l1);
            int cc = (q0 + q4) * 4;
            *(uint32_t*)(Xh + row * XS + cc) = h0;
            *(uint32_t*)(Xh + row * XS + cc + 2) = h1;
            *(uint32_t*)(Xl + row * XS + cc) = l0;
            *(uint32_t*)(Xl + row * XS + cc + 2) = l1;
        }
    }
    auto proj = [&](float (&c)[8][4], const __half* Wb) {
#pragma unroll
        for (int nt = 0; nt < 8; nt++)
#pragma unroll
            for (int i = 0; i < 4; i++) c[nt][i] = 0.f;
#pragma unroll
        for (int ks = 0; ks < 4; ks++) {
            uint32_t ah[4], al[4];
            ldsm4(ah, aAddr(Xh, lane, m0, ks * 16));
            ldsm4(al, aAddr(Xl, lane, m0, ks * 16));
#pragma unroll
            for (int np = 0; np < 4; np++) {
                uint32_t bh[4];
                ldsm4t(bh, bAddrT(Wb, lane, ks * 16, np * 16));
#pragma unroll
                for (int hf = 0; hf < 2; hf++) {
                    float* cc = c[np * 2 + hf];
                    mmaH(cc, ah, bh + hf * 2);
                    mmaH(cc, al, bh + hf * 2);
                }
            }
        }
    };
    auto storeHi = [&](float (&c)[8][4], __half* Dh) {
#pragma unroll
        for (int nt = 0; nt < 8; nt++) {
            int r = m0 + (lane >> 2), cc = nt * 8 + ((lane & 3) << 1);
            *(uint32_t*)(Dh + r * XS + cc) = packH(c[nt][0], c[nt][1]);
            *(uint32_t*)(Dh + (r + 8) * XS + cc) = packH(c[nt][2], c[nt][3]);
        }
    };

    float c[8][4];
    __syncthreads();
    loadW(W1, 1);
    proj(c, W0);
    storeHi(c, Kh);
    __syncthreads();
    loadW(W0, 2);
    proj(c, W1);
    uint32_t qh[4][4];  // hi-only Q fragments
#pragma unroll
    for (int ks = 0; ks < 4; ks++) {
        qh[ks][0] = packH(c[2 * ks][0], c[2 * ks][1]);
        qh[ks][1] = packH(c[2 * ks][2], c[2 * ks][3]);
        qh[ks][2] = packH(c[2 * ks + 1][0], c[2 * ks + 1][1]);
        qh[ks][3] = packH(c[2 * ks + 1][2], c[2 * ks + 1][3]);
    }
    __syncthreads();
    loadW(W1, 3);
    proj(c, W0);
    storeHi(c, Xh);
    __syncthreads();

    float o[8][4];
#pragma unroll
    for (int nt = 0; nt < 8; nt++)
#pragma unroll
        for (int i = 0; i < 4; i++) o[nt][i] = 0.f;
    float lsum[2] = {0.f, 0.f};

    for (int jc = 0; jc < 8; jc++) {
        float s[4][4];
#pragma unroll
        for (int jt = 0; jt < 4; jt++)
#pragma unroll
            for (int i = 0; i < 4; i++) s[jt][i] = 0.f;
#pragma unroll
        for (int ks = 0; ks < 4; ks++) {
            uint32_t kb[2][4];
            ldsm4(kb[0], bAddrN(Kh, lane, jc * 32, ks * 16));
            ldsm4(kb[1], bAddrN(Kh, lane, jc * 32 + 16, ks * 16));
#pragma unroll
            for (int jt = 0; jt < 4; jt++)
                mmaH(s[jt], qh[ks], &kb[jt >> 1][(jt & 1) * 2]);
        }
        uint32_t ph[2][4];
#pragma unroll
        for (int k2 = 0; k2 < 2; k2++) {
            float e0 = __expf(s[2 * k2][0]), e1 = __expf(s[2 * k2][1]);
            float e2 = __expf(s[2 * k2][2]), e3 = __expf(s[2 * k2][3]);
            float f0 = __expf(s[2 * k2 + 1][0]), f1 = __expf(s[2 * k2 + 1][1]);
            float f2 = __expf(s[2 * k2 + 1][2]), f3 = __expf(s[2 * k2 + 1][3]);
            lsum[0] += e0 + e1 + f0 + f1;
            lsum[1] += e2 + e3 + f2 + f3;
            ph[k2][0] = packH(e0, e1);
            ph[k2][1] = packH(e2, e3);
            ph[k2][2] = packH(f0, f1);
            ph[k2][3] = packH(f2, f3);
        }
#pragma unroll
        for (int k2 = 0; k2 < 2; k2++) {
            int j0 = jc * 32 + k2 * 16;
#pragma unroll
            for (int np = 0; np < 4; np++) {
                uint32_t vb[4];
                ldsm4t(vb, bAddrT(Xh, lane, j0, np * 16));
#pragma unroll
                for (int hf = 0; hf < 2; hf++)
                    mmaH(o[np * 2 + hf], ph[k2], vb + hf * 2);
            }
        }
    }
#pragma unroll
    for (int i = 0; i < 2; i++) {
        lsum[i] += __shfl_xor_sync(0xffffffffu, lsum[i], 1);
        lsum[i] += __shfl_xor_sync(0xffffffffu, lsum[i], 2);
    }
    float i0 = 1.f / lsum[0], i1 = 1.f / lsum[1];
    uint32_t oh[4][4], ol[4][4];
#pragma unroll
    for (int ks = 0; ks < 4; ks++) {
        splitH(o[2 * ks][0] * i0, o[2 * ks][1] * i0, oh[ks][0], ol[ks][0]);
        splitH(o[2 * ks][2] * i1, o[2 * ks][3] * i1, oh[ks][1], ol[ks][1]);
        splitH(o[2 * ks + 1][0] * i0, o[2 * ks + 1][1] * i0, oh[ks][2], ol[ks][2]);
        splitH(o[2 * ks + 1][2] * i1, o[2 * ks + 1][3] * i1, oh[ks][3], ol[ks][3]);
    }
    float r[8][4];
#pragma unroll
    for (int nt = 0; nt < 8; nt++)
#pragma unroll
        for (int i = 0; i < 4; i++) r[nt][i] = 0.f;
#pragma unroll
    for (int ks = 0; ks < 4; ks++)
#pragma unroll
        for (int np = 0; np < 4; np++) {
            uint32_t bh[4];
            ldsm4t(bh, bAddrT(W1, lane, ks * 16, np * 16));
#pragma unroll
            for (int hf = 0; hf < 2; hf++) {
                float* rr = r[np * 2 + hf];
                mmaH(rr, oh[ks], bh + hf * 2);
                mmaH(rr, ol[ks], bh + hf * 2);
            }
        }
#pragma unroll
    for (int nt = 0; nt < 8; nt++) {
        int row = m0 + (lane >> 2), col = nt * 8 + ((lane & 3) << 1);
        float* op = out + ((size_t)row * WW + w) * DD;
        atomicAdd(op + col, 0.5f * r[nt][0]);
        atomicAdd(op + col + 1, 0.5f * r[nt][1]);
        float* op2 = out + ((size_t)(row + 8) * WW + w) * DD;
        atomicAdd(op2 + col, 0.5f * r[nt][2]);
        atomicAdd(op2 + col + 1, 0.5f * r[nt][3]);
    }
}

// ============================================================================
// Height projection v4: chunk-major stores (fully contiguous per (head, r)).
// ============================================================================
__global__ void __launch_bounds__(512, 1)
k_hproj_mma(const float* __restrict__ x) {
    extern __shared__ __half sb[];
    __half* Xh = sb;
    __half* Xl = sb + 256 * XS;
    __half* Wb[2] = {sb + 512 * XS, sb + 576 * XS};
    __half* Sg0 = sb + 640 * XS;

    const int t = threadIdx.x, lane = t & 31, warp = t >> 5, m0 = warp * 16;
    const int r = blockIdx.x, mk = blockIdx.y;

    auto issueW = [&](__half* dst, int g) {
        int row = t >> 3, c8 = t & 7;
        uint32_t sa = (uint32_t)__cvta_generic_to_shared(dst + row * XS + c8 * 8);
        CP16(sa, g_Whgt + (size_t)(mk * 8 + g) * 4096 + row * 64 + c8 * 8);
        CP_COMMIT();
    };
    issueW(Wb[0], 0);
    {
        int row = t >> 1, q0 = (t & 1) * 8;
        const float4* src = (const float4*)(x + (size_t)r * (WW * DD) + row * 64) + q0;
#pragma unroll
        for (int q4 = 0; q4 < 8; q4++) {
            float4 v = src[q4];
            uint32_t h0, l0, h1, l1;
            splitH(v.x, v.y, h0, l0);
            splitH(v.z, v.w, h1, l1);
            int cc = (q0 + q4) * 4;
            *(uint32_t*)(Xh + row * XS + cc) = h0;
            *(uint32_t*)(Xh + row * XS + cc + 2) = h1;
            *(uint32_t*)(Xl + row * XS + cc) = l0;
            *(uint32_t*)(Xl + row * XS + cc + 2) = l1;
        }
    }
    for (int g = 0; g < 8; g++) {
        CP_WAIT0();
        __syncthreads();
        __half* cur = Wb[g & 1];
        if (g + 1 < 8) issueW(Wb[(g + 1) & 1], g + 1);

        float c[8][4];
#pragma unroll
        for (int nt = 0; nt < 8; nt++)
#pragma unroll
            for (int i = 0; i < 4; i++) c[nt][i] = 0.f;
#pragma unroll
        for (int ks = 0; ks < 4; ks++) {
            uint32_t ah[4], al[4];
            ldsm4(ah, aAddr(Xh, lane, m0, ks * 16));
            ldsm4(al, aAddr(Xl, lane, m0, ks * 16));
#pragma unroll
            for (int np = 0; np < 4; np++) {
                uint32_t bh[4];
                ldsm4t(bh, bAddrT(cur, lane, ks * 16, np * 16));
#pragma unroll
                for (int hf = 0; hf < 2; hf++) {
                    float* cc = c[np * 2 + hf];
                    mmaH(cc, ah, bh + hf * 2);
                    mmaH(cc, al, bh + hf * 2);
                }
            }
        }
#pragma unroll
        for (int nt = 0; nt < 8; nt++) {
            int row = m0 + (lane >> 2), cc = nt * 8 + ((lane & 3) << 1);
            *(uint32_t*)(Sg0 + row * XS + cc) = packH(c[nt][0], c[nt][1]);
            *(uint32_t*)(Sg0 + (row + 8) * XS + cc) = packH(c[nt][2], c[nt][3]);
        }
        __syncthreads();
        // fully contiguous 32KB block per (g, r)
#pragma unroll
        for (int pass = 0; pass < 4; pass++) {
            int idx = pass * 512 + t, row = idx >> 3, c8 = idx & 7;
            uint4 v = *(uint4*)(Sg0 + row * XS + c8 * 8);
            if (mk == 0) {
                *(uint4*)(g_Qh + (((size_t)(g * 256 + r)) * 256 + row) * 64 + c8 * 8) = v;
            } else if (mk == 1) {
                *(uint4*)(g_Kh + (((size_t)(g * 256 + r)) * 256 + row) * 64 + c8 * 8) = v;
            } else {
                *(uint4*)(g_Vh + (((size_t)(r * 8 + g)) * 256 + row) * 64 + c8 * 8) = v;
            }
        }
        __syncthreads();
    }
}

// ============================================================================
// Height dots v4: chunk-major loads (contiguous 16/32KB tiles per step).
// ============================================================================
__global__ void __launch_bounds__(512, 1) k_hdots_mma() {
    extern __shared__ __half sb[];
    const int t = threadIdx.x, lane = t & 31, warp = t >> 5;
    const int kc = blockIdx.x, it = blockIdx.y, head = blockIdx.z;
    const int wm = warp >> 1, wn = warp & 1;
    const int m0 = wm * 16, j0 = wn * 128;

    auto issue = [&](__half* base, int step) {
        const int rk = kc * 32 + step;  // which r-chunk of k
#pragma unroll
        for (int rr2 = 0; rr2 < 6; rr2++) {
            int e = rr2 * 512 + t;
            const __half* gp;
            uint32_t sa;
            if (e < 1024) {
                int row = e >> 3, c8 = e & 7;
                gp = g_Qh + (((size_t)(head * 256 + rk)) * 256 + it * 128 + row) * 64 + c8 * 8;
                sa = (uint32_t)__cvta_generic_to_shared(base + row * XS + c8 * 8);
            } else {
                int idx = e - 1024, row = idx >> 3, c8 = idx & 7;
                gp = g_Kh + (((size_t)(head * 256 + rk)) * 256 + row) * 64 + c8 * 8;
                sa = (uint32_t)__cvta_generic_to_shared(base + (128 + row) * XS + c8 * 8);
            }
            CP16(sa, gp);
        }
        CP_COMMIT();
    };

    float c[16][4];
#pragma unroll
    for (int nt = 0; nt < 16; nt++)
#pragma unroll
        for (int i = 0; i < 4; i++) c[nt][i] = 0.f;

    issue(sb, 0);
    for (int step = 0; step < 32; step++) {
        CP_WAIT0();
        __syncthreads();
        __half* cur = sb + (step & 1) * 384 * XS;
        if (step + 1 < 32) issue(sb + ((step + 1) & 1) * 384 * XS, step + 1);
        __half* Qh = cur;
        __half* Kh = cur + 128 * XS;
#pragma unroll
        for (int ks = 0; ks < 4; ks++) {
            uint32_t ah[4];
            ldsm4(ah, aAddr(Qh, lane, m0, ks * 16));
#pragma unroll
            for (int jt = 0; jt < 8; jt++) {
                uint32_t bh[4];
                ldsm4(bh, bAddrN(Kh, lane, j0 + jt * 16, ks * 16));
#pragma unroll
                for (int hf = 0; hf < 2; hf++)
                    mmaH(c[jt * 2 + hf], ah, bh + hf * 2);
            }
        }
    }
#pragma unroll
    for (int nt = 0; nt < 16; nt++) {
        int row = it * 128 + m0 + (lane >> 2), col = j0 + nt * 8 + ((lane & 3) << 1);
        atomicAdd(&g_DOTS[head * 65536 + row * 256 + col], c[nt][0]);
        atomicAdd(&g_DOTS[head * 65536 + row * 256 + col + 1], c[nt][1]);
        atomicAdd(&g_DOTS[head * 65536 + (row + 8) * 256 + col], c[nt][2]);
        atomicAdd(&g_DOTS[head * 65536 + (row + 8) * 256 + col + 1], c[nt][3]);
    }
}

// ============================================================================
__global__ void k_hsm2() {
    const int t = threadIdx.x, warp = t >> 5, lane = t & 31;
    const int row = blockIdx.x * 8 + warp;
    float v[8];
    float mx = -1e30f;
#pragma unroll
    for (int kk = 0; kk < 8; kk++) {
        int j = kk * 32 + lane;
        v[kk] = g_DOTS[row * 256 + j] + g_PB[row * 256 + j];
        mx = fmaxf(mx, v[kk]);
    }
#pragma unroll
    for (int o = 16; o; o >>= 1) mx = fmaxf(mx, __shfl_xor_sync(0xffffffffu, mx, o));
    float s = 0.f;
#pragma unroll
    for (int kk = 0; kk < 8; kk++) { v[kk] = __expf(v[kk] - mx); s += v[kk]; }
#pragma unroll
    for (int o = 16; o; o >>= 1) s += __shfl_xor_sync(0xffffffffu, s, o);
    float inv = 1.f / s;
#pragma unroll
    for (int kk = 0; kk < 8; kk++)
        g_Ph[row * 256 + kk * 32 + lane] = __float2half_rn(v[kk] * inv);
}

// ============================================================================
// Height AV v3: P[head] resident; V contiguous chunk-major, double-buffered.
// ============================================================================
__global__ void __launch_bounds__(512, 1)
k_hav_mma(const float* __restrict__ Wout, float* __restrict__ out) {
    extern __shared__ __half sb[];
    __half* Pm = sb;
    __half* Vb[2] = {sb + 256 * PS, sb + 256 * PS + 256 * XS};
    __half* Wh = sb + 256 * PS + 512 * XS;

    const int t = threadIdx.x, lane = t & 31, warp = t >> 5, m0 = warp * 16;
    const int rg = blockIdx.x, head = blockIdx.y;

    for (int e = t; e < 2048; e += 512) {
        int k = e >> 5, n2 = e & 31;
        float2 v = *(const float2*)(Wout + (size_t)(head * 64 + k) * 64 + n2 * 2);
        *(uint32_t*)(Wh + k * XS + n2 * 2) = packH(v.x, v.y);
    }
#pragma unroll
    for (int p = 0; p < 16; p++) {
        int e = p * 512 + t, row = e >> 5, c8 = e & 31;
        uint32_t sa = (uint32_t)__cvta_generic_to_shared(Pm + row * PS + c8 * 8);
        CP16(sa, g_Ph + (size_t)head * 65536 + row * 256 + c8 * 8);
    }
    CP_COMMIT();

    auto issueV = [&](__half* dst, int r) {
#pragma unroll
        for (int p = 0; p < 4; p++) {
            int e = p * 512 + t, row = e >> 3, c8 = e & 7;
            uint32_t sa = (uint32_t)__cvta_generic_to_shared(dst + row * XS + c8 * 8);
            CP16(sa, g_Vh + (((size_t)(r * 8 + head)) * 256 + row) * 64 + c8 * 8);
        }
        CP_COMMIT();
    };
    issueV(Vb[0], rg * 4);

    for (int rr = 0; rr < 4; rr++) {
        int r = rg * 4 + rr;
        CP_WAIT0();
        __syncthreads();
        __half* Vc = Vb[rr & 1];
        if (rr + 1 < 4) issueV(Vb[(rr + 1) & 1], r + 1);

        float o[8][4];
#pragma unroll
        for (int nt = 0; nt < 8; nt++)
#pragma unroll
            for (int i = 0; i < 4; i++) o[nt][i] = 0.f;
#pragma unroll
        for (int ks = 0; ks < 16; ks++) {
            uint32_t ah[4];
            ldsm4(ah, aAddrS(Pm, lane, m0, ks * 16, PS));
#pragma unroll
            for (int np = 0; np < 4; np++) {
                uint32_t bh[4];
                ldsm4t(bh, bAddrT(Vc, lane, ks * 16, np * 16));
#pragma unroll
                for (int hf = 0; hf < 2; hf++)
                    mmaH(o[np * 2 + hf], ah, bh + hf * 2);
            }
        }
        uint32_t oh[4][4], ol[4][4];
#pragma unroll
        for (int ks = 0; ks < 4; ks++) {
            splitH(o[2 * ks][0], o[2 * ks][1], oh[ks][0], ol[ks][0]);
            splitH(o[2 * ks][2], o[2 * ks][3], oh[ks][1], ol[ks][1]);
            splitH(o[2 * ks + 1][0], o[2 * ks + 1][1], oh[ks][2], ol[ks][2]);
            splitH(o[2 * ks + 1][2], o[2 * ks + 1][3], oh[ks][3], ol[ks][3]);
        }
        float rv[8][4];
#pragma unroll
        for (int nt = 0; nt < 8; nt++)
#pragma unroll
            for (int i = 0; i < 4; i++) rv[nt][i] = 0.f;
#pragma unroll
        for (int ks = 0; ks < 4; ks++)
#pragma unroll
            for (int np = 0; np < 4; np++) {
                uint32_t bh[4];
                ldsm4t(bh, bAddrT(Wh, lane, ks * 16, np * 16));
#pragma unroll
                for (int hf = 0; hf < 2; hf++) {
                    float* cc = rv[np * 2 + hf];
                    mmaH(cc, oh[ks], bh + hf * 2);
                    mmaH(cc, ol[ks], bh + hf * 2);
                }
            }
#pragma unroll
        for (int nt = 0; nt < 8; nt++) {
            int row = m0 + (lane >> 2), col = nt * 8 + ((lane & 3) << 1);
            float* op = out + ((size_t)r * WW + row) * DD;
            atomicAdd(op + col, 0.5f * rv[nt][0]);
            atomicAdd(op + col + 1, 0.5f * rv[nt][1]);
            float* op2 = out + ((size_t)r * WW + row + 8) * DD;
            atomicAdd(op2 + col, 0.5f * rv[nt][2]);
            atomicAdd(op2 + col + 1, 0.5f * rv[nt][3]);
        }
        __syncthreads();
    }
}

// ============================ small kernels ==================================
__global__ void k_init(const float* __restrict__ bw, const float* __restrict__ bh,
                       float* __restrict__ out) {
    int idx = blockIdx.x * 256 + threadIdx.x;
    out[idx] = 0.5f * (bw[idx & 63] + bh[idx & 63]);
}
__global__ void k_zero_dots() { g_DOTS[blockIdx.x * 256 + threadIdx.x] = 0.f; }

__global__ void k_pair(const float* __restrict__ pb, const float* __restrict__ g,
                       const float* __restrict__ b, const float* __restrict__ Wp) {
    const int t = threadIdx.x;
    const int warp = t >> 5, lane = t & 31, sub = lane >> 3, l8 = lane & 7;
    const int gw = (blockIdx.x * 8 + warp) * 4 + sub;

    const float4* src = (const float4*)(pb + (size_t)gw * 128) + l8 * 4;
    float4 v[4];
#pragma unroll
    for (int qi = 0; qi < 4; qi++) v[qi] = src[qi];
    float s1 = 0.f, s2 = 0.f;
#pragma unroll
    for (int qi = 0; qi < 4; qi++) {
        s1 += v[qi].x + v[qi].y + v[qi].z + v[qi].w;
        s2 += v[qi].x * v[qi].x + v[qi].y * v[qi].y + v[qi].z * v[qi].z + v[qi].w * v[qi].w;
    }
#pragma unroll
    for (int o = 4; o; o >>= 1) {
        s1 += __shfl_xor_sync(0xffffffffu, s1, o);
        s2 += __shfl_xor_sync(0xffffffffu, s2, o);
    }
    float mu = s1 * (1.f / 128.f);
    float rstd = rsqrtf(s2 * (1.f / 128.f) - mu * mu + 1e-5f);

    float phd[8];
#pragma unroll
    for (int h = 0; h < 8; h++) phd[h] = 0.f;
#pragma unroll
    for (int qi = 0; qi < 4; qi++) {
        float4 gv = ((const float4*)g)[l8 * 4 + qi];
        float4 bv = ((const float4*)b)[l8 * 4 + qi];
        float vv[4] = {v[qi].x, v[qi].y, v[qi].z, v[qi].w};
        float gg[4] = {gv.x, gv.y, gv.z, gv.w};
        float bb[4] = {bv.x, bv.y, bv.z, bv.w};
#pragma unroll
        for (int u = 0; u < 4; u++) {
            int p = l8 * 16 + qi * 4 + u;
            float n = (vv[u] - mu) * rstd * gg[u] + bb[u];
            float4 wa = *(const float4*)(Wp + (size_t)p * 8);
            float4 wb = *(const float4*)(Wp + (size_t)p * 8 + 4);
            phd[0] = fmaf(n, wa.x, phd[0]);
            phd[1] = fmaf(n, wa.y, phd[1]);
            phd[2] = fmaf(n, wa.z, phd[2]);
            phd[3] = fmaf(n, wa.w, phd[3]);
            phd[4] = fmaf(n, wb.x, phd[4]);
            phd[5] = fmaf(n, wb.y, phd[5]);
            phd[6] = fmaf(n, wb.z, phd[6]);
            phd[7] = fmaf(n, wb.w, phd[7]);
        }
    }
#pragma unroll
    for (int h = 0; h < 8; h++)
#pragma unroll
        for (int o = 4; o; o >>= 1) phd[h] += __shfl_xor_sync(0xffffffffu, phd[h], o);
    if (l8 == 0)
#pragma unroll
        for (int h = 0; h < 8; h++) g_PB[h * 65536 + gw] = phd[h];
}

// ============================================================================
extern "C" void kernel_launch(void* const* d_in, const int* in_sizes, int n_in,
                              void* d_out, int out_size) {
    (void)in_sizes; (void)n_in; (void)out_size;
    const float* x = (const float*)d_in[0];
    const float* pb = (const float*)d_in[1];
    const float* Wq_w = (const float*)d_in[2];
    const float* Wkv_w = (const float*)d_in[3];
    const float* Wout_w = (const float*)d_in[4];
    const float* bout_w = (const float*)d_in[5];
    const float* Wq_h = (const float*)d_in[6];
    const float* Wkv_h = (const float*)d_in[7];
    const float* Wout_h = (const float*)d_in[8];
    const float* bout_h = (const float*)d_in[9];
    const float* lng = (const float*)d_in[10];
    const float* lnb = (const float*)d_in[11];
    const float* Wp = (const float*)d_in[12];
    float* out = (float*)d_out;

    const int smw = 896 * XS * 2;
    const int smp = 896 * XS * 2;
    const int smd = 2 * 384 * XS * 2;
    const int sma = (256 * PS + 512 * XS + 64 * XS) * 2;
    cudaFuncSetAttribute(k_width_mma, cudaFuncAttributeMaxDynamicSharedMemorySize, smw);
    cudaFuncSetAttribute(k_hproj_mma, cudaFuncAttributeMaxDynamicSharedMemorySize, smp);
    cudaFuncSetAttribute(k_hdots_mma, cudaFuncAttributeMaxDynamicSharedMemorySize, smd);
    cudaFuncSetAttribute(k_hav_mma, cudaFuncAttributeMaxDynamicSharedMemorySize, sma);

    k_init<<<16384, 256>>>(bout_w, bout_h, out);
    k_zero_dots<<<2048, 256>>>();
    k_wconv<<<448, 512>>>(Wq_w, Wkv_w, Wout_w, Wq_h, Wkv_h);
    k_hproj_mma<<<dim3(256, 3), 512, smp>>>(x);
    k_pair<<<2048, 256>>>(pb, lng, lnb, Wp);
    k_hdots_mma<<<dim3(8, 2, 8), 512, smd>>>();
    k_hsm2<<<256, 256>>>();
    k_hav_mma<<<dim3(64, 8), 512, sma>>>(Wout_h, out);
    k_width_mma<<<dim3(256, 8), 512, smw>>>(x, out);
}

// round 15
// speedup vs baseline: 2.1325x; 1.0123x over previous
#include <cuda_runtime.h>
#include <cuda_fp16.h>
#include <cstdint>
#include <math.h>

#define HH 256
#define WW 256
#define DD 64
#define NH 8
#define KBIG 16384
#define XS 72
#define PS 264

// chunk-major scratch: Q/K = [head][r][i][64], V = [r][head][j][64]
__device__ __half g_Qh[NH * 256 * KBIG];
__device__ __half g_Kh[NH * 256 * KBIG];
__device__ __half g_Vh[256 * 256 * 512];
__device__ __half g_Ph[NH * 256 * 256];
__device__ float g_DOTS[NH * 256 * 256];
__device__ float g_PB[NH * 256 * 256];
__device__ __half g_Wwid[4 * 8 * 64 * 64];
__device__ __half g_Whgt[3 * 8 * 64 * 64];

// ---------------- warp-MMA helpers ------------------------------------------
__device__ __forceinline__ void ldsm4(uint32_t* r, uint32_t a) {
    asm volatile("ldmatrix.sync.aligned.m8n8.x4.shared.b16 {%0,%1,%2,%3}, [%4];"
                 : "=r"(r[0]), "=r"(r[1]), "=r"(r[2]), "=r"(r[3]) : "r"(a));
}
__device__ __forceinline__ void ldsm4t(uint32_t* r, uint32_t a) {
    asm volatile("ldmatrix.sync.aligned.m8n8.x4.trans.shared.b16 {%0,%1,%2,%3}, [%4];"
                 : "=r"(r[0]), "=r"(r[1]), "=r"(r[2]), "=r"(r[3]) : "r"(a));
}
__device__ __forceinline__ void mmaH(float* c, const uint32_t* a, const uint32_t* b) {
    asm volatile("mma.sync.aligned.m16n8k16.row.col.f32.f16.f16.f32 "
                 "{%0,%1,%2,%3},{%4,%5,%6,%7},{%8,%9},{%0,%1,%2,%3};"
                 : "+f"(c[0]), "+f"(c[1]), "+f"(c[2]), "+f"(c[3])
                 : "r"(a[0]), "r"(a[1]), "r"(a[2]), "r"(a[3]), "r"(b[0]), "r"(b[1]));
}
__device__ __forceinline__ void splitH(float a, float b, uint32_t& h, uint32_t& l) {
    __half2 hv = __floats2half2_rn(a, b);
    float2 hf = __half22float2(hv);
    __half2 lv = __floats2half2_rn(a - hf.x, b - hf.y);
    h = *reinterpret_cast<uint32_t*>(&hv);
    l = *reinterpret_cast<uint32_t*>(&lv);
}
__device__ __forceinline__ uint32_t packH(float a, float b) {
    __half2 hv = __floats2half2_rn(a, b);
    return *reinterpret_cast<uint32_t*>(&hv);
}
__device__ __forceinline__ uint32_t aAddr(const __half* base, int lane, int r0, int k0) {
    int row = r0 + (lane & 15), col = k0 + ((lane >> 4) << 3);
    return (uint32_t)__cvta_generic_to_shared(base + row * XS + col);
}
__device__ __forceinline__ uint32_t aAddrS(const __half* base, int lane, int r0, int k0, int st) {
    int row = r0 + (lane & 15), col = k0 + ((lane >> 4) << 3);
    return (uint32_t)__cvta_generic_to_shared(base + row * st + col);
}
__device__ __forceinline__ uint32_t bAddrT(const __half* base, int lane, int k0, int n0) {
    int row = k0 + (lane & 7) + (((lane >> 3) & 1) << 3);
    int col = n0 + ((lane >> 4) << 3);
    return (uint32_t)__cvta_generic_to_shared(base + row * XS + col);
}
__device__ __forceinline__ uint32_t bAddrN(const __half* base, int lane, int j0, int d0) {
    int row = j0 + (lane & 7) + ((lane >> 4) << 3);
    int col = d0 + (((lane >> 3) & 1) << 3);
    return (uint32_t)__cvta_generic_to_shared(base + row * XS + col);
}
#define CP16(sa, gp) asm volatile("cp.async.cg.shared.global [%0], [%1], 16;" :: "r"(sa), "l"(gp))
#define CP_COMMIT()  asm volatile("cp.async.commit_group;" ::: "memory")
#define CP_WAIT0()   asm volatile("cp.async.wait_group 0;" ::: "memory")
#define CP_WAIT1()   asm volatile("cp.async.wait_group 1;" ::: "memory")

// ============================================================================
__global__ void k_wconv(const float* __restrict__ Wq_w, const float* __restrict__ Wkv_w,
                        const float* __restrict__ Wout_w, const float* __restrict__ Wq_h,
                        const float* __restrict__ Wkv_h) {
    int idx = blockIdx.x * 512 + threadIdx.x;
    if (idx < 131072) {
        int mat = idx >> 15, rem = idx & 32767, head = rem >> 12, e = rem & 4095;
        int k = e >> 6, n = e & 63;
        float v;
        if (mat == 0) v = Wkv_w[k * 1024 + head * 64 + n];
        else if (mat == 1) v = Wq_w[k * 512 + head * 64 + n] * 0.125f;
        else if (mat == 2) v = Wkv_w[k * 1024 + 512 + head * 64 + n];
        else v = Wout_w[(head * 64 + k) * 64 + n];
        g_Wwid[idx] = __float2half_rn(v);
    } else if (idx < 229376) {
        int j = idx - 131072;
        int mk = j >> 15, rem = j & 32767, gg = rem >> 12, e = rem & 4095;
        int k = e >> 6, n = e & 63;
        float v;
        if (mk == 0) v = Wq_h[k * 512 + gg * 64 + n] * 0.0078125f;
        else if (mk == 1) v = Wkv_h[k * 1024 + gg * 64 + n];
        else v = Wkv_h[k * 1024 + 512 + gg * 64 + n];
        g_Whgt[j] = __float2half_rn(v);
    }
}

// ============================================================================
// Width attention (validated round 14) — unchanged.
// ============================================================================
__global__ void __launch_bounds__(512, 1)
k_width_mma(const float* __restrict__ x, float* __restrict__ out) {
    extern __shared__ __half sb[];
    __half* Xh = sb;
    __half* Xl = sb + 256 * XS;
    __half* Kh = sb + 512 * XS;
    __half* W0 = sb + 768 * XS;
    __half* W1 = sb + 832 * XS;

    const int t = threadIdx.x, lane = t & 31, warp = t >> 5, m0 = warp * 16;
    const int w = blockIdx.x, head = blockIdx.y;

    auto loadW = [&](__half* dst, int mat) {
        const __half* src = g_Wwid + (size_t)(mat * 8 + head) * 4096;
        for (int e = t; e < 2048; e += 512) {
            int k = e >> 5, n2 = e & 31;
            *(uint32_t*)(dst + k * XS + n2 * 2) = *(const uint32_t*)(src + k * 64 + n2 * 2);
        }
    };
    loadW(W0, 0);
    {
        int row = t >> 1, q0 = (t & 1) * 8;
        const float4* src = (const float4*)(x + (size_t)row * (WW * DD) + w * DD) + q0;
#pragma unroll
        for (int q4 = 0; q4 < 8; q4++) {
            float4 v = src[q4];
            uint32_t h0, l0, h1, l1;
            splitH(v.x, v.y, h0, l0);
            splitH(v.z, v.w, h1, l1);
            int cc = (q0 + q4) * 4;
            *(uint32_t*)(Xh + row * XS + cc) = h0;
            *(uint32_t*)(Xh + row * XS + cc + 2) = h1;
            *(uint32_t*)(Xl + row * XS + cc) = l0;
            *(uint32_t*)(Xl + row * XS + cc + 2) = l1;
        }
    }
    auto proj = [&](float (&c)[8][4], const __half* Wb) {
#pragma unroll
        for (int nt = 0; nt < 8; nt++)
#pragma unroll
            for (int i = 0; i < 4; i++) c[nt][i] = 0.f;
#pragma unroll
        for (int ks = 0; ks < 4; ks++) {
            uint32_t ah[4], al[4];
            ldsm4(ah, aAddr(Xh, lane, m0, ks * 16));
            ldsm4(al, aAddr(Xl, lane, m0, ks * 16));
#pragma unroll
            for (int np = 0; np < 4; np++) {
                uint32_t bh[4];
                ldsm4t(bh, bAddrT(Wb, lane, ks * 16, np * 16));
#pragma unroll
                for (int hf = 0; hf < 2; hf++) {
                    float* cc = c[np * 2 + hf];
                    mmaH(cc, ah, bh + hf * 2);
                    mmaH(cc, al, bh + hf * 2);
                }
            }
        }
    };
    auto storeHi = [&](float (&c)[8][4], __half* Dh) {
#pragma unroll
        for (int nt = 0; nt < 8; nt++) {
            int r = m0 + (lane >> 2), cc = nt * 8 + ((lane & 3) << 1);
            *(uint32_t*)(Dh + r * XS + cc) = packH(c[nt][0], c[nt][1]);
            *(uint32_t*)(Dh + (r + 8) * XS + cc) = packH(c[nt][2], c[nt][3]);
        }
    };

    float c[8][4];
    __syncthreads();
    loadW(W1, 1);
    proj(c, W0);
    storeHi(c, Kh);
    __syncthreads();
    loadW(W0, 2);
    proj(c, W1);
    uint32_t qh[4][4];
#pragma unroll
    for (int ks = 0; ks < 4; ks++) {
        qh[ks][0] = packH(c[2 * ks][0], c[2 * ks][1]);
        qh[ks][1] = packH(c[2 * ks][2], c[2 * ks][3]);
        qh[ks][2] = packH(c[2 * ks + 1][0], c[2 * ks + 1][1]);
        qh[ks][3] = packH(c[2 * ks + 1][2], c[2 * ks + 1][3]);
    }
    __syncthreads();
    loadW(W1, 3);
    proj(c, W0);
    storeHi(c, Xh);
    __syncthreads();

    float o[8][4];
#pragma unroll
    for (int nt = 0; nt < 8; nt++)
#pragma unroll
        for (int i = 0; i < 4; i++) o[nt][i] = 0.f;
    float lsum[2] = {0.f, 0.f};

    for (int jc = 0; jc < 8; jc++) {
        float s[4][4];
#pragma unroll
        for (int jt = 0; jt < 4; jt++)
#pragma unroll
            for (int i = 0; i < 4; i++) s[jt][i] = 0.f;
#pragma unroll
        for (int ks = 0; ks < 4; ks++) {
            uint32_t kb[2][4];
            ldsm4(kb[0], bAddrN(Kh, lane, jc * 32, ks * 16));
            ldsm4(kb[1], bAddrN(Kh, lane, jc * 32 + 16, ks * 16));
#pragma unroll
            for (int jt = 0; jt < 4; jt++)
                mmaH(s[jt], qh[ks], &kb[jt >> 1][(jt & 1) * 2]);
        }
        uint32_t ph[2][4];
#pragma unroll
        for (int k2 = 0; k2 < 2; k2++) {
            float e0 = __expf(s[2 * k2][0]), e1 = __expf(s[2 * k2][1]);
            float e2 = __expf(s[2 * k2][2]), e3 = __expf(s[2 * k2][3]);
            float f0 = __expf(s[2 * k2 + 1][0]), f1 = __expf(s[2 * k2 + 1][1]);
            float f2 = __expf(s[2 * k2 + 1][2]), f3 = __expf(s[2 * k2 + 1][3]);
            lsum[0] += e0 + e1 + f0 + f1;
            lsum[1] += e2 + e3 + f2 + f3;
            ph[k2][0] = packH(e0, e1);
            ph[k2][1] = packH(e2, e3);
            ph[k2][2] = packH(f0, f1);
            ph[k2][3] = packH(f2, f3);
        }
#pragma unroll
        for (int k2 = 0; k2 < 2; k2++) {
            int j0 = jc * 32 + k2 * 16;
#pragma unroll
            for (int np = 0; np < 4; np++) {
                uint32_t vb[4];
                ldsm4t(vb, bAddrT(Xh, lane, j0, np * 16));
#pragma unroll
                for (int hf = 0; hf < 2; hf++)
                    mmaH(o[np * 2 + hf], ph[k2], vb + hf * 2);
            }
        }
    }
#pragma unroll
    for (int i = 0; i < 2; i++) {
        lsum[i] += __shfl_xor_sync(0xffffffffu, lsum[i], 1);
        lsum[i] += __shfl_xor_sync(0xffffffffu, lsum[i], 2);
    }
    float i0 = 1.f / lsum[0], i1 = 1.f / lsum[1];
    uint32_t oh[4][4], ol[4][4];
#pragma unroll
    for (int ks = 0; ks < 4; ks++) {
        splitH(o[2 * ks][0] * i0, o[2 * ks][1] * i0, oh[ks][0], ol[ks][0]);
        splitH(o[2 * ks][2] * i1, o[2 * ks][3] * i1, oh[ks][1], ol[ks][1]);
        splitH(o[2 * ks + 1][0] * i0, o[2 * ks + 1][1] * i0, oh[ks][2], ol[ks][2]);
        splitH(o[2 * ks + 1][2] * i1, o[2 * ks + 1][3] * i1, oh[ks][3], ol[ks][3]);
    }
    float r[8][4];
#pragma unroll
    for (int nt = 0; nt < 8; nt++)
#pragma unroll
        for (int i = 0; i < 4; i++) r[nt][i] = 0.f;
#pragma unroll
    for (int ks = 0; ks < 4; ks++)
#pragma unroll
        for (int np = 0; np < 4; np++) {
            uint32_t bh[4];
            ldsm4t(bh, bAddrT(W1, lane, ks * 16, np * 16));
#pragma unroll
            for (int hf = 0; hf < 2; hf++) {
                float* rr = r[np * 2 + hf];
                mmaH(rr, oh[ks], bh + hf * 2);
                mmaH(rr, ol[ks], bh + hf * 2);
            }
        }
#pragma unroll
    for (int nt = 0; nt < 8; nt++) {
        int row = m0 + (lane >> 2), col = nt * 8 + ((lane & 3) << 1);
        float* op = out + ((size_t)row * WW + w) * DD;
        atomicAdd(op + col, 0.5f * r[nt][0]);
        atomicAdd(op + col + 1, 0.5f * r[nt][1]);
        float* op2 = out + ((size_t)(row + 8) * WW + w) * DD;
        atomicAdd(op2 + col, 0.5f * r[nt][2]);
        atomicAdd(op2 + col + 1, 0.5f * r[nt][3]);
    }
}

// ============================================================================
// Height projection v5: X hi-only, depth-2 W prefetch (3 buffers),
// warp-local staging (ONE block sync per iteration).
// smem rows: Xh 256, W 3x64, Sg 256 = 704 rows (~101 KB)
// ============================================================================
__global__ void __launch_bounds__(512, 1)
k_hproj_mma(const float* __restrict__ x) {
    extern __shared__ __half sb[];
    __half* Xh = sb;
    __half* Wb = sb + 256 * XS;      // 3 buffers of 64 rows
    __half* Sg = sb + 448 * XS;      // per-warp 16-row slices

    const int t = threadIdx.x, lane = t & 31, warp = t >> 5, m0 = warp * 16;
    const int r = blockIdx.x, mk = blockIdx.y;

    auto issueW = [&](int g) {
        __half* dst = Wb + (g % 3) * 64 * XS;
        int row = t >> 3, c8 = t & 7;
        uint32_t sa = (uint32_t)__cvta_generic_to_shared(dst + row * XS + c8 * 8);
        CP16(sa, g_Whgt + (size_t)(mk * 8 + g) * 4096 + row * 64 + c8 * 8);
        CP_COMMIT();
    };
    issueW(0);
    issueW(1);
    {   // X hi-only
        int row = t >> 1, q0 = (t & 1) * 8;
        const float4* src = (const float4*)(x + (size_t)r * (WW * DD) + row * 64) + q0;
#pragma unroll
        for (int q4 = 0; q4 < 8; q4++) {
            float4 v = src[q4];
            int cc = (q0 + q4) * 4;
            *(uint32_t*)(Xh + row * XS + cc) = packH(v.x, v.y);
            *(uint32_t*)(Xh + row * XS + cc + 2) = packH(v.z, v.w);
        }
    }
    for (int g = 0; g < 8; g++) {
        if (g < 7) CP_WAIT1(); else CP_WAIT0();
        __syncthreads();                     // W[g] visible; X visible (g==0)
        if (g + 2 < 8) issueW(g + 2);
        const __half* cur = Wb + (g % 3) * 64 * XS;

        float c[8][4];
#pragma unroll
        for (int nt = 0; nt < 8; nt++)
#pragma unroll
            for (int i = 0; i < 4; i++) c[nt][i] = 0.f;
#pragma unroll
        for (int ks = 0; ks < 4; ks++) {
            uint32_t ah[4];
            ldsm4(ah, aAddr(Xh, lane, m0, ks * 16));
#pragma unroll
            for (int np = 0; np < 4; np++) {
                uint32_t bh[4];
                ldsm4t(bh, bAddrT(cur, lane, ks * 16, np * 16));
#pragma unroll
                for (int hf = 0; hf < 2; hf++)
                    mmaH(c[np * 2 + hf], ah, bh + hf * 2);
            }
        }
        // warp-local staging (own 16 rows)
#pragma unroll
        for (int nt = 0; nt < 8; nt++) {
            int row = m0 + (lane >> 2), cc = nt * 8 + ((lane & 3) << 1);
            *(uint32_t*)(Sg + row * XS + cc) = packH(c[nt][0], c[nt][1]);
            *(uint32_t*)(Sg + (row + 8) * XS + cc) = packH(c[nt][2], c[nt][3]);
        }
        __syncwarp();
        // warp-coalesced copy-out of own 16x64 tile (2KB contiguous in global)
        {
            int rrow = m0 + (lane >> 1), coff = (lane & 1) * 32;
            size_t gb;
            if (mk == 0)      gb = (((size_t)(g * 256 + r)) * 256 + rrow) * 64 + coff;
            else if (mk == 1) gb = (((size_t)(g * 256 + r)) * 256 + rrow) * 64 + coff;
            else              gb = (((size_t)(r * 8 + g)) * 256 + rrow) * 64 + coff;
            __half* gdst = (mk == 0) ? g_Qh : (mk == 1) ? g_Kh : g_Vh;
#pragma unroll
            for (int q = 0; q < 4; q++) {
                uint4 v = *(uint4*)(Sg + rrow * XS + coff + q * 8);
                *(uint4*)(gdst + gb + q * 8) = v;
            }
        }
    }
}

// ============================================================================
// Height dots v4 (validated round 14) — unchanged.
// ============================================================================
__global__ void __launch_bounds__(512, 1) k_hdots_mma() {
    extern __shared__ __half sb[];
    const int t = threadIdx.x, lane = t & 31, warp = t >> 5;
    const int kc = blockIdx.x, it = blockIdx.y, head = blockIdx.z;
    const int wm = warp >> 1, wn = warp & 1;
    const int m0 = wm * 16, j0 = wn * 128;

    auto issue = [&](__half* base, int step) {
        const int rk = kc * 32 + step;
#pragma unroll
        for (int rr2 = 0; rr2 < 6; rr2++) {
            int e = rr2 * 512 + t;
            const __half* gp;
            uint32_t sa;
            if (e < 1024) {
                int row = e >> 3, c8 = e & 7;
                gp = g_Qh + (((size_t)(head * 256 + rk)) * 256 + it * 128 + row) * 64 + c8 * 8;
                sa = (uint32_t)__cvta_generic_to_shared(base + row * XS + c8 * 8);
            } else {
                int idx = e - 1024, row = idx >> 3, c8 = idx & 7;
                gp = g_Kh + (((size_t)(head * 256 + rk)) * 256 + row) * 64 + c8 * 8;
                sa = (uint32_t)__cvta_generic_to_shared(base + (128 + row) * XS + c8 * 8);
            }
            CP16(sa, gp);
        }
        CP_COMMIT();
    };

    float c[16][4];
#pragma unroll
    for (int nt = 0; nt < 16; nt++)
#pragma unroll
        for (int i = 0; i < 4; i++) c[nt][i] = 0.f;

    issue(sb, 0);
    for (int step = 0; step < 32; step++) {
        CP_WAIT0();
        __syncthreads();
        __half* cur = sb + (step & 1) * 384 * XS;
        if (step + 1 < 32) issue(sb + ((step + 1) & 1) * 384 * XS, step + 1);
        __half* Qh = cur;
        __half* Kh = cur + 128 * XS;
#pragma unroll
        for (int ks = 0; ks < 4; ks++) {
            uint32_t ah[4];
            ldsm4(ah, aAddr(Qh, lane, m0, ks * 16));
#pragma unroll
            for (int jt = 0; jt < 8; jt++) {
                uint32_t bh[4];
                ldsm4(bh, bAddrN(Kh, lane, j0 + jt * 16, ks * 16));
#pragma unroll
                for (int hf = 0; hf < 2; hf++)
                    mmaH(c[jt * 2 + hf], ah, bh + hf * 2);
            }
        }
    }
#pragma unroll
    for (int nt = 0; nt < 16; nt++) {
        int row = it * 128 + m0 + (lane >> 2), col = j0 + nt * 8 + ((lane & 3) << 1);
        atomicAdd(&g_DOTS[head * 65536 + row * 256 + col], c[nt][0]);
        atomicAdd(&g_DOTS[head * 65536 + row * 256 + col + 1], c[nt][1]);
        atomicAdd(&g_DOTS[head * 65536 + (row + 8) * 256 + col], c[nt][2]);
        atomicAdd(&g_DOTS[head * 65536 + (row + 8) * 256 + col + 1], c[nt][3]);
    }
}

// ============================================================================
__global__ void k_hsm2() {
    const int t = threadIdx.x, warp = t >> 5, lane = t & 31;
    const int row = blockIdx.x * 8 + warp;
    float v[8];
    float mx = -1e30f;
#pragma unroll
    for (int kk = 0; kk < 8; kk++) {
        int j = kk * 32 + lane;
        v[kk] = g_DOTS[row * 256 + j] + g_PB[row * 256 + j];
        mx = fmaxf(mx, v[kk]);
    }
#pragma unroll
    for (int o = 16; o; o >>= 1) mx = fmaxf(mx, __shfl_xor_sync(0xffffffffu, mx, o));
    float s = 0.f;
#pragma unroll
    for (int kk = 0; kk < 8; kk++) { v[kk] = __expf(v[kk] - mx); s += v[kk]; }
#pragma unroll
    for (int o = 16; o; o >>= 1) s += __shfl_xor_sync(0xffffffffu, s, o);
    float inv = 1.f / s;
#pragma unroll
    for (int kk = 0; kk < 8; kk++)
        g_Ph[row * 256 + kk * 32 + lane] = __float2half_rn(v[kk] * inv);
}

// ============================================================================
// Height AV v3 (validated round 14) — unchanged.
// ============================================================================
__global__ void __launch_bounds__(512, 1)
k_hav_mma(const float* __restrict__ Wout, float* __restrict__ out) {
    extern __shared__ __half sb[];
    __half* Pm = sb;
    __half* Vb[2] = {sb + 256 * PS, sb + 256 * PS + 256 * XS};
    __half* Wh = sb + 256 * PS + 512 * XS;

    const int t = threadIdx.x, lane = t & 31, warp = t >> 5, m0 = warp * 16;
    const int rg = blockIdx.x, head = blockIdx.y;

    for (int e = t; e < 2048; e += 512) {
        int k = e >> 5, n2 = e & 31;
        float2 v = *(const float2*)(Wout + (size_t)(head * 64 + k) * 64 + n2 * 2);
        *(uint32_t*)(Wh + k * XS + n2 * 2) = packH(v.x, v.y);
    }
#pragma unroll
    for (int p = 0; p < 16; p++) {
        int e = p * 512 + t, row = e >> 5, c8 = e & 31;
        uint32_t sa = (uint32_t)__cvta_generic_to_shared(Pm + row * PS + c8 * 8);
        CP16(sa, g_Ph + (size_t)head * 65536 + row * 256 + c8 * 8);
    }
    CP_COMMIT();

    auto issueV = [&](__half* dst, int r) {
#pragma unroll
        for (int p = 0; p < 4; p++) {
            int e = p * 512 + t, row = e >> 3, c8 = e & 7;
            uint32_t sa = (uint32_t)__cvta_generic_to_shared(dst + row * XS + c8 * 8);
            CP16(sa, g_Vh + (((size_t)(r * 8 + head)) * 256 + row) * 64 + c8 * 8);
        }
        CP_COMMIT();
    };
    issueV(Vb[0], rg * 4);

    for (int rr = 0; rr < 4; rr++) {
        int r = rg * 4 + rr;
        CP_WAIT0();
        __syncthreads();
        __half* Vc = Vb[rr & 1];
        if (rr + 1 < 4) issueV(Vb[(rr + 1) & 1], r + 1);

        float o[8][4];
#pragma unroll
        for (int nt = 0; nt < 8; nt++)
#pragma unroll
            for (int i = 0; i < 4; i++) o[nt][i] = 0.f;
#pragma unroll
        for (int ks = 0; ks < 16; ks++) {
            uint32_t ah[4];
            ldsm4(ah, aAddrS(Pm, lane, m0, ks * 16, PS));
#pragma unroll
            for (int np = 0; np < 4; np++) {
                uint32_t bh[4];
                ldsm4t(bh, bAddrT(Vc, lane, ks * 16, np * 16));
#pragma unroll
                for (int hf = 0; hf < 2; hf++)
                    mmaH(o[np * 2 + hf], ah, bh + hf * 2);
            }
        }
        uint32_t oh[4][4], ol[4][4];
#pragma unroll
        for (int ks = 0; ks < 4; ks++) {
            splitH(o[2 * ks][0], o[2 * ks][1], oh[ks][0], ol[ks][0]);
            splitH(o[2 * ks][2], o[2 * ks][3], oh[ks][1], ol[ks][1]);
            splitH(o[2 * ks + 1][0], o[2 * ks + 1][1], oh[ks][2], ol[ks][2]);
            splitH(o[2 * ks + 1][2], o[2 * ks + 1][3], oh[ks][3], ol[ks][3]);
        }
        float rv[8][4];
#pragma unroll
        for (int nt = 0; nt < 8; nt++)
#pragma unroll
            for (int i = 0; i < 4; i++) rv[nt][i] = 0.f;
#pragma unroll
        for (int ks = 0; ks < 4; ks++)
#pragma unroll
            for (int np = 0; np < 4; np++) {
                uint32_t bh[4];
                ldsm4t(bh, bAddrT(Wh, lane, ks * 16, np * 16));
#pragma unroll
                for (int hf = 0; hf < 2; hf++) {
                    float* cc = rv[np * 2 + hf];
                    mmaH(cc, oh[ks], bh + hf * 2);
                    mmaH(cc, ol[ks], bh + hf * 2);
                }
            }
#pragma unroll
        for (int nt = 0; nt < 8; nt++) {
            int row = m0 + (lane >> 2), col = nt * 8 + ((lane & 3) << 1);
            float* op = out + ((size_t)r * WW + row) * DD;
            atomicAdd(op + col, 0.5f * rv[nt][0]);
            atomicAdd(op + col + 1, 0.5f * rv[nt][1]);
            float* op2 = out + ((size_t)r * WW + row + 8) * DD;
            atomicAdd(op2 + col, 0.5f * rv[nt][2]);
            atomicAdd(op2 + col + 1, 0.5f * rv[nt][3]);
        }
        __syncthreads();
    }
}

// ============================ small kernels ==================================
__global__ void k_init(const float* __restrict__ bw, const float* __restrict__ bh,
                       float* __restrict__ out) {
    int idx = blockIdx.x * 256 + threadIdx.x;
    out[idx] = 0.5f * (bw[idx & 63] + bh[idx & 63]);
}
__global__ void k_zero_dots() { g_DOTS[blockIdx.x * 256 + threadIdx.x] = 0.f; }

__global__ void k_pair(const float* __restrict__ pb, const float* __restrict__ g,
                       const float* __restrict__ b, const float* __restrict__ Wp) {
    const int t = threadIdx.x;
    const int warp = t >> 5, lane = t & 31, sub = lane >> 3, l8 = lane & 7;
    const int gw = (blockIdx.x * 8 + warp) * 4 + sub;

    const float4* src = (const float4*)(pb + (size_t)gw * 128) + l8 * 4;
    float4 v[4];
#pragma unroll
    for (int qi = 0; qi < 4; qi++) v[qi] = src[qi];
    float s1 = 0.f, s2 = 0.f;
#pragma unroll
    for (int qi = 0; qi < 4; qi++) {
        s1 += v[qi].x + v[qi].y + v[qi].z + v[qi].w;
        s2 += v[qi].x * v[qi].x + v[qi].y * v[qi].y + v[qi].z * v[qi].z + v[qi].w * v[qi].w;
    }
#pragma unroll
    for (int o = 4; o; o >>= 1) {
        s1 += __shfl_xor_sync(0xffffffffu, s1, o);
        s2 += __shfl_xor_sync(0xffffffffu, s2, o);
    }
    float mu = s1 * (1.f / 128.f);
    float rstd = rsqrtf(s2 * (1.f / 128.f) - mu * mu + 1e-5f);

    float phd[8];
#pragma unroll
    for (int h = 0; h < 8; h++) phd[h] = 0.f;
#pragma unroll
    for (int qi = 0; qi < 4; qi++) {
        float4 gv = ((const float4*)g)[l8 * 4 + qi];
        float4 bv = ((const float4*)b)[l8 * 4 + qi];
        float vv[4] = {v[qi].x, v[qi].y, v[qi].z, v[qi].w};
        float gg[4] = {gv.x, gv.y, gv.z, gv.w};
        float bb[4] = {bv.x, bv.y, bv.z, bv.w};
#pragma unroll
        for (int u = 0; u < 4; u++) {
            int p = l8 * 16 + qi * 4 + u;
            float n = (vv[u] - mu) * rstd * gg[u] + bb[u];
            float4 wa = *(const float4*)(Wp + (size_t)p * 8);
            float4 wb = *(const float4*)(Wp + (size_t)p * 8 + 4);
            phd[0] = fmaf(n, wa.x, phd[0]);
            phd[1] = fmaf(n, wa.y, phd[1]);
            phd[2] = fmaf(n, wa.z, phd[2]);
            phd[3] = fmaf(n, wa.w, phd[3]);
            phd[4] = fmaf(n, wb.x, phd[4]);
            phd[5] = fmaf(n, wb.y, phd[5]);
            phd[6] = fmaf(n, wb.z, phd[6]);
            phd[7] = fmaf(n, wb.w, phd[7]);
        }
    }
#pragma unroll
    for (int h = 0; h < 8; h++)
#pragma unroll
        for (int o = 4; o; o >>= 1) phd[h] += __shfl_xor_sync(0xffffffffu, phd[h], o);
    if (l8 == 0)
#pragma unroll
        for (int h = 0; h < 8; h++) g_PB[h * 65536 + gw] = phd[h];
}

// ============================================================================
extern "C" void kernel_launch(void* const* d_in, const int* in_sizes, int n_in,
                              void* d_out, int out_size) {
    (void)in_sizes; (void)n_in; (void)out_size;
    const float* x = (const float*)d_in[0];
    const float* pb = (const float*)d_in[1];
    const float* Wq_w = (const float*)d_in[2];
    const float* Wkv_w = (const float*)d_in[3];
    const float* Wout_w = (const float*)d_in[4];
    const float* bout_w = (const float*)d_in[5];
    const float* Wq_h = (const float*)d_in[6];
    const float* Wkv_h = (const float*)d_in[7];
    const float* Wout_h = (const float*)d_in[8];
    const float* bout_h = (const float*)d_in[9];
    const float* lng = (const float*)d_in[10];
    const float* lnb = (const float*)d_in[11];
    const float* Wp = (const float*)d_in[12];
    float* out = (float*)d_out;

    const int smw = 896 * XS * 2;
    const int smp = 704 * XS * 2;     // Xh + 3xW + Sg
    const int smd = 2 * 384 * XS * 2;
    const int sma = (256 * PS + 512 * XS + 64 * XS) * 2;
    cudaFuncSetAttribute(k_width_mma, cudaFuncAttributeMaxDynamicSharedMemorySize, smw);
    cudaFuncSetAttribute(k_hproj_mma, cudaFuncAttributeMaxDynamicSharedMemorySize, smp);
    cudaFuncSetAttribute(k_hdots_mma, cudaFuncAttributeMaxDynamicSharedMemorySize, smd);
    cudaFuncSetAttribute(k_hav_mma, cudaFuncAttributeMaxDynamicSharedMemorySize, sma);

    k_init<<<16384, 256>>>(bout_w, bout_h, out);
    k_zero_dots<<<2048, 256>>>();
    k_wconv<<<448, 512>>>(Wq_w, Wkv_w, Wout_w, Wq_h, Wkv_h);
    k_hproj_mma<<<dim3(256, 3), 512, smp>>>(x);
    k_pair<<<2048, 256>>>(pb, lng, lnb, Wp);
    k_hdots_mma<<<dim3(8, 2, 8), 512, smd>>>();
    k_hsm2<<<256, 256>>>();
    k_hav_mma<<<dim3(64, 8), 512, sma>>>(Wout_h, out);
    k_width_mma<<<dim3(256, 8), 512, smw>>>(x, out);
}

// round 16
// speedup vs baseline: 2.1787x; 1.0217x over previous
#include <cuda_runtime.h>
#include <cuda_fp16.h>
#include <cstdint>
#include <math.h>

#define HH 256
#define WW 256
#define DD 64
#define NH 8
#define KBIG 16384
#define XS 72
#define PS 264

// chunk-major scratch: Q/K = [head][r][i][64], V = [r][head][j][64]
__device__ __half g_Qh[NH * 256 * KBIG];
__device__ __half g_Kh[NH * 256 * KBIG];
__device__ __half g_Vh[256 * 256 * 512];
__device__ __half g_Ph[NH * 256 * 256];
__device__ float g_DOTS[NH * 256 * 256];
__device__ float g_PB[NH * 256 * 256];
__device__ __half g_Wwid[4 * 8 * 64 * 64];
__device__ __half g_Whgt[3 * 8 * 64 * 64];

// ---------------- warp-MMA helpers ------------------------------------------
__device__ __forceinline__ void ldsm4(uint32_t* r, uint32_t a) {
    asm volatile("ldmatrix.sync.aligned.m8n8.x4.shared.b16 {%0,%1,%2,%3}, [%4];"
                 : "=r"(r[0]), "=r"(r[1]), "=r"(r[2]), "=r"(r[3]) : "r"(a));
}
__device__ __forceinline__ void ldsm4t(uint32_t* r, uint32_t a) {
    asm volatile("ldmatrix.sync.aligned.m8n8.x4.trans.shared.b16 {%0,%1,%2,%3}, [%4];"
                 : "=r"(r[0]), "=r"(r[1]), "=r"(r[2]), "=r"(r[3]) : "r"(a));
}
__device__ __forceinline__ void mmaH(float* c, const uint32_t* a, const uint32_t* b) {
    asm volatile("mma.sync.aligned.m16n8k16.row.col.f32.f16.f16.f32 "
                 "{%0,%1,%2,%3},{%4,%5,%6,%7},{%8,%9},{%0,%1,%2,%3};"
                 : "+f"(c[0]), "+f"(c[1]), "+f"(c[2]), "+f"(c[3])
                 : "r"(a[0]), "r"(a[1]), "r"(a[2]), "r"(a[3]), "r"(b[0]), "r"(b[1]));
}
__device__ __forceinline__ void splitH(float a, float b, uint32_t& h, uint32_t& l) {
    __half2 hv = __floats2half2_rn(a, b);
    float2 hf = __half22float2(hv);
    __half2 lv = __floats2half2_rn(a - hf.x, b - hf.y);
    h = *reinterpret_cast<uint32_t*>(&hv);
    l = *reinterpret_cast<uint32_t*>(&lv);
}
__device__ __forceinline__ uint32_t packH(float a, float b) {
    __half2 hv = __floats2half2_rn(a, b);
    return *reinterpret_cast<uint32_t*>(&hv);
}
__device__ __forceinline__ uint32_t aAddr(const __half* base, int lane, int r0, int k0) {
    int row = r0 + (lane & 15), col = k0 + ((lane >> 4) << 3);
    return (uint32_t)__cvta_generic_to_shared(base + row * XS + col);
}
__device__ __forceinline__ uint32_t aAddrS(const __half* base, int lane, int r0, int k0, int st) {
    int row = r0 + (lane & 15), col = k0 + ((lane >> 4) << 3);
    return (uint32_t)__cvta_generic_to_shared(base + row * st + col);
}
__device__ __forceinline__ uint32_t bAddrT(const __half* base, int lane, int k0, int n0) {
    int row = k0 + (lane & 7) + (((lane >> 3) & 1) << 3);
    int col = n0 + ((lane >> 4) << 3);
    return (uint32_t)__cvta_generic_to_shared(base + row * XS + col);
}
__device__ __forceinline__ uint32_t bAddrN(const __half* base, int lane, int j0, int d0) {
    int row = j0 + (lane & 7) + ((lane >> 4) << 3);
    int col = d0 + (((lane >> 3) & 1) << 3);
    return (uint32_t)__cvta_generic_to_shared(base + row * XS + col);
}
#define CP16(sa, gp) asm volatile("cp.async.cg.shared.global [%0], [%1], 16;" :: "r"(sa), "l"(gp))
#define CP_COMMIT()  asm volatile("cp.async.commit_group;" ::: "memory")
#define CP_WAIT0()   asm volatile("cp.async.wait_group 0;" ::: "memory")
#define CP_WAIT1()   asm volatile("cp.async.wait_group 1;" ::: "memory")

// ============================================================================
__global__ void k_wconv(const float* __restrict__ Wq_w, const float* __restrict__ Wkv_w,
                        const float* __restrict__ Wout_w, const float* __restrict__ Wq_h,
                        const float* __restrict__ Wkv_h) {
    int idx = blockIdx.x * 512 + threadIdx.x;
    if (idx < 131072) {
        int mat = idx >> 15, rem = idx & 32767, head = rem >> 12, e = rem & 4095;
        int k = e >> 6, n = e & 63;
        float v;
        if (mat == 0) v = Wkv_w[k * 1024 + head * 64 + n];
        else if (mat == 1) v = Wq_w[k * 512 + head * 64 + n] * 0.125f;
        else if (mat == 2) v = Wkv_w[k * 1024 + 512 + head * 64 + n];
        else v = Wout_w[(head * 64 + k) * 64 + n];
        g_Wwid[idx] = __float2half_rn(v);
    } else if (idx < 229376) {
        int j = idx - 131072;
        int mk = j >> 15, rem = j & 32767, gg = rem >> 12, e = rem & 4095;
        int k = e >> 6, n = e & 63;
        float v;
        if (mk == 0) v = Wq_h[k * 512 + gg * 64 + n] * 0.0078125f;
        else if (mk == 1) v = Wkv_h[k * 1024 + gg * 64 + n];
        else v = Wkv_h[k * 1024 + 512 + gg * 64 + n];
        g_Whgt[j] = __float2half_rn(v);
    }
}

// ============================================================================
// Width attention (validated round 14/15) — unchanged.
// ============================================================================
__global__ void __launch_bounds__(512, 1)
k_width_mma(const float* __restrict__ x, float* __restrict__ out) {
    extern __shared__ __half sb[];
    __half* Xh = sb;
    __half* Xl = sb + 256 * XS;
    __half* Kh = sb + 512 * XS;
    __half* W0 = sb + 768 * XS;
    __half* W1 = sb + 832 * XS;

    const int t = threadIdx.x, lane = t & 31, warp = t >> 5, m0 = warp * 16;
    const int w = blockIdx.x, head = blockIdx.y;

    auto loadW = [&](__half* dst, int mat) {
        const __half* src = g_Wwid + (size_t)(mat * 8 + head) * 4096;
        for (int e = t; e < 2048; e += 512) {
            int k = e >> 5, n2 = e & 31;
            *(uint32_t*)(dst + k * XS + n2 * 2) = *(const uint32_t*)(src + k * 64 + n2 * 2);
        }
    };
    loadW(W0, 0);
    {
        int row = t >> 1, q0 = (t & 1) * 8;
        const float4* src = (const float4*)(x + (size_t)row * (WW * DD) + w * DD) + q0;
#pragma unroll
        for (int q4 = 0; q4 < 8; q4++) {
            float4 v = src[q4];
            uint32_t h0, l0, h1, l1;
            splitH(v.x, v.y, h0, l0);
            splitH(v.z, v.w, h1, l1);
            int cc = (q0 + q4) * 4;
            *(uint32_t*)(Xh + row * XS + cc) = h0;
            *(uint32_t*)(Xh + row * XS + cc + 2) = h1;
            *(uint32_t*)(Xl + row * XS + cc) = l0;
            *(uint32_t*)(Xl + row * XS + cc + 2) = l1;
        }
    }
    auto proj = [&](float (&c)[8][4], const __half* Wb) {
#pragma unroll
        for (int nt = 0; nt < 8; nt++)
#pragma unroll
            for (int i = 0; i < 4; i++) c[nt][i] = 0.f;
#pragma unroll
        for (int ks = 0; ks < 4; ks++) {
            uint32_t ah[4], al[4];
            ldsm4(ah, aAddr(Xh, lane, m0, ks * 16));
            ldsm4(al, aAddr(Xl, lane, m0, ks * 16));
#pragma unroll
            for (int np = 0; np < 4; np++) {
                uint32_t bh[4];
                ldsm4t(bh, bAddrT(Wb, lane, ks * 16, np * 16));
#pragma unroll
                for (int hf = 0; hf < 2; hf++) {
                    float* cc = c[np * 2 + hf];
                    mmaH(cc, ah, bh + hf * 2);
                    mmaH(cc, al, bh + hf * 2);
                }
            }
        }
    };
    auto storeHi = [&](float (&c)[8][4], __half* Dh) {
#pragma unroll
        for (int nt = 0; nt < 8; nt++) {
            int r = m0 + (lane >> 2), cc = nt * 8 + ((lane & 3) << 1);
            *(uint32_t*)(Dh + r * XS + cc) = packH(c[nt][0], c[nt][1]);
            *(uint32_t*)(Dh + (r + 8) * XS + cc) = packH(c[nt][2], c[nt][3]);
        }
    };

    float c[8][4];
    __syncthreads();
    loadW(W1, 1);
    proj(c, W0);
    storeHi(c, Kh);
    __syncthreads();
    loadW(W0, 2);
    proj(c, W1);
    uint32_t qh[4][4];
#pragma unroll
    for (int ks = 0; ks < 4; ks++) {
        qh[ks][0] = packH(c[2 * ks][0], c[2 * ks][1]);
        qh[ks][1] = packH(c[2 * ks][2], c[2 * ks][3]);
        qh[ks][2] = packH(c[2 * ks + 1][0], c[2 * ks + 1][1]);
        qh[ks][3] = packH(c[2 * ks + 1][2], c[2 * ks + 1][3]);
    }
    __syncthreads();
    loadW(W1, 3);
    proj(c, W0);
    storeHi(c, Xh);
    __syncthreads();

    float o[8][4];
#pragma unroll
    for (int nt = 0; nt < 8; nt++)
#pragma unroll
        for (int i = 0; i < 4; i++) o[nt][i] = 0.f;
    float lsum[2] = {0.f, 0.f};

    for (int jc = 0; jc < 8; jc++) {
        float s[4][4];
#pragma unroll
        for (int jt = 0; jt < 4; jt++)
#pragma unroll
            for (int i = 0; i < 4; i++) s[jt][i] = 0.f;
#pragma unroll
        for (int ks = 0; ks < 4; ks++) {
            uint32_t kb[2][4];
            ldsm4(kb[0], bAddrN(Kh, lane, jc * 32, ks * 16));
            ldsm4(kb[1], bAddrN(Kh, lane, jc * 32 + 16, ks * 16));
#pragma unroll
            for (int jt = 0; jt < 4; jt++)
                mmaH(s[jt], qh[ks], &kb[jt >> 1][(jt & 1) * 2]);
        }
        uint32_t ph[2][4];
#pragma unroll
        for (int k2 = 0; k2 < 2; k2++) {
            float e0 = __expf(s[2 * k2][0]), e1 = __expf(s[2 * k2][1]);
            float e2 = __expf(s[2 * k2][2]), e3 = __expf(s[2 * k2][3]);
            float f0 = __expf(s[2 * k2 + 1][0]), f1 = __expf(s[2 * k2 + 1][1]);
            float f2 = __expf(s[2 * k2 + 1][2]), f3 = __expf(s[2 * k2 + 1][3]);
            lsum[0] += e0 + e1 + f0 + f1;
            lsum[1] += e2 + e3 + f2 + f3;
            ph[k2][0] = packH(e0, e1);
            ph[k2][1] = packH(e2, e3);
            ph[k2][2] = packH(f0, f1);
            ph[k2][3] = packH(f2, f3);
        }
#pragma unroll
        for (int k2 = 0; k2 < 2; k2++) {
            int j0 = jc * 32 + k2 * 16;
#pragma unroll
            for (int np = 0; np < 4; np++) {
                uint32_t vb[4];
                ldsm4t(vb, bAddrT(Xh, lane, j0, np * 16));
#pragma unroll
                for (int hf = 0; hf < 2; hf++)
                    mmaH(o[np * 2 + hf], ph[k2], vb + hf * 2);
            }
        }
    }
#pragma unroll
    for (int i = 0; i < 2; i++) {
        lsum[i] += __shfl_xor_sync(0xffffffffu, lsum[i], 1);
        lsum[i] += __shfl_xor_sync(0xffffffffu, lsum[i], 2);
    }
    float i0 = 1.f / lsum[0], i1 = 1.f / lsum[1];
    uint32_t oh[4][4], ol[4][4];
#pragma unroll
    for (int ks = 0; ks < 4; ks++) {
        splitH(o[2 * ks][0] * i0, o[2 * ks][1] * i0, oh[ks][0], ol[ks][0]);
        splitH(o[2 * ks][2] * i1, o[2 * ks][3] * i1, oh[ks][1], ol[ks][1]);
        splitH(o[2 * ks + 1][0] * i0, o[2 * ks + 1][1] * i0, oh[ks][2], ol[ks][2]);
        splitH(o[2 * ks + 1][2] * i1, o[2 * ks + 1][3] * i1, oh[ks][3], ol[ks][3]);
    }
    float r[8][4];
#pragma unroll
    for (int nt = 0; nt < 8; nt++)
#pragma unroll
        for (int i = 0; i < 4; i++) r[nt][i] = 0.f;
#pragma unroll
    for (int ks = 0; ks < 4; ks++)
#pragma unroll
        for (int np = 0; np < 4; np++) {
            uint32_t bh[4];
            ldsm4t(bh, bAddrT(W1, lane, ks * 16, np * 16));
#pragma unroll
            for (int hf = 0; hf < 2; hf++) {
                float* rr = r[np * 2 + hf];
                mmaH(rr, oh[ks], bh + hf * 2);
                mmaH(rr, ol[ks], bh + hf * 2);
            }
        }
#pragma unroll
    for (int nt = 0; nt < 8; nt++) {
        int row = m0 + (lane >> 2), col = nt * 8 + ((lane & 3) << 1);
        float* op = out + ((size_t)row * WW + w) * DD;
        atomicAdd(op + col, 0.5f * r[nt][0]);
        atomicAdd(op + col + 1, 0.5f * r[nt][1]);
        float* op2 = out + ((size_t)(row + 8) * WW + w) * DD;
        atomicAdd(op2 + col, 0.5f * r[nt][2]);
        atomicAdd(op2 + col + 1, 0.5f * r[nt][3]);
    }
}

// ============================================================================
// Height projection v6: 256-thread blocks, 128 X rows each, 2 CTAs/SM.
// grid (r=256, mk=3, half=2). smem rows: Xh 128, W 3x64, Sg 128 = 448 (~63KB)
// ============================================================================
__global__ void __launch_bounds__(256, 2)
k_hproj_mma(const float* __restrict__ x) {
    extern __shared__ __half sb[];
    __half* Xh = sb;                 // 128 rows
    __half* Wb = sb + 128 * XS;      // 3 x 64 rows
    __half* Sg = sb + 320 * XS;      // 128 rows

    const int t = threadIdx.x, lane = t & 31, warp = t >> 5, m0 = warp * 16;
    const int r = blockIdx.x, mk = blockIdx.y, half = blockIdx.z;
    const int rbase = half * 128;

    auto issueW = [&](int g) {
        __half* dst = Wb + (g % 3) * 64 * XS;
        const __half* src = g_Whgt + (size_t)(mk * 8 + g) * 4096;
#pragma unroll
        for (int p = 0; p < 2; p++) {
            int e = p * 256 + t, row = e >> 3, c8 = e & 7;
            uint32_t sa = (uint32_t)__cvta_generic_to_shared(dst + row * XS + c8 * 8);
            CP16(sa, src + row * 64 + c8 * 8);
        }
        CP_COMMIT();
    };
    issueW(0);
    issueW(1);
    {   // X hi-only: 128 rows, each thread loads half a row
        int lrow = t >> 1, q0 = (t & 1) * 8;
        const float4* src = (const float4*)(x + (size_t)r * (WW * DD) + (rbase + lrow) * 64) + q0;
#pragma unroll
        for (int q4 = 0; q4 < 8; q4++) {
            float4 v = src[q4];
            int cc = (q0 + q4) * 4;
            *(uint32_t*)(Xh + lrow * XS + cc) = packH(v.x, v.y);
            *(uint32_t*)(Xh + lrow * XS + cc + 2) = packH(v.z, v.w);
        }
    }
    for (int g = 0; g < 8; g++) {
        if (g < 7) CP_WAIT1(); else CP_WAIT0();
        __syncthreads();
        if (g + 2 < 8) issueW(g + 2);
        const __half* cur = Wb + (g % 3) * 64 * XS;

        float c[8][4];
#pragma unroll
        for (int nt = 0; nt < 8; nt++)
#pragma unroll
            for (int i = 0; i < 4; i++) c[nt][i] = 0.f;
#pragma unroll
        for (int ks = 0; ks < 4; ks++) {
            uint32_t ah[4];
            ldsm4(ah, aAddr(Xh, lane, m0, ks * 16));
#pragma unroll
            for (int np = 0; np < 4; np++) {
                uint32_t bh[4];
                ldsm4t(bh, bAddrT(cur, lane, ks * 16, np * 16));
#pragma unroll
                for (int hf = 0; hf < 2; hf++)
                    mmaH(c[np * 2 + hf], ah, bh + hf * 2);
            }
        }
        // warp-local staging (own 16 local rows)
#pragma unroll
        for (int nt = 0; nt < 8; nt++) {
            int row = m0 + (lane >> 2), cc = nt * 8 + ((lane & 3) << 1);
            *(uint32_t*)(Sg + row * XS + cc) = packH(c[nt][0], c[nt][1]);
            *(uint32_t*)(Sg + (row + 8) * XS + cc) = packH(c[nt][2], c[nt][3]);
        }
        __syncwarp();
        // warp-coalesced copy-out of own 16x64 tile
        {
            int lrow = m0 + (lane >> 1), coff = (lane & 1) * 32;
            int grow = rbase + lrow;
            size_t gb;
            if (mk < 2) gb = (((size_t)(g * 256 + r)) * 256 + grow) * 64 + coff;
            else        gb = (((size_t)(r * 8 + g)) * 256 + grow) * 64 + coff;
            __half* gdst = (mk == 0) ? g_Qh : (mk == 1) ? g_Kh : g_Vh;
#pragma unroll
            for (int q = 0; q < 4; q++) {
                uint4 v = *(uint4*)(Sg + lrow * XS + coff + q * 8);
                *(uint4*)(gdst + gb + q * 8) = v;
            }
        }
    }
}

// ============================================================================
// Height dots v4 (validated round 14) — unchanged.
// ============================================================================
__global__ void __launch_bounds__(512, 1) k_hdots_mma() {
    extern __shared__ __half sb[];
    const int t = threadIdx.x, lane = t & 31, warp = t >> 5;
    const int kc = blockIdx.x, it = blockIdx.y, head = blockIdx.z;
    const int wm = warp >> 1, wn = warp & 1;
    const int m0 = wm * 16, j0 = wn * 128;

    auto issue = [&](__half* base, int step) {
        const int rk = kc * 32 + step;
#pragma unroll
        for (int rr2 = 0; rr2 < 6; rr2++) {
            int e = rr2 * 512 + t;
            const __half* gp;
            uint32_t sa;
            if (e < 1024) {
                int row = e >> 3, c8 = e & 7;
                gp = g_Qh + (((size_t)(head * 256 + rk)) * 256 + it * 128 + row) * 64 + c8 * 8;
                sa = (uint32_t)__cvta_generic_to_shared(base + row * XS + c8 * 8);
            } else {
                int idx = e - 1024, row = idx >> 3, c8 = idx & 7;
                gp = g_Kh + (((size_t)(head * 256 + rk)) * 256 + row) * 64 + c8 * 8;
                sa = (uint32_t)__cvta_generic_to_shared(base + (128 + row) * XS + c8 * 8);
            }
            CP16(sa, gp);
        }
        CP_COMMIT();
    };

    float c[16][4];
#pragma unroll
    for (int nt = 0; nt < 16; nt++)
#pragma unroll
        for (int i = 0; i < 4; i++) c[nt][i] = 0.f;

    issue(sb, 0);
    for (int step = 0; step < 32; step++) {
        CP_WAIT0();
        __syncthreads();
        __half* cur = sb + (step & 1) * 384 * XS;
        if (step + 1 < 32) issue(sb + ((step + 1) & 1) * 384 * XS, step + 1);
        __half* Qh = cur;
        __half* Kh = cur + 128 * XS;
#pragma unroll
        for (int ks = 0; ks < 4; ks++) {
            uint32_t ah[4];
            ldsm4(ah, aAddr(Qh, lane, m0, ks * 16));
#pragma unroll
            for (int jt = 0; jt < 8; jt++) {
                uint32_t bh[4];
                ldsm4(bh, bAddrN(Kh, lane, j0 + jt * 16, ks * 16));
#pragma unroll
                for (int hf = 0; hf < 2; hf++)
                    mmaH(c[jt * 2 + hf], ah, bh + hf * 2);
            }
        }
    }
#pragma unroll
    for (int nt = 0; nt < 16; nt++) {
        int row = it * 128 + m0 + (lane >> 2), col = j0 + nt * 8 + ((lane & 3) << 1);
        atomicAdd(&g_DOTS[head * 65536 + row * 256 + col], c[nt][0]);
        atomicAdd(&g_DOTS[head * 65536 + row * 256 + col + 1], c[nt][1]);
        atomicAdd(&g_DOTS[head * 65536 + (row + 8) * 256 + col], c[nt][2]);
        atomicAdd(&g_DOTS[head * 65536 + (row + 8) * 256 + col + 1], c[nt][3]);
    }
}

// ============================================================================
__global__ void k_hsm2() {
    const int t = threadIdx.x, warp = t >> 5, lane = t & 31;
    const int row = blockIdx.x * 8 + warp;
    float v[8];
    float mx = -1e30f;
#pragma unroll
    for (int kk = 0; kk < 8; kk++) {
        int j = kk * 32 + lane;
        v[kk] = g_DOTS[row * 256 + j] + g_PB[row * 256 + j];
        mx = fmaxf(mx, v[kk]);
    }
#pragma unroll
    for (int o = 16; o; o >>= 1) mx = fmaxf(mx, __shfl_xor_sync(0xffffffffu, mx, o));
    float s = 0.f;
#pragma unroll
    for (int kk = 0; kk < 8; kk++) { v[kk] = __expf(v[kk] - mx); s += v[kk]; }
#pragma unroll
    for (int o = 16; o; o >>= 1) s += __shfl_xor_sync(0xffffffffu, s, o);
    float inv = 1.f / s;
#pragma unroll
    for (int kk = 0; kk < 8; kk++)
        g_Ph[row * 256 + kk * 32 + lane] = __float2half_rn(v[kk] * inv);
}

// ============================================================================
// Height AV v3 (validated round 14) — unchanged.
// ============================================================================
__global__ void __launch_bounds__(512, 1)
k_hav_mma(const float* __restrict__ Wout, float* __restrict__ out) {
    extern __shared__ __half sb[];
    __half* Pm = sb;
    __half* Vb[2] = {sb + 256 * PS, sb + 256 * PS + 256 * XS};
    __half* Wh = sb + 256 * PS + 512 * XS;

    const int t = threadIdx.x, lane = t & 31, warp = t >> 5, m0 = warp * 16;
    const int rg = blockIdx.x, head = blockIdx.y;

    for (int e = t; e < 2048; e += 512) {
        int k = e >> 5, n2 = e & 31;
        float2 v = *(const float2*)(Wout + (size_t)(head * 64 + k) * 64 + n2 * 2);
        *(uint32_t*)(Wh + k * XS + n2 * 2) = packH(v.x, v.y);
    }
#pragma unroll
    for (int p = 0; p < 16; p++) {
        int e = p * 512 + t, row = e >> 5, c8 = e & 31;
        uint32_t sa = (uint32_t)__cvta_generic_to_shared(Pm + row * PS + c8 * 8);
        CP16(sa, g_Ph + (size_t)head * 65536 + row * 256 + c8 * 8);
    }
    CP_COMMIT();

    auto issueV = [&](__half* dst, int r) {
#pragma unroll
        for (int p = 0; p < 4; p++) {
            int e = p * 512 + t, row = e >> 3, c8 = e & 7;
            uint32_t sa = (uint32_t)__cvta_generic_to_shared(dst + row * XS + c8 * 8);
            CP16(sa, g_Vh + (((size_t)(r * 8 + head)) * 256 + row) * 64 + c8 * 8);
        }
        CP_COMMIT();
    };
    issueV(Vb[0], rg * 4);

    for (int rr = 0; rr < 4; rr++) {
        int r = rg * 4 + rr;
        CP_WAIT0();
        __syncthreads();
        __half* Vc = Vb[rr & 1];
        if (rr + 1 < 4) issueV(Vb[(rr + 1) & 1], r + 1);

        float o[8][4];
#pragma unroll
        for (int nt = 0; nt < 8; nt++)
#pragma unroll
            for (int i = 0; i < 4; i++) o[nt][i] = 0.f;
#pragma unroll
        for (int ks = 0; ks < 16; ks++) {
            uint32_t ah[4];
            ldsm4(ah, aAddrS(Pm, lane, m0, ks * 16, PS));
#pragma unroll
            for (int np = 0; np < 4; np++) {
                uint32_t bh[4];
                ldsm4t(bh, bAddrT(Vc, lane, ks * 16, np * 16));
#pragma unroll
                for (int hf = 0; hf < 2; hf++)
                    mmaH(o[np * 2 + hf], ah, bh + hf * 2);
            }
        }
        uint32_t oh[4][4], ol[4][4];
#pragma unroll
        for (int ks = 0; ks < 4; ks++) {
            splitH(o[2 * ks][0], o[2 * ks][1], oh[ks][0], ol[ks][0]);
            splitH(o[2 * ks][2], o[2 * ks][3], oh[ks][1], ol[ks][1]);
            splitH(o[2 * ks + 1][0], o[2 * ks + 1][1], oh[ks][2], ol[ks][2]);
            splitH(o[2 * ks + 1][2], o[2 * ks + 1][3], oh[ks][3], ol[ks][3]);
        }
        float rv[8][4];
#pragma unroll
        for (int nt = 0; nt < 8; nt++)
#pragma unroll
            for (int i = 0; i < 4; i++) rv[nt][i] = 0.f;
#pragma unroll
        for (int ks = 0; ks < 4; ks++)
#pragma unroll
            for (int np = 0; np < 4; np++) {
                uint32_t bh[4];
                ldsm4t(bh, bAddrT(Wh, lane, ks * 16, np * 16));
#pragma unroll
                for (int hf = 0; hf < 2; hf++) {
                    float* cc = rv[np * 2 + hf];
                    mmaH(cc, oh[ks], bh + hf * 2);
                    mmaH(cc, ol[ks], bh + hf * 2);
                }
            }
#pragma unroll
        for (int nt = 0; nt < 8; nt++) {
            int row = m0 + (lane >> 2), col = nt * 8 + ((lane & 3) << 1);
            float* op = out + ((size_t)r * WW + row) * DD;
            atomicAdd(op + col, 0.5f * rv[nt][0]);
            atomicAdd(op + col + 1, 0.5f * rv[nt][1]);
            float* op2 = out + ((size_t)r * WW + row + 8) * DD;
            atomicAdd(op2 + col, 0.5f * rv[nt][2]);
            atomicAdd(op2 + col + 1, 0.5f * rv[nt][3]);
        }
        __syncthreads();
    }
}

// ============================ small kernels ==================================
__global__ void k_init(const float* __restrict__ bw, const float* __restrict__ bh,
                       float* __restrict__ out) {
    int idx = blockIdx.x * 256 + threadIdx.x;
    out[idx] = 0.5f * (bw[idx & 63] + bh[idx & 63]);
}
__global__ void k_zero_dots() { g_DOTS[blockIdx.x * 256 + threadIdx.x] = 0.f; }

__global__ void k_pair(const float* __restrict__ pb, const float* __restrict__ g,
                       const float* __restrict__ b, const float* __restrict__ Wp) {
    const int t = threadIdx.x;
    const int warp = t >> 5, lane = t & 31, sub = lane >> 3, l8 = lane & 7;
    const int gw = (blockIdx.x * 8 + warp) * 4 + sub;

    const float4* src = (const float4*)(pb + (size_t)gw * 128) + l8 * 4;
    float4 v[4];
#pragma unroll
    for (int qi = 0; qi < 4; qi++) v[qi] = src[qi];
    float s1 = 0.f, s2 = 0.f;
#pragma unroll
    for (int qi = 0; qi < 4; qi++) {
        s1 += v[qi].x + v[qi].y + v[qi].z + v[qi].w;
        s2 += v[qi].x * v[qi].x + v[qi].y * v[qi].y + v[qi].z * v[qi].z + v[qi].w * v[qi].w;
    }
#pragma unroll
    for (int o = 4; o; o >>= 1) {
        s1 += __shfl_xor_sync(0xffffffffu, s1, o);
        s2 += __shfl_xor_sync(0xffffffffu, s2, o);
    }
    float mu = s1 * (1.f / 128.f);
    float rstd = rsqrtf(s2 * (1.f / 128.f) - mu * mu + 1e-5f);

    float phd[8];
#pragma unroll
    for (int h = 0; h < 8; h++) phd[h] = 0.f;
#pragma unroll
    for (int qi = 0; qi < 4; qi++) {
        float4 gv = ((const float4*)g)[l8 * 4 + qi];
        float4 bv = ((const float4*)b)[l8 * 4 + qi];
        float vv[4] = {v[qi].x, v[qi].y, v[qi].z, v[qi].w};
        float gg[4] = {gv.x, gv.y, gv.z, gv.w};
        float bb[4] = {bv.x, bv.y, bv.z, bv.w};
#pragma unroll
        for (int u = 0; u < 4; u++) {
            int p = l8 * 16 + qi * 4 + u;
            float n = (vv[u] - mu) * rstd * gg[u] + bb[u];
            float4 wa = *(const float4*)(Wp + (size_t)p * 8);
            float4 wb = *(const float4*)(Wp + (size_t)p * 8 + 4);
            phd[0] = fmaf(n, wa.x, phd[0]);
            phd[1] = fmaf(n, wa.y, phd[1]);
            phd[2] = fmaf(n, wa.z, phd[2]);
            phd[3] = fmaf(n, wa.w, phd[3]);
            phd[4] = fmaf(n, wb.x, phd[4]);
            phd[5] = fmaf(n, wb.y, phd[5]);
            phd[6] = fmaf(n, wb.z, phd[6]);
            phd[7] = fmaf(n, wb.w, phd[7]);
        }
    }
#pragma unroll
    for (int h = 0; h < 8; h++)
#pragma unroll
        for (int o = 4; o; o >>= 1) phd[h] += __shfl_xor_sync(0xffffffffu, phd[h], o);
    if (l8 == 0)
#pragma unroll
        for (int h = 0; h < 8; h++) g_PB[h * 65536 + gw] = phd[h];
}

// ============================================================================
extern "C" void kernel_launch(void* const* d_in, const int* in_sizes, int n_in,
                              void* d_out, int out_size) {
    (void)in_sizes; (void)n_in; (void)out_size;
    const float* x = (const float*)d_in[0];
    const float* pb = (const float*)d_in[1];
    const float* Wq_w = (const float*)d_in[2];
    const float* Wkv_w = (const float*)d_in[3];
    const float* Wout_w = (const float*)d_in[4];
    const float* bout_w = (const float*)d_in[5];
    const float* Wq_h = (const float*)d_in[6];
    const float* Wkv_h = (const float*)d_in[7];
    const float* Wout_h = (const float*)d_in[8];
    const float* bout_h = (const float*)d_in[9];
    const float* lng = (const float*)d_in[10];
    const float* lnb = (const float*)d_in[11];
    const float* Wp = (const float*)d_in[12];
    float* out = (float*)d_out;

    const int smw = 896 * XS * 2;
    const int smp = 448 * XS * 2;      // Xh128 + 3xW64 + Sg128
    const int smd = 2 * 384 * XS * 2;
    const int sma = (256 * PS + 512 * XS + 64 * XS) * 2;
    cudaFuncSetAttribute(k_width_mma, cudaFuncAttributeMaxDynamicSharedMemorySize, smw);
    cudaFuncSetAttribute(k_hproj_mma, cudaFuncAttributeMaxDynamicSharedMemorySize, smp);
    cudaFuncSetAttribute(k_hdots_mma, cudaFuncAttributeMaxDynamicSharedMemorySize, smd);
    cudaFuncSetAttribute(k_hav_mma, cudaFuncAttributeMaxDynamicSharedMemorySize, sma);

    k_init<<<16384, 256>>>(bout_w, bout_h, out);
    k_zero_dots<<<2048, 256>>>();
    k_wconv<<<448, 512>>>(Wq_w, Wkv_w, Wout_w, Wq_h, Wkv_h);
    k_hproj_mma<<<dim3(256, 3, 2), 256, smp>>>(x);
    k_pair<<<2048, 256>>>(pb, lng, lnb, Wp);
    k_hdots_mma<<<dim3(8, 2, 8), 512, smd>>>();
    k_hsm2<<<256, 256>>>();
    k_hav_mma<<<dim3(64, 8), 512, sma>>>(Wout_h, out);
    k_width_mma<<<dim3(256, 8), 512, smw>>>(x, out);
}

// round 17
// speedup vs baseline: 2.2354x; 1.0260x over previous
#include <cuda_runtime.h>
#include <cuda_fp16.h>
#include <cstdint>
#include <math.h>

#define HH 256
#define WW 256
#define DD 64
#define NH 8
#define KBIG 16384
#define XS 72
#define PS 264

// chunk-major scratch: Q/K = [head][r][i][64], V = [r][head][j][64]
__device__ __half g_Qh[NH * 256 * KBIG];
__device__ __half g_Kh[NH * 256 * KBIG];
__device__ __half g_Vh[256 * 256 * 512];
__device__ __half g_Ph[NH * 256 * 256];
__device__ float g_DOTS[NH * 256 * 256];
__device__ float g_PB[NH * 256 * 256];
__device__ __half g_Wwid[4 * 8 * 64 * 64];
__device__ __half g_Whgt[3 * 8 * 64 * 64];

// ---------------- warp-MMA helpers ------------------------------------------
__device__ __forceinline__ void ldsm4(uint32_t* r, uint32_t a) {
    asm volatile("ldmatrix.sync.aligned.m8n8.x4.shared.b16 {%0,%1,%2,%3}, [%4];"
                 : "=r"(r[0]), "=r"(r[1]), "=r"(r[2]), "=r"(r[3]) : "r"(a));
}
__device__ __forceinline__ void ldsm4t(uint32_t* r, uint32_t a) {
    asm volatile("ldmatrix.sync.aligned.m8n8.x4.trans.shared.b16 {%0,%1,%2,%3}, [%4];"
                 : "=r"(r[0]), "=r"(r[1]), "=r"(r[2]), "=r"(r[3]) : "r"(a));
}
__device__ __forceinline__ void mmaH(float* c, const uint32_t* a, const uint32_t* b) {
    asm volatile("mma.sync.aligned.m16n8k16.row.col.f32.f16.f16.f32 "
                 "{%0,%1,%2,%3},{%4,%5,%6,%7},{%8,%9},{%0,%1,%2,%3};"
                 : "+f"(c[0]), "+f"(c[1]), "+f"(c[2]), "+f"(c[3])
                 : "r"(a[0]), "r"(a[1]), "r"(a[2]), "r"(a[3]), "r"(b[0]), "r"(b[1]));
}
__device__ __forceinline__ void splitH(float a, float b, uint32_t& h, uint32_t& l) {
    __half2 hv = __floats2half2_rn(a, b);
    float2 hf = __half22float2(hv);
    __half2 lv = __floats2half2_rn(a - hf.x, b - hf.y);
    h = *reinterpret_cast<uint32_t*>(&hv);
    l = *reinterpret_cast<uint32_t*>(&lv);
}
__device__ __forceinline__ uint32_t packH(float a, float b) {
    __half2 hv = __floats2half2_rn(a, b);
    return *reinterpret_cast<uint32_t*>(&hv);
}
__device__ __forceinline__ uint32_t aAddr(const __half* base, int lane, int r0, int k0) {
    int row = r0 + (lane & 15), col = k0 + ((lane >> 4) << 3);
    return (uint32_t)__cvta_generic_to_shared(base + row * XS + col);
}
__device__ __forceinline__ uint32_t aAddrS(const __half* base, int lane, int r0, int k0, int st) {
    int row = r0 + (lane & 15), col = k0 + ((lane >> 4) << 3);
    return (uint32_t)__cvta_generic_to_shared(base + row * st + col);
}
__device__ __forceinline__ uint32_t bAddrT(const __half* base, int lane, int k0, int n0) {
    int row = k0 + (lane & 7) + (((lane >> 3) & 1) << 3);
    int col = n0 + ((lane >> 4) << 3);
    return (uint32_t)__cvta_generic_to_shared(base + row * XS + col);
}
__device__ __forceinline__ uint32_t bAddrN(const __half* base, int lane, int j0, int d0) {
    int row = j0 + (lane & 7) + ((lane >> 4) << 3);
    int col = d0 + (((lane >> 3) & 1) << 3);
    return (uint32_t)__cvta_generic_to_shared(base + row * XS + col);
}
#define CP16(sa, gp) asm volatile("cp.async.cg.shared.global [%0], [%1], 16;" :: "r"(sa), "l"(gp))
#define CP_COMMIT()  asm volatile("cp.async.commit_group;" ::: "memory")
#define CP_WAIT0()   asm volatile("cp.async.wait_group 0;" ::: "memory")
#define CP_WAIT1()   asm volatile("cp.async.wait_group 1;" ::: "memory")

// ============================================================================
// Merged init: out = 0.5*(bw+bh) broadcast, plus zero g_DOTS.
// ============================================================================
__global__ void k_init(const float* __restrict__ bw, const float* __restrict__ bh,
                       float* __restrict__ out) {
    int idx = blockIdx.x * 256 + threadIdx.x;
    out[idx] = 0.5f * (bw[idx & 63] + bh[idx & 63]);
    if (idx < NH * 256 * 256) g_DOTS[idx] = 0.f;
}

__global__ void k_wconv(const float* __restrict__ Wq_w, const float* __restrict__ Wkv_w,
                        const float* __restrict__ Wout_w, const float* __restrict__ Wq_h,
                        const float* __restrict__ Wkv_h) {
    int idx = blockIdx.x * 512 + threadIdx.x;
    if (idx < 131072) {
        int mat = idx >> 15, rem = idx & 32767, head = rem >> 12, e = rem & 4095;
        int k = e >> 6, n = e & 63;
        float v;
        if (mat == 0) v = Wkv_w[k * 1024 + head * 64 + n];
        else if (mat == 1) v = Wq_w[k * 512 + head * 64 + n] * 0.125f;
        else if (mat == 2) v = Wkv_w[k * 1024 + 512 + head * 64 + n];
        else v = Wout_w[(head * 64 + k) * 64 + n];
        g_Wwid[idx] = __float2half_rn(v);
    } else if (idx < 229376) {
        int j = idx - 131072;
        int mk = j >> 15, rem = j & 32767, gg = rem >> 12, e = rem & 4095;
        int k = e >> 6, n = e & 63;
        float v;
        if (mk == 0) v = Wq_h[k * 512 + gg * 64 + n] * 0.0078125f;
        else if (mk == 1) v = Wkv_h[k * 1024 + gg * 64 + n];
        else v = Wkv_h[k * 1024 + 512 + gg * 64 + n];
        g_Whgt[j] = __float2half_rn(v);
    }
}

// ============================================================================
// Width attention (validated rounds 14-16) — unchanged.
// ============================================================================
__global__ void __launch_bounds__(512, 1)
k_width_mma(const float* __restrict__ x, float* __restrict__ out) {
    extern __shared__ __half sb[];
    __half* Xh = sb;
    __half* Xl = sb + 256 * XS;
    __half* Kh = sb + 512 * XS;
    __half* W0 = sb + 768 * XS;
    __half* W1 = sb + 832 * XS;

    const int t = threadIdx.x, lane = t & 31, warp = t >> 5, m0 = warp * 16;
    const int w = blockIdx.x, head = blockIdx.y;

    auto loadW = [&](__half* dst, int mat) {
        const __half* src = g_Wwid + (size_t)(mat * 8 + head) * 4096;
        for (int e = t; e < 2048; e += 512) {
            int k = e >> 5, n2 = e & 31;
            *(uint32_t*)(dst + k * XS + n2 * 2) = *(const uint32_t*)(src + k * 64 + n2 * 2);
        }
    };
    loadW(W0, 0);
    {
        int row = t >> 1, q0 = (t & 1) * 8;
        const float4* src = (const float4*)(x + (size_t)row * (WW * DD) + w * DD) + q0;
#pragma unroll
        for (int q4 = 0; q4 < 8; q4++) {
            float4 v = src[q4];
            uint32_t h0, l0, h1, l1;
            splitH(v.x, v.y, h0, l0);
            splitH(v.z, v.w, h1, l1);
            int cc = (q0 + q4) * 4;
            *(uint32_t*)(Xh + row * XS + cc) = h0;
            *(uint32_t*)(Xh + row * XS + cc + 2) = h1;
            *(uint32_t*)(Xl + row * XS + cc) = l0;
            *(uint32_t*)(Xl + row * XS + cc + 2) = l1;
        }
    }
    auto proj = [&](float (&c)[8][4], const __half* Wb) {
#pragma unroll
        for (int nt = 0; nt < 8; nt++)
#pragma unroll
            for (int i = 0; i < 4; i++) c[nt][i] = 0.f;
#pragma unroll
        for (int ks = 0; ks < 4; ks++) {
            uint32_t ah[4], al[4];
            ldsm4(ah, aAddr(Xh, lane, m0, ks * 16));
            ldsm4(al, aAddr(Xl, lane, m0, ks * 16));
#pragma unroll
            for (int np = 0; np < 4; np++) {
                uint32_t bh[4];
                ldsm4t(bh, bAddrT(Wb, lane, ks * 16, np * 16));
#pragma unroll
                for (int hf = 0; hf < 2; hf++) {
                    float* cc = c[np * 2 + hf];
                    mmaH(cc, ah, bh + hf * 2);
                    mmaH(cc, al, bh + hf * 2);
                }
            }
        }
    };
    auto storeHi = [&](float (&c)[8][4], __half* Dh) {
#pragma unroll
        for (int nt = 0; nt < 8; nt++) {
            int r = m0 + (lane >> 2), cc = nt * 8 + ((lane & 3) << 1);
            *(uint32_t*)(Dh + r * XS + cc) = packH(c[nt][0], c[nt][1]);
            *(uint32_t*)(Dh + (r + 8) * XS + cc) = packH(c[nt][2], c[nt][3]);
        }
    };

    float c[8][4];
    __syncthreads();
    loadW(W1, 1);
    proj(c, W0);
    storeHi(c, Kh);
    __syncthreads();
    loadW(W0, 2);
    proj(c, W1);
    uint32_t qh[4][4];
#pragma unroll
    for (int ks = 0; ks < 4; ks++) {
        qh[ks][0] = packH(c[2 * ks][0], c[2 * ks][1]);
        qh[ks][1] = packH(c[2 * ks][2], c[2 * ks][3]);
        qh[ks][2] = packH(c[2 * ks + 1][0], c[2 * ks + 1][1]);
        qh[ks][3] = packH(c[2 * ks + 1][2], c[2 * ks + 1][3]);
    }
    __syncthreads();
    loadW(W1, 3);
    proj(c, W0);
    storeHi(c, Xh);
    __syncthreads();

    float o[8][4];
#pragma unroll
    for (int nt = 0; nt < 8; nt++)
#pragma unroll
        for (int i = 0; i < 4; i++) o[nt][i] = 0.f;
    float lsum[2] = {0.f, 0.f};

    for (int jc = 0; jc < 8; jc++) {
        float s[4][4];
#pragma unroll
        for (int jt = 0; jt < 4; jt++)
#pragma unroll
            for (int i = 0; i < 4; i++) s[jt][i] = 0.f;
#pragma unroll
        for (int ks = 0; ks < 4; ks++) {
            uint32_t kb[2][4];
            ldsm4(kb[0], bAddrN(Kh, lane, jc * 32, ks * 16));
            ldsm4(kb[1], bAddrN(Kh, lane, jc * 32 + 16, ks * 16));
#pragma unroll
            for (int jt = 0; jt < 4; jt++)
                mmaH(s[jt], qh[ks], &kb[jt >> 1][(jt & 1) * 2]);
        }
        uint32_t ph[2][4];
#pragma unroll
        for (int k2 = 0; k2 < 2; k2++) {
            float e0 = __expf(s[2 * k2][0]), e1 = __expf(s[2 * k2][1]);
            float e2 = __expf(s[2 * k2][2]), e3 = __expf(s[2 * k2][3]);
            float f0 = __expf(s[2 * k2 + 1][0]), f1 = __expf(s[2 * k2 + 1][1]);
            float f2 = __expf(s[2 * k2 + 1][2]), f3 = __expf(s[2 * k2 + 1][3]);
            lsum[0] += e0 + e1 + f0 + f1;
            lsum[1] += e2 + e3 + f2 + f3;
            ph[k2][0] = packH(e0, e1);
            ph[k2][1] = packH(e2, e3);
            ph[k2][2] = packH(f0, f1);
            ph[k2][3] = packH(f2, f3);
        }
#pragma unroll
        for (int k2 = 0; k2 < 2; k2++) {
            int j0 = jc * 32 + k2 * 16;
#pragma unroll
            for (int np = 0; np < 4; np++) {
                uint32_t vb[4];
                ldsm4t(vb, bAddrT(Xh, lane, j0, np * 16));
#pragma unroll
                for (int hf = 0; hf < 2; hf++)
                    mmaH(o[np * 2 + hf], ph[k2], vb + hf * 2);
            }
        }
    }
#pragma unroll
    for (int i = 0; i < 2; i++) {
        lsum[i] += __shfl_xor_sync(0xffffffffu, lsum[i], 1);
        lsum[i] += __shfl_xor_sync(0xffffffffu, lsum[i], 2);
    }
    float i0 = 1.f / lsum[0], i1 = 1.f / lsum[1];
    uint32_t oh[4][4], ol[4][4];
#pragma unroll
    for (int ks = 0; ks < 4; ks++) {
        splitH(o[2 * ks][0] * i0, o[2 * ks][1] * i0, oh[ks][0], ol[ks][0]);
        splitH(o[2 * ks][2] * i1, o[2 * ks][3] * i1, oh[ks][1], ol[ks][1]);
        splitH(o[2 * ks + 1][0] * i0, o[2 * ks + 1][1] * i0, oh[ks][2], ol[ks][2]);
        splitH(o[2 * ks + 1][2] * i1, o[2 * ks + 1][3] * i1, oh[ks][3], ol[ks][3]);
    }
    float r[8][4];
#pragma unroll
    for (int nt = 0; nt < 8; nt++)
#pragma unroll
        for (int i = 0; i < 4; i++) r[nt][i] = 0.f;
#pragma unroll
    for (int ks = 0; ks < 4; ks++)
#pragma unroll
        for (int np = 0; np < 4; np++) {
            uint32_t bh[4];
            ldsm4t(bh, bAddrT(W1, lane, ks * 16, np * 16));
#pragma unroll
            for (int hf = 0; hf < 2; hf++) {
                float* rr = r[np * 2 + hf];
                mmaH(rr, oh[ks], bh + hf * 2);
                mmaH(rr, ol[ks], bh + hf * 2);
            }
        }
#pragma unroll
    for (int nt = 0; nt < 8; nt++) {
        int row = m0 + (lane >> 2), col = nt * 8 + ((lane & 3) << 1);
        float* op = out + ((size_t)row * WW + w) * DD;
        atomicAdd(op + col, 0.5f * r[nt][0]);
        atomicAdd(op + col + 1, 0.5f * r[nt][1]);
        float* op2 = out + ((size_t)(row + 8) * WW + w) * DD;
        atomicAdd(op2 + col, 0.5f * r[nt][2]);
        atomicAdd(op2 + col + 1, 0.5f * r[nt][3]);
    }
}

// ============================================================================
// Height projection v6 (validated round 16) — unchanged.
// ============================================================================
__global__ void __launch_bounds__(256, 2)
k_hproj_mma(const float* __restrict__ x) {
    extern __shared__ __half sb[];
    __half* Xh = sb;
    __half* Wb = sb + 128 * XS;
    __half* Sg = sb + 320 * XS;

    const int t = threadIdx.x, lane = t & 31, warp = t >> 5, m0 = warp * 16;
    const int r = blockIdx.x, mk = blockIdx.y, half = blockIdx.z;
    const int rbase = half * 128;

    auto issueW = [&](int g) {
        __half* dst = Wb + (g % 3) * 64 * XS;
        const __half* src = g_Whgt + (size_t)(mk * 8 + g) * 4096;
#pragma unroll
        for (int p = 0; p < 2; p++) {
            int e = p * 256 + t, row = e >> 3, c8 = e & 7;
            uint32_t sa = (uint32_t)__cvta_generic_to_shared(dst + row * XS + c8 * 8);
            CP16(sa, src + row * 64 + c8 * 8);
        }
        CP_COMMIT();
    };
    issueW(0);
    issueW(1);
    {
        int lrow = t >> 1, q0 = (t & 1) * 8;
        const float4* src = (const float4*)(x + (size_t)r * (WW * DD) + (rbase + lrow) * 64) + q0;
#pragma unroll
        for (int q4 = 0; q4 < 8; q4++) {
            float4 v = src[q4];
            int cc = (q0 + q4) * 4;
            *(uint32_t*)(Xh + lrow * XS + cc) = packH(v.x, v.y);
            *(uint32_t*)(Xh + lrow * XS + cc + 2) = packH(v.z, v.w);
        }
    }
    for (int g = 0; g < 8; g++) {
        if (g < 7) CP_WAIT1(); else CP_WAIT0();
        __syncthreads();
        if (g + 2 < 8) issueW(g + 2);
        const __half* cur = Wb + (g % 3) * 64 * XS;

        float c[8][4];
#pragma unroll
        for (int nt = 0; nt < 8; nt++)
#pragma unroll
            for (int i = 0; i < 4; i++) c[nt][i] = 0.f;
#pragma unroll
        for (int ks = 0; ks < 4; ks++) {
            uint32_t ah[4];
            ldsm4(ah, aAddr(Xh, lane, m0, ks * 16));
#pragma unroll
            for (int np = 0; np < 4; np++) {
                uint32_t bh[4];
                ldsm4t(bh, bAddrT(cur, lane, ks * 16, np * 16));
#pragma unroll
                for (int hf = 0; hf < 2; hf++)
                    mmaH(c[np * 2 + hf], ah, bh + hf * 2);
            }
        }
#pragma unroll
        for (int nt = 0; nt < 8; nt++) {
            int row = m0 + (lane >> 2), cc = nt * 8 + ((lane & 3) << 1);
            *(uint32_t*)(Sg + row * XS + cc) = packH(c[nt][0], c[nt][1]);
            *(uint32_t*)(Sg + (row + 8) * XS + cc) = packH(c[nt][2], c[nt][3]);
        }
        __syncwarp();
        {
            int lrow = m0 + (lane >> 1), coff = (lane & 1) * 32;
            int grow = rbase + lrow;
            size_t gb;
            if (mk < 2) gb = (((size_t)(g * 256 + r)) * 256 + grow) * 64 + coff;
            else        gb = (((size_t)(r * 8 + g)) * 256 + grow) * 64 + coff;
            __half* gdst = (mk == 0) ? g_Qh : (mk == 1) ? g_Kh : g_Vh;
#pragma unroll
            for (int q = 0; q < 4; q++) {
                uint4 v = *(uint4*)(Sg + lrow * XS + coff + q * 8);
                *(uint4*)(gdst + gb + q * 8) = v;
            }
        }
    }
}

// ============================================================================
// Height dots v4 (validated round 14) — unchanged.
// ============================================================================
__global__ void __launch_bounds__(512, 1) k_hdots_mma() {
    extern __shared__ __half sb[];
    const int t = threadIdx.x, lane = t & 31, warp = t >> 5;
    const int kc = blockIdx.x, it = blockIdx.y, head = blockIdx.z;
    const int wm = warp >> 1, wn = warp & 1;
    const int m0 = wm * 16, j0 = wn * 128;

    auto issue = [&](__half* base, int step) {
        const int rk = kc * 32 + step;
#pragma unroll
        for (int rr2 = 0; rr2 < 6; rr2++) {
            int e = rr2 * 512 + t;
            const __half* gp;
            uint32_t sa;
            if (e < 1024) {
                int row = e >> 3, c8 = e & 7;
                gp = g_Qh + (((size_t)(head * 256 + rk)) * 256 + it * 128 + row) * 64 + c8 * 8;
                sa = (uint32_t)__cvta_generic_to_shared(base + row * XS + c8 * 8);
            } else {
                int idx = e - 1024, row = idx >> 3, c8 = idx & 7;
                gp = g_Kh + (((size_t)(head * 256 + rk)) * 256 + row) * 64 + c8 * 8;
                sa = (uint32_t)__cvta_generic_to_shared(base + (128 + row) * XS + c8 * 8);
            }
            CP16(sa, gp);
        }
        CP_COMMIT();
    };

    float c[16][4];
#pragma unroll
    for (int nt = 0; nt < 16; nt++)
#pragma unroll
        for (int i = 0; i < 4; i++) c[nt][i] = 0.f;

    issue(sb, 0);
    for (int step = 0; step < 32; step++) {
        CP_WAIT0();
        __syncthreads();
        __half* cur = sb + (step & 1) * 384 * XS;
        if (step + 1 < 32) issue(sb + ((step + 1) & 1) * 384 * XS, step + 1);
        __half* Qh = cur;
        __half* Kh = cur + 128 * XS;
#pragma unroll
        for (int ks = 0; ks < 4; ks++) {
            uint32_t ah[4];
            ldsm4(ah, aAddr(Qh, lane, m0, ks * 16));
#pragma unroll
            for (int jt = 0; jt < 8; jt++) {
                uint32_t bh[4];
                ldsm4(bh, bAddrN(Kh, lane, j0 + jt * 16, ks * 16));
#pragma unroll
                for (int hf = 0; hf < 2; hf++)
                    mmaH(c[jt * 2 + hf], ah, bh + hf * 2);
            }
        }
    }
#pragma unroll
    for (int nt = 0; nt < 16; nt++) {
        int row = it * 128 + m0 + (lane >> 2), col = j0 + nt * 8 + ((lane & 3) << 1);
        atomicAdd(&g_DOTS[head * 65536 + row * 256 + col], c[nt][0]);
        atomicAdd(&g_DOTS[head * 65536 + row * 256 + col + 1], c[nt][1]);
        atomicAdd(&g_DOTS[head * 65536 + (row + 8) * 256 + col], c[nt][2]);
        atomicAdd(&g_DOTS[head * 65536 + (row + 8) * 256 + col + 1], c[nt][3]);
    }
}

// ============================================================================
__global__ void k_hsm2() {
    const int t = threadIdx.x, warp = t >> 5, lane = t & 31;
    const int row = blockIdx.x * 8 + warp;
    float v[8];
    float mx = -1e30f;
#pragma unroll
    for (int kk = 0; kk < 8; kk++) {
        int j = kk * 32 + lane;
        v[kk] = g_DOTS[row * 256 + j] + g_PB[row * 256 + j];
        mx = fmaxf(mx, v[kk]);
    }
#pragma unroll
    for (int o = 16; o; o >>= 1) mx = fmaxf(mx, __shfl_xor_sync(0xffffffffu, mx, o));
    float s = 0.f;
#pragma unroll
    for (int kk = 0; kk < 8; kk++) { v[kk] = __expf(v[kk] - mx); s += v[kk]; }
#pragma unroll
    for (int o = 16; o; o >>= 1) s += __shfl_xor_sync(0xffffffffu, s, o);
    float inv = 1.f / s;
#pragma unroll
    for (int kk = 0; kk < 8; kk++)
        g_Ph[row * 256 + kk * 32 + lane] = __float2half_rn(v[kk] * inv);
}

// ============================================================================
// Height AV v3 (validated round 14) — unchanged.
// ============================================================================
__global__ void __launch_bounds__(512, 1)
k_hav_mma(const float* __restrict__ Wout, float* __restrict__ out) {
    extern __shared__ __half sb[];
    __half* Pm = sb;
    __half* Vb[2] = {sb + 256 * PS, sb + 256 * PS + 256 * XS};
    __half* Wh = sb + 256 * PS + 512 * XS;

    const int t = threadIdx.x, lane = t & 31, warp = t >> 5, m0 = warp * 16;
    const int rg = blockIdx.x, head = blockIdx.y;

    for (int e = t; e < 2048; e += 512) {
        int k = e >> 5, n2 = e & 31;
        float2 v = *(const float2*)(Wout + (size_t)(head * 64 + k) * 64 + n2 * 2);
        *(uint32_t*)(Wh + k * XS + n2 * 2) = packH(v.x, v.y);
    }
#pragma unroll
    for (int p = 0; p < 16; p++) {
        int e = p * 512 + t, row = e >> 5, c8 = e & 31;
        uint32_t sa = (uint32_t)__cvta_generic_to_shared(Pm + row * PS + c8 * 8);
        CP16(sa, g_Ph + (size_t)head * 65536 + row * 256 + c8 * 8);
    }
    CP_COMMIT();

    auto issueV = [&](__half* dst, int r) {
#pragma unroll
        for (int p = 0; p < 4; p++) {
            int e = p * 512 + t, row = e >> 3, c8 = e & 7;
            uint32_t sa = (uint32_t)__cvta_generic_to_shared(dst + row * XS + c8 * 8);
            CP16(sa, g_Vh + (((size_t)(r * 8 + head)) * 256 + row) * 64 + c8 * 8);
        }
        CP_COMMIT();
    };
    issueV(Vb[0], rg * 4);

    for (int rr = 0; rr < 4; rr++) {
        int r = rg * 4 + rr;
        CP_WAIT0();
        __syncthreads();
        __half* Vc = Vb[rr & 1];
        if (rr + 1 < 4) issueV(Vb[(rr + 1) & 1], r + 1);

        float o[8][4];
#pragma unroll
        for (int nt = 0; nt < 8; nt++)
#pragma unroll
            for (int i = 0; i < 4; i++) o[nt][i] = 0.f;
#pragma unroll
        for (int ks = 0; ks < 16; ks++) {
            uint32_t ah[4];
            ldsm4(ah, aAddrS(Pm, lane, m0, ks * 16, PS));
#pragma unroll
            for (int np = 0; np < 4; np++) {
                uint32_t bh[4];
                ldsm4t(bh, bAddrT(Vc, lane, ks * 16, np * 16));
#pragma unroll
                for (int hf = 0; hf < 2; hf++)
                    mmaH(o[np * 2 + hf], ah, bh + hf * 2);
            }
        }
        uint32_t oh[4][4], ol[4][4];
#pragma unroll
        for (int ks = 0; ks < 4; ks++) {
            splitH(o[2 * ks][0], o[2 * ks][1], oh[ks][0], ol[ks][0]);
            splitH(o[2 * ks][2], o[2 * ks][3], oh[ks][1], ol[ks][1]);
            splitH(o[2 * ks + 1][0], o[2 * ks + 1][1], oh[ks][2], ol[ks][2]);
            splitH(o[2 * ks + 1][2], o[2 * ks + 1][3], oh[ks][3], ol[ks][3]);
        }
        float rv[8][4];
#pragma unroll
        for (int nt = 0; nt < 8; nt++)
#pragma unroll
            for (int i = 0; i < 4; i++) rv[nt][i] = 0.f;
#pragma unroll
        for (int ks = 0; ks < 4; ks++)
#pragma unroll
            for (int np = 0; np < 4; np++) {
                uint32_t bh[4];
                ldsm4t(bh, bAddrT(Wh, lane, ks * 16, np * 16));
#pragma unroll
                for (int hf = 0; hf < 2; hf++) {
                    float* cc = rv[np * 2 + hf];
                    mmaH(cc, oh[ks], bh + hf * 2);
                    mmaH(cc, ol[ks], bh + hf * 2);
                }
            }
#pragma unroll
        for (int nt = 0; nt < 8; nt++) {
            int row = m0 + (lane >> 2), col = nt * 8 + ((lane & 3) << 1);
            float* op = out + ((size_t)r * WW + row) * DD;
            atomicAdd(op + col, 0.5f * rv[nt][0]);
            atomicAdd(op + col + 1, 0.5f * rv[nt][1]);
            float* op2 = out + ((size_t)r * WW + row + 8) * DD;
            atomicAdd(op2 + col, 0.5f * rv[nt][2]);
            atomicAdd(op2 + col + 1, 0.5f * rv[nt][3]);
        }
        __syncthreads();
    }
}

// ============================================================================
__global__ void k_pair(const float* __restrict__ pb, const float* __restrict__ g,
                       const float* __restrict__ b, const float* __restrict__ Wp) {
    const int t = threadIdx.x;
    const int warp = t >> 5, lane = t & 31, sub = lane >> 3, l8 = lane & 7;
    const int gw = (blockIdx.x * 8 + warp) * 4 + sub;

    const float4* src = (const float4*)(pb + (size_t)gw * 128) + l8 * 4;
    float4 v[4];
#pragma unroll
    for (int qi = 0; qi < 4; qi++) v[qi] = src[qi];
    float s1 = 0.f, s2 = 0.f;
#pragma unroll
    for (int qi = 0; qi < 4; qi++) {
        s1 += v[qi].x + v[qi].y + v[qi].z + v[qi].w;
        s2 += v[qi].x * v[qi].x + v[qi].y * v[qi].y + v[qi].z * v[qi].z + v[qi].w * v[qi].w;
    }
#pragma unroll
    for (int o = 4; o; o >>= 1) {
        s1 += __shfl_xor_sync(0xffffffffu, s1, o);
        s2 += __shfl_xor_sync(0xffffffffu, s2, o);
    }
    float mu = s1 * (1.f / 128.f);
    float rstd = rsqrtf(s2 * (1.f / 128.f) - mu * mu + 1e-5f);

    float phd[8];
#pragma unroll
    for (int h = 0; h < 8; h++) phd[h] = 0.f;
#pragma unroll
    for (int qi = 0; qi < 4; qi++) {
        float4 gv = ((const float4*)g)[l8 * 4 + qi];
        float4 bv = ((const float4*)b)[l8 * 4 + qi];
        float vv[4] = {v[qi].x, v[qi].y, v[qi].z, v[qi].w};
        float gg[4] = {gv.x, gv.y, gv.z, gv.w};
        float bb[4] = {bv.x, bv.y, bv.z, bv.w};
#pragma unroll
        for (int u = 0; u < 4; u++) {
            int p = l8 * 16 + qi * 4 + u;
            float n = (vv[u] - mu) * rstd * gg[u] + bb[u];
            float4 wa = *(const float4*)(Wp + (size_t)p * 8);
            float4 wb = *(const float4*)(Wp + (size_t)p * 8 + 4);
            phd[0] = fmaf(n, wa.x, phd[0]);
            phd[1] = fmaf(n, wa.y, phd[1]);
            phd[2] = fmaf(n, wa.z, phd[2]);
            phd[3] = fmaf(n, wa.w, phd[3]);
            phd[4] = fmaf(n, wb.x, phd[4]);
            phd[5] = fmaf(n, wb.y, phd[5]);
            phd[6] = fmaf(n, wb.z, phd[6]);
            phd[7] = fmaf(n, wb.w, phd[7]);
        }
    }
#pragma unroll
    for (int h = 0; h < 8; h++)
#pragma unroll
        for (int o = 4; o; o >>= 1) phd[h] += __shfl_xor_sync(0xffffffffu, phd[h], o);
    if (l8 == 0)
#pragma unroll
        for (int h = 0; h < 8; h++) g_PB[h * 65536 + gw] = phd[h];
}

// ============================================================================
extern "C" void kernel_launch(void* const* d_in, const int* in_sizes, int n_in,
                              void* d_out, int out_size) {
    (void)in_sizes; (void)n_in; (void)out_size;
    const float* x = (const float*)d_in[0];
    const float* pb = (const float*)d_in[1];
    const float* Wq_w = (const float*)d_in[2];
    const float* Wkv_w = (const float*)d_in[3];
    const float* Wout_w = (const float*)d_in[4];
    const float* bout_w = (const float*)d_in[5];
    const float* Wq_h = (const float*)d_in[6];
    const float* Wkv_h = (const float*)d_in[7];
    const float* Wout_h = (const float*)d_in[8];
    const float* bout_h = (const float*)d_in[9];
    const float* lng = (const float*)d_in[10];
    const float* lnb = (const float*)d_in[11];
    const float* Wp = (const float*)d_in[12];
    float* out = (float*)d_out;

    // one-time stream/event setup (no device memory; same launches every call)
    static cudaStream_t s2 = nullptr;
    static cudaEvent_t evF = nullptr, evJ = nullptr;
    if (s2 == nullptr) {
        cudaStreamCreateWithFlags(&s2, cudaStreamNonBlocking);
        cudaEventCreateWithFlags(&evF, cudaEventDisableTiming);
        cudaEventCreateWithFlags(&evJ, cudaEventDisableTiming);
    }

    const int smw = 896 * XS * 2;
    const int smp = 448 * XS * 2;
    const int smd = 2 * 384 * XS * 2;
    const int sma = (256 * PS + 512 * XS + 64 * XS) * 2;
    cudaFuncSetAttribute(k_width_mma, cudaFuncAttributeMaxDynamicSharedMemorySize, smw);
    cudaFuncSetAttribute(k_hproj_mma, cudaFuncAttributeMaxDynamicSharedMemorySize, smp);
    cudaFuncSetAttribute(k_hdots_mma, cudaFuncAttributeMaxDynamicSharedMemorySize, smd);
    cudaFuncSetAttribute(k_hav_mma, cudaFuncAttributeMaxDynamicSharedMemorySize, sma);

    // prologue on main stream
    k_init<<<16384, 256>>>(bout_w, bout_h, out);
    k_wconv<<<448, 512>>>(Wq_w, Wkv_w, Wout_w, Wq_h, Wkv_h);

    // fork: width branch runs concurrently with the height chain
    cudaEventRecord(evF, 0);
    cudaStreamWaitEvent(s2, evF, 0);
    k_width_mma<<<dim3(256, 8), 512, smw, s2>>>(x, out);

    // height chain on main stream
    k_hproj_mma<<<dim3(256, 3, 2), 256, smp>>>(x);
    k_pair<<<2048, 256>>>(pb, lng, lnb, Wp);
    k_hdots_mma<<<dim3(8, 2, 8), 512, smd>>>();
    k_hsm2<<<256, 256>>>();
    k_hav_mma<<<dim3(64, 8), 512, sma>>>(Wout_h, out);

    // join
    cudaEventRecord(evJ, s2);
    cudaStreamWaitEvent(0, evJ, 0);
}